// round 9
// baseline (speedup 1.0000x reference)
#include <cuda_runtime.h>
#include <cuda_bf16.h>
#include <cstdint>
#include <cstdio>

#define BATCH 1024
#define NS    30
#define NT    1024
#define NFD   200
#define NCL   7
#define MROWS (BATCH*NS)      // 30720

static inline int cdiv(int a, int b) { return (a + b - 1) / b; }

// ---------------- scratch (device globals; no allocation) ----------------
__device__ float g_h2  [BATCH*NS*NT];
__device__ float g_F2  [MROWS*NFD];
__device__ float g_tmp [MROWS*NFD];
__device__ float g_P1  [MROWS*NFD];
__device__ float g_x1  [MROWS*NFD];
__device__ float g_x2  [MROWS*NFD];
__device__ float g_x3  [MROWS*NFD];
__device__ float g_Q   [MROWS*NFD];
__device__ float g_h1s [MROWS*NFD];
__device__ float g_xsn [MROWS*NFD];
__device__ float g_gH1 [MROWS*NFD];
__device__ float g_gH2 [MROWS*NFD];
__device__ float g_gH3 [MROWS*NFD];
__device__ float g_AF  [BATCH*NS*NS];
__device__ float g_Gh  [MROWS*300];
__device__ float g_Gv  [MROWS*300];
__device__ float g_wch [MROWS];
__device__ float g_wft [BATCH*300];

// packed weight fragments: uint4 = {hi_r0, hi_r1, lo_r0, lo_r1}
__device__ uint4 g_bf4[150000];
__device__ uint4 g_cw1[768];
__device__ uint4 g_cw2[768];

// ---------------- mma + split helpers ----------------
__device__ __forceinline__ void mma16816(float* c, uint32_t a0, uint32_t a1, uint32_t a2, uint32_t a3,
                                         uint32_t b0, uint32_t b1) {
    asm volatile("mma.sync.aligned.m16n8k16.row.col.f32.bf16.bf16.f32 "
        "{%0,%1,%2,%3}, {%4,%5,%6,%7}, {%8,%9}, {%0,%1,%2,%3};"
        : "+f"(c[0]), "+f"(c[1]), "+f"(c[2]), "+f"(c[3])
        : "r"(a0), "r"(a1), "r"(a2), "r"(a3), "r"(b0), "r"(b1));
}
__device__ __forceinline__ void split2(float2 v, uint32_t& hi, uint32_t& lo) {
    __nv_bfloat162 h = __floats2bfloat162_rn(v.x, v.y);
    float2 hf = __bfloat1622float2(h);
    __nv_bfloat162 l = __floats2bfloat162_rn(v.x - hf.x, v.y - hf.y);
    hi = reinterpret_cast<uint32_t&>(h);
    lo = reinterpret_cast<uint32_t&>(l);
}

// ---------------- merged weight prep: all 12 GEMM weights in one launch ----------------
struct PJobs {
    const float* W[12];
    int K[12], N[12], nT[12], nks[12], off[12];   // off in uint4 units
};
__global__ void prepall_kernel(PJobs J, uint4* __restrict__ out)
{
    const int j = blockIdx.y;
    const int idx = blockIdx.x * 256 + threadIdx.x;
    const int nks = J.nks[j];
    const int total = J.nT[j] * nks * 32;
    if (idx >= total) return;
    const int K = J.K[j], N = J.N[j];
    const float* W = J.W[j];
    int lane = idx & 31;
    int s = idx >> 5;
    int ks = s % nks;
    int t  = s / nks;
    int n = t * 8 + (lane >> 2);
    float v[4];
    #pragma unroll
    for (int reg = 0; reg < 2; reg++) {
        #pragma unroll
        for (int jj = 0; jj < 2; jj++) {
            int k = ks * 16 + (lane & 3) * 2 + reg * 8 + jj;
            v[reg * 2 + jj] = (n < N && k < K) ? W[(size_t)k * N + n] : 0.f;
        }
    }
    uint32_t h0, l0, h1, l1;
    split2(make_float2(v[0], v[1]), h0, l0);
    split2(make_float2(v[2], v[3]), h1, l1);
    out[J.off[j] + idx] = make_uint4(h0, h1, l0, l1);
}

// ---------------- conv weight prep: Wc[30,30,3] -> 768 uint4 frags, kidx = kk*32 + i ----------------
__global__ void prepcw_kernel(const float* __restrict__ W, uint4* __restrict__ out)
{
    int idx = blockIdx.x * 256 + threadIdx.x;
    if (idx >= 768) return;
    int lane = idx & 31;
    int ks = (idx >> 5) % 6;
    int t  = idx / 192;
    int n = t * 8 + (lane >> 2);
    float v[4];
    #pragma unroll
    for (int reg = 0; reg < 2; reg++) {
        #pragma unroll
        for (int jj = 0; jj < 2; jj++) {
            int kidx = ks * 16 + (lane & 3) * 2 + reg * 8 + jj;
            int kk = kidx >> 5, i = kidx & 31;
            float w = 0.f;
            if (n < 30 && i < 30) w = W[(n * 30 + i) * 3 + kk];
            v[reg * 2 + jj] = w;
        }
    }
    uint32_t h0, l0, h1, l1;
    split2(make_float2(v[0], v[1]), h0, l0);
    split2(make_float2(v[2], v[3]), h1, l1);
    out[idx] = make_uint4(h0, h1, l0, l1);
}

// ---------------- fused conv (HMMA, x->smem, layer1 -> smem -> layer2), 64 t-rows/block ----------------
// smem xs[32][84]: col j <-> t = t0 - 9 + j ; rows 30,31 zero. Layer-1 reads unguarded LDS.
__device__ __forceinline__ void conv_l1_group(
    const float (*xs)[84], const uint4* __restrict__ Wf, const float* __restrict__ bc1,
    uint2 (*h1s)[16], int g, int tlo, int thi, int lane)
{
    const int gq = lane >> 2, kq = (lane & 3) * 2;
    const int rel0 = g * 16 + gq, rel1 = rel0 + 8;   // col = rel + kk, kidx -> i=kidx&31, kk=kidx>>5
    float acc[4][4];
    #pragma unroll
    for (int t = 0; t < 4; t++) { acc[t][0] = 0.f; acc[t][1] = 0.f; acc[t][2] = 0.f; acc[t][3] = 0.f; }
    #pragma unroll
    for (int ks = 0; ks < 6; ks++) {
        const int kb = ks * 16 + kq;
        const int i0 = kb & 31,        k0 = kb >> 5;
        const int i1 = (kb + 1) & 31,  k1 = (kb + 1) >> 5;
        const int i2 = (kb + 8) & 31,  k2 = (kb + 8) >> 5;
        const int i3 = (kb + 9) & 31,  k3 = (kb + 9) >> 5;
        float v00 = xs[i0][rel0 + k0], v01 = xs[i1][rel0 + k1];
        float v10 = xs[i0][rel1 + k0], v11 = xs[i1][rel1 + k1];
        float v02 = xs[i2][rel0 + k2], v03 = xs[i3][rel0 + k3];
        float v12 = xs[i2][rel1 + k2], v13 = xs[i3][rel1 + k3];
        uint32_t ah0, al0, ah1, al1, ah2, al2, ah3, al3;
        split2(make_float2(v00, v01), ah0, al0);
        split2(make_float2(v10, v11), ah1, al1);
        split2(make_float2(v02, v03), ah2, al2);
        split2(make_float2(v12, v13), ah3, al3);
        const uint4* bp = Wf + ks * 32 + lane;
        #pragma unroll
        for (int t = 0; t < 4; t++) {
            if (t < tlo || t >= thi) continue;
            uint4 w = bp[t * 192];
            mma16816(acc[t], ah0, ah1, ah2, ah3, w.x, w.y);
            mma16816(acc[t], ah0, ah1, ah2, ah3, w.z, w.w);
            mma16816(acc[t], al0, al1, al2, al3, w.x, w.y);
        }
    }
    const int sr0 = g * 16 + gq, sr1 = sr0 + 8;
    #pragma unroll
    for (int t = 0; t < 4; t++) {
        if (t < tlo || t >= thi) continue;
        int n0 = t * 8 + kq;
        float bb0 = (n0 < 30) ? bc1[n0] : 0.f;
        float bb1 = (n0 + 1 < 30) ? bc1[n0 + 1] : 0.f;
        float v0 = fmaxf(acc[t][0] + bb0, 0.f), v1 = fmaxf(acc[t][1] + bb1, 0.f);
        float v2 = fmaxf(acc[t][2] + bb0, 0.f), v3 = fmaxf(acc[t][3] + bb1, 0.f);
        uint32_t h, l;
        split2(make_float2(v0, v1), h, l);
        h1s[sr0][t * 4 + (kq >> 1)] = make_uint2(h, l);
        split2(make_float2(v2, v3), h, l);
        h1s[sr1][t * 4 + (kq >> 1)] = make_uint2(h, l);
    }
}

__global__ __launch_bounds__(128) void convf_kernel(
    const float* __restrict__ x, const uint4* __restrict__ Wf1, const float* __restrict__ bc1,
    const uint4* __restrict__ Wf2, const float* __restrict__ bc2, float* __restrict__ out)
{
    __shared__ float xs[32][84];
    __shared__ uint2 h1s[80][16];
    const int b = blockIdx.y;
    const int t0 = blockIdx.x * 64;
    const int lane = threadIdx.x & 31, warp = threadIdx.x >> 5;
    const float* xb = x + (size_t)b * NS * NT;

    // stage x window [t0-9, t0+73), rows 30/31 zeroed (coalesced LDG -> STS)
    for (int i = warp; i < 32; i += 4) {
        for (int j = lane; j < 82; j += 32) {
            int t = t0 - 9 + j;
            xs[i][j] = (i < NS && t >= 0 && t < NT) ? xb[i * NT + t] : 0.f;
        }
    }
    __syncthreads();

    // layer 1: 5 row-groups cover t in [t0-8, t0+72)
    conv_l1_group(xs, Wf1, bc1, h1s, warp, 0, 4, lane);
    if (warp < 2) conv_l1_group(xs, Wf1, bc1, h1s, 4, warp * 2, warp * 2 + 2, lane);
    __syncthreads();

    // layer 2: rows t0 + warp*16 ..
    const int gq = lane >> 2, kq = (lane & 3) * 2;
    const int r0 = t0 + warp * 16 + gq, r1 = r0 + 8;
    float acc[4][4];
    #pragma unroll
    for (int t = 0; t < 4; t++) { acc[t][0] = 0.f; acc[t][1] = 0.f; acc[t][2] = 0.f; acc[t][3] = 0.f; }
    for (int ks = 0; ks < 6; ks++) {
        int kb = ks * 16 + kq;
        int kk = kb >> 5;
        int i  = kb & 31;
        int ts0 = r0 + kk - 1, ts1 = r1 + kk - 1;
        int s0 = ts0 - (t0 - 8), s1 = ts1 - (t0 - 8);
        uint2 z = make_uint2(0u, 0u);
        uint2 p00 = (ts0 >= 0 && ts0 < NT) ? h1s[s0][i >> 1]       : z;
        uint2 p01 = (ts0 >= 0 && ts0 < NT) ? h1s[s0][(i + 8) >> 1] : z;
        uint2 p10 = (ts1 >= 0 && ts1 < NT) ? h1s[s1][i >> 1]       : z;
        uint2 p11 = (ts1 >= 0 && ts1 < NT) ? h1s[s1][(i + 8) >> 1] : z;
        const uint4* bp = Wf2 + ks * 32 + lane;
        #pragma unroll
        for (int t = 0; t < 4; t++) {
            uint4 w = bp[t * 192];
            mma16816(acc[t], p00.x, p10.x, p01.x, p11.x, w.x, w.y);
            mma16816(acc[t], p00.x, p10.x, p01.x, p11.x, w.z, w.w);
            mma16816(acc[t], p00.y, p10.y, p01.y, p11.y, w.x, w.y);
        }
    }
    #pragma unroll
    for (int t = 0; t < 4; t++) {
        int n0 = t * 8 + kq;
        if (n0 < 30) {
            float bb = bc2[n0];
            out[((size_t)b * NS + n0) * NT + r0] = fmaxf(acc[t][0] + bb, 0.f);
            out[((size_t)b * NS + n0) * NT + r1] = fmaxf(acc[t][2] + bb, 0.f);
        }
        if (n0 + 1 < 30) {
            float bb = bc2[n0 + 1];
            out[((size_t)b * NS + n0 + 1) * NT + r0] = fmaxf(acc[t][1] + bb, 0.f);
            out[((size_t)b * NS + n0 + 1) * NT + r1] = fmaxf(acc[t][3] + bb, 0.f);
        }
    }
}

// ---------------- HMMA split-bf16 GEMM body ----------------
template<int NTl>
__device__ __forceinline__ void mgemm_body(
    const float* __restrict__ A, const uint4* __restrict__ B4,
    const float* __restrict__ bias, float* __restrict__ C,
    int N, int K, int nks, int ldc, int coloff, int relu)
{
    const int lane = threadIdx.x & 31;
    const int warp = threadIdx.x >> 5;
    const int gq = lane >> 2;
    const int q  = lane & 3;
    const int r0 = blockIdx.x * 64 + warp * 16 + gq;
    const int r1 = r0 + 8;
    const int kq = q * 2;

    float acc[NTl][4];
    #pragma unroll
    for (int t = 0; t < NTl; t++) {
        acc[t][0] = 0.f; acc[t][1] = 0.f; acc[t][2] = 0.f; acc[t][3] = 0.f;
    }

    const float* a0p = A + (size_t)r0 * K;
    const float* a1p = A + (size_t)r1 * K;

    for (int ks = 0; ks < nks; ks++) {
        const int kb = ks * 16 + kq;
        float2 x00 = (kb     < K) ? *reinterpret_cast<const float2*>(a0p + kb)     : make_float2(0.f, 0.f);
        float2 x01 = (kb + 8 < K) ? *reinterpret_cast<const float2*>(a0p + kb + 8) : make_float2(0.f, 0.f);
        float2 x10 = (kb     < K) ? *reinterpret_cast<const float2*>(a1p + kb)     : make_float2(0.f, 0.f);
        float2 x11 = (kb + 8 < K) ? *reinterpret_cast<const float2*>(a1p + kb + 8) : make_float2(0.f, 0.f);
        uint32_t ah0, al0, ah1, al1, ah2, al2, ah3, al3;
        split2(x00, ah0, al0);
        split2(x10, ah1, al1);
        split2(x01, ah2, al2);
        split2(x11, ah3, al3);
        const uint4* bp = B4 + ks * 32 + lane;
        const int stride = nks * 32;
        #pragma unroll
        for (int t = 0; t < NTl; t++) {
            uint4 w = bp[(size_t)t * stride];
            mma16816(acc[t], ah0, ah1, ah2, ah3, w.x, w.y);
            mma16816(acc[t], ah0, ah1, ah2, ah3, w.z, w.w);
            mma16816(acc[t], al0, al1, al2, al3, w.x, w.y);
        }
    }

    #pragma unroll
    for (int t = 0; t < NTl; t++) {
        int n0 = t * 8 + kq;
        if (n0 < N) {
            float b0v = bias ? bias[n0] : 0.f;
            float b1v = bias ? bias[n0 + 1] : 0.f;
            float v0 = acc[t][0] + b0v, v1 = acc[t][1] + b1v;
            float v2 = acc[t][2] + b0v, v3 = acc[t][3] + b1v;
            if (relu) {
                v0 = fmaxf(v0, 0.f); v1 = fmaxf(v1, 0.f);
                v2 = fmaxf(v2, 0.f); v3 = fmaxf(v3, 0.f);
            }
            *reinterpret_cast<float2*>(&C[(size_t)r0 * ldc + coloff + n0]) = make_float2(v0, v1);
            *reinterpret_cast<float2*>(&C[(size_t)r1 * ldc + coloff + n0]) = make_float2(v2, v3);
        }
    }
}

// N-split GEMM (200 cols -> 104 + 96), grid (480, 2)
__global__ __launch_bounds__(128, 4) void mgemmS_kernel(
    const float* __restrict__ A, const uint4* __restrict__ B4,
    const float* __restrict__ bias, float* __restrict__ C,
    int K, int nks, int ldc, int relu)
{
    if (blockIdx.y == 0)
        mgemm_body<13>(A, B4, bias, C, 104, K, nks, ldc, 0, relu);
    else
        mgemm_body<12>(A, B4 + 13 * nks * 32, bias ? bias + 104 : nullptr, C, 96, K, nks, ldc, 104, relu);
}

// merged 3x (N=100, K=200), split 56+44, grid (480, 6)
__global__ __launch_bounds__(128, 4) void mgemm3_kernel(
    const float* __restrict__ A0, const float* __restrict__ A1, const float* __restrict__ A2,
    const uint4* __restrict__ B4, float* __restrict__ C)
{
    const int j = blockIdx.y >> 1, h = blockIdx.y & 1;
    const float* A = (j == 0) ? A0 : (j == 1) ? A1 : A2;
    const uint4* B = B4 + j * 5408;
    if (h == 0) mgemm_body<7>(A, B, nullptr, C, 56, 200, 13, 300, j * 100, 0);
    else        mgemm_body<6>(A, B + 7 * 13 * 32, nullptr, C, 44, 200, 13, 300, j * 100 + 56, 0);
}

// merged 2x (N=150, K=200, relu), split 80+70, grid (480, 4)
__global__ __launch_bounds__(128, 4) void mgemm2_kernel(
    const float* __restrict__ A0, const float* __restrict__ A1,
    const uint4* __restrict__ B4, float* __restrict__ C)
{
    const int j = blockIdx.y >> 1, h = blockIdx.y & 1;
    const float* A = j ? A1 : A0;
    const uint4* B = B4 + j * 7904;
    if (h == 0) mgemm_body<10>(A, B, nullptr, C, 80, 200, 13, 300, j * 150, 1);
    else        mgemm_body<9>(A, B + 10 * 13 * 32, nullptr, C, 70, 200, 13, 300, j * 150 + 80, 1);
}

// ---------------- batched small matmul body: Out[b] = A @ X[b] ----------------
__device__ __forceinline__ void bmm30_body(
    const float* __restrict__ Am, const float* __restrict__ X, float* __restrict__ Out,
    int batched, int b, int tid)
{
    __shared__ float As[NS * NS];
    __shared__ float Xs[NS * NFD];
    const float* A = batched ? (Am + (size_t)b * NS * NS) : Am;
    for (int i = tid; i < NS * NS; i += 256) As[i] = A[i];
    for (int i = tid; i < NS * NFD; i += 256) Xs[i] = X[(size_t)b * NS * NFD + i];
    __syncthreads();
    if (tid < 250) {
        int si = tid / 25, fi = tid - (tid / 25) * 25;
        int s0 = si * 3, f0 = fi * 8;
        float acc[3][8];
        #pragma unroll
        for (int r = 0; r < 3; r++)
            #pragma unroll
            for (int q = 0; q < 8; q++) acc[r][q] = 0.f;
        for (int j = 0; j < NS; j++) {
            float a0 = As[(s0 + 0) * NS + j];
            float a1 = As[(s0 + 1) * NS + j];
            float a2 = As[(s0 + 2) * NS + j];
            float4 xA = *reinterpret_cast<const float4*>(&Xs[j * NFD + f0]);
            float4 xB = *reinterpret_cast<const float4*>(&Xs[j * NFD + f0 + 4]);
            float xv[8] = {xA.x, xA.y, xA.z, xA.w, xB.x, xB.y, xB.z, xB.w};
            #pragma unroll
            for (int q = 0; q < 8; q++) {
                acc[0][q] += a0 * xv[q];
                acc[1][q] += a1 * xv[q];
                acc[2][q] += a2 * xv[q];
            }
        }
        #pragma unroll
        for (int r = 0; r < 3; r++)
            #pragma unroll
            for (int q = 0; q < 8; q++)
                Out[(size_t)b * NS * NFD + (s0 + r) * NFD + f0 + q] = acc[r][q];
    }
}

__global__ __launch_bounds__(256) void bmm30_kernel(
    const float* __restrict__ Am, const float* __restrict__ X, float* __restrict__ Out, int batched)
{
    bmm30_body(Am, X, Out, batched, blockIdx.x, threadIdx.x);
}

// merged P1 = A_F@F2 (y=0) and Q = adj@F2 (y=1)
__global__ __launch_bounds__(256) void bmm2_kernel(
    const float* __restrict__ AF, const float* __restrict__ adj,
    const float* __restrict__ F2, float* __restrict__ P1, float* __restrict__ Q)
{
    if (blockIdx.y == 0) bmm30_body(AF, F2, P1, 1, blockIdx.x, threadIdx.x);
    else                 bmm30_body(adj, F2, Q, 0, blockIdx.x, threadIdx.x);
}

// ---------------- fused gate + 3x bmm30(adj, g_k*H_k) ----------------
__global__ __launch_bounds__(256) void gbmm_kernel(
    const float* __restrict__ adj, const float* __restrict__ x1, const float* __restrict__ x2,
    const float* __restrict__ x3, const float* __restrict__ xsn, const float* __restrict__ wg,
    float* __restrict__ o1, float* __restrict__ o2, float* __restrict__ o3)
{
    extern __shared__ float sm[];
    float* As = sm;                                   // 900
    float* X0 = sm + 900;                             // 6000 each
    float* X1 = sm + 6900;
    float* X2 = sm + 12900;
    float* Xs = sm + 18900;
    const int b = blockIdx.x, tid = threadIdx.x;
    const size_t base = (size_t)b * 6000;
    for (int i = tid; i < 900; i += 256) As[i] = adj[i];
    for (int i = tid; i < 6000; i += 256) {
        X0[i] = x1[base + i];
        X1[i] = x2[base + i];
        X2[i] = x3[base + i];
        Xs[i] = xsn[base + i];
    }
    __syncthreads();

    {
        const int warp = tid >> 5, lane = tid & 31;
        for (int rr = 0; rr < 4; rr++) {
            int r = warp * 4 + rr;
            if (r >= NS) break;
            float H0[7], H1[7], H2[7];
            float s0 = 0.f, s1 = 0.f, s2 = 0.f;
            #pragma unroll
            for (int q = 0; q < 7; q++) {
                int f = q * 32 + lane;
                float h0 = 0.f, h1 = 0.f, h2 = 0.f;
                if (f < NFD) {
                    float sv = Xs[r * NFD + f];
                    h0 = (X0[r * NFD + f] + sv) * 0.5f;
                    h1 = (X1[r * NFD + f] + sv) * 0.5f;
                    h2 = (X2[r * NFD + f] + sv) * 0.5f;
                    s0 += h0 * wg[f * 3 + 0];
                    s1 += h1 * wg[f * 3 + 1];
                    s2 += h2 * wg[f * 3 + 2];
                }
                H0[q] = h0; H1[q] = h1; H2[q] = h2;
            }
            #pragma unroll
            for (int o = 16; o; o >>= 1) {
                s0 += __shfl_xor_sync(0xffffffffu, s0, o);
                s1 += __shfl_xor_sync(0xffffffffu, s1, o);
                s2 += __shfl_xor_sync(0xffffffffu, s2, o);
            }
            float mx = fmaxf(s0, fmaxf(s1, s2));
            float e0 = expf(s0 - mx), e1 = expf(s1 - mx), e2 = expf(s2 - mx);
            float inv = 1.f / (e0 + e1 + e2);
            e0 *= inv; e1 *= inv; e2 *= inv;
            #pragma unroll
            for (int q = 0; q < 7; q++) {
                int f = q * 32 + lane;
                if (f < NFD) {
                    X0[r * NFD + f] = e0 * H0[q];
                    X1[r * NFD + f] = e1 * H1[q];
                    X2[r * NFD + f] = e2 * H2[q];
                }
            }
        }
    }
    __syncthreads();

    if (tid < 250) {
        int si = tid / 25, fi = tid - (tid / 25) * 25;
        int s0 = si * 3, f0 = fi * 8;
        float* Xk[3] = {X0, X1, X2};
        float* Ok[3] = {o1, o2, o3};
        #pragma unroll
        for (int k = 0; k < 3; k++) {
            const float* X = Xk[k];
            float acc[3][8];
            #pragma unroll
            for (int r = 0; r < 3; r++)
                #pragma unroll
                for (int q = 0; q < 8; q++) acc[r][q] = 0.f;
            for (int j = 0; j < NS; j++) {
                float a0 = As[(s0 + 0) * NS + j];
                float a1 = As[(s0 + 1) * NS + j];
                float a2 = As[(s0 + 2) * NS + j];
                float4 xA = *reinterpret_cast<const float4*>(&X[j * NFD + f0]);
                float4 xB = *reinterpret_cast<const float4*>(&X[j * NFD + f0 + 4]);
                float xv[8] = {xA.x, xA.y, xA.z, xA.w, xB.x, xB.y, xB.z, xB.w};
                #pragma unroll
                for (int q = 0; q < 8; q++) {
                    acc[0][q] += a0 * xv[q];
                    acc[1][q] += a1 * xv[q];
                    acc[2][q] += a2 * xv[q];
                }
            }
            #pragma unroll
            for (int r = 0; r < 3; r++)
                #pragma unroll
                for (int q = 0; q < 8; q++)
                    Ok[k][base + (s0 + r) * NFD + f0 + q] = acc[r][q];
        }
    }
}

// ---------------- A_F = softmax(relu(tmp @ F2^T)) per batch ----------------
__global__ __launch_bounds__(128) void af_kernel(
    const float* __restrict__ Tm, const float* __restrict__ F2, float* __restrict__ AF)
{
    __shared__ float Ts[NS * NFD];
    __shared__ float Fs[NS * NFD];
    const int b = blockIdx.x;
    const int tid = threadIdx.x;
    for (int i = tid; i < NS * NFD; i += 128) {
        Ts[i] = Tm[(size_t)b * NS * NFD + i];
        Fs[i] = F2[(size_t)b * NS * NFD + i];
    }
    __syncthreads();
    float acc[3][3];
    int ii = 0, jj = 0;
    if (tid < 100) {
        ii = (tid / 10) * 3; jj = (tid % 10) * 3;
        #pragma unroll
        for (int r = 0; r < 3; r++)
            #pragma unroll
            for (int c = 0; c < 3; c++) acc[r][c] = 0.f;
        for (int g = 0; g < NFD; g++) {
            float t0 = Ts[(ii + 0) * NFD + g], t1 = Ts[(ii + 1) * NFD + g], t2 = Ts[(ii + 2) * NFD + g];
            float f0 = Fs[(jj + 0) * NFD + g], f1 = Fs[(jj + 1) * NFD + g], f2 = Fs[(jj + 2) * NFD + g];
            acc[0][0] += t0 * f0; acc[0][1] += t0 * f1; acc[0][2] += t0 * f2;
            acc[1][0] += t1 * f0; acc[1][1] += t1 * f1; acc[1][2] += t1 * f2;
            acc[2][0] += t2 * f0; acc[2][1] += t2 * f1; acc[2][2] += t2 * f2;
        }
    }
    __syncthreads();
    float (*Ms)[31] = reinterpret_cast<float(*)[31]>(Ts);
    if (tid < 100) {
        #pragma unroll
        for (int r = 0; r < 3; r++)
            #pragma unroll
            for (int c = 0; c < 3; c++) Ms[ii + r][jj + c] = fmaxf(acc[r][c], 0.f);
    }
    __syncthreads();
    if (tid < NS) {
        float mx = -1e30f;
        for (int j = 0; j < NS; j++) mx = fmaxf(mx, Ms[tid][j]);
        float s = 0.f;
        for (int j = 0; j < NS; j++) s += expf(Ms[tid][j] - mx);
        float inv = 1.f / s;
        for (int j = 0; j < NS; j++)
            AF[(size_t)b * NS * NS + tid * NS + j] = expf(Ms[tid][j] - mx) * inv;
    }
}

// ---------------- SE blocks ----------------
__global__ void se1_kernel(const float* __restrict__ Gv, const float* __restrict__ Ws1,
                           const float* __restrict__ Ws2, float* __restrict__ wch)
{
    const int b = blockIdx.x;
    const int lane = threadIdx.x;
    __shared__ float mv[NS];
    __shared__ float av[15];
    for (int s = 0; s < NS; s++) {
        float p = 0.f;
        for (int j = lane; j < 300; j += 32) p += Gv[(size_t)b * 9000 + s * 300 + j];
        #pragma unroll
        for (int o = 16; o; o >>= 1) p += __shfl_xor_sync(0xffffffffu, p, o);
        if (lane == 0) mv[s] = p * (1.f / 300.f);
    }
    __syncwarp();
    if (lane < 15) {
        float a = 0.f;
        for (int s = 0; s < NS; s++) a += mv[s] * Ws1[s * 15 + lane];
        av[lane] = fmaxf(a, 0.f);
    }
    __syncwarp();
    if (lane < NS) {
        float a = 0.f;
        for (int h = 0; h < 15; h++) a += av[h] * Ws2[h * NS + lane];
        wch[b * NS + lane] = 1.f / (1.f + expf(-a));
    }
}

__global__ __launch_bounds__(320) void se2_kernel(const float* __restrict__ Gh,
                                                  const float* __restrict__ Wf1,
                                                  const float* __restrict__ Wf2,
                                                  float* __restrict__ wft)
{
    __shared__ float m[4][300];
    __shared__ float t1[4][152];
    const int b0 = blockIdx.x * 4, tid = threadIdx.x;
    if (tid < 300) {
        #pragma unroll
        for (int bb = 0; bb < 4; bb++) {
            float a = 0.f;
            for (int s = 0; s < NS; s++) a += Gh[(size_t)(b0 + bb) * 9000 + s * 300 + tid];
            m[bb][tid] = a * (1.f / 30.f);
        }
    }
    __syncthreads();
    if (tid < 150) {
        float a[4] = {0.f, 0.f, 0.f, 0.f};
        for (int j = 0; j < 300; j++) {
            float w = Wf1[j * 150 + tid];
            #pragma unroll
            for (int bb = 0; bb < 4; bb++) a[bb] += m[bb][j] * w;
        }
        #pragma unroll
        for (int bb = 0; bb < 4; bb++) t1[bb][tid] = fmaxf(a[bb], 0.f);
    }
    __syncthreads();
    if (tid < 300) {
        float a[4] = {0.f, 0.f, 0.f, 0.f};
        for (int h = 0; h < 150; h++) {
            float w = Wf2[h * 300 + tid];
            #pragma unroll
            for (int bb = 0; bb < 4; bb++) a[bb] += t1[bb][h] * w;
        }
        #pragma unroll
        for (int bb = 0; bb < 4; bb++)
            wft[(size_t)(b0 + bb) * 300 + tid] = 1.f / (1.f + expf(-a[bb]));
    }
}

// ---------------- classifier + log_softmax (4 batches per block, direct Wcls) ----------------
__global__ __launch_bounds__(256) void cls_kernel(
    const float* __restrict__ Gh, const float* __restrict__ Gv,
    const float* __restrict__ wch, const float* __restrict__ wft,
    const float* __restrict__ Wcls, const float* __restrict__ bcls, float* __restrict__ out)
{
    const int b0 = blockIdx.x * 4, tid = threadIdx.x;
    const int lane = tid & 31, warp = tid >> 5;
    float acc[4][NCL];
    #pragma unroll
    for (int bb = 0; bb < 4; bb++)
        #pragma unroll
        for (int k = 0; k < NCL; k++) acc[bb][k] = 0.f;

    for (int idx = tid; idx < 18000; idx += 256) {
        int s = idx / 600;
        int c = idx - s * 600;
        float w[NCL];
        #pragma unroll
        for (int k = 0; k < NCL; k++) w[k] = Wcls[(size_t)idx * NCL + k];
        #pragma unroll
        for (int bb = 0; bb < 4; bb++) {
            int b = b0 + bb;
            float val;
            if (c < 300) val = Gh[(size_t)b * 9000 + s * 300 + c] * wch[b * NS + s];
            else {
                int cc = c - 300;
                val = Gv[(size_t)b * 9000 + s * 300 + cc] * wft[(size_t)b * 300 + cc];
            }
            #pragma unroll
            for (int k = 0; k < NCL; k++) acc[bb][k] += val * w[k];
        }
    }
    #pragma unroll
    for (int bb = 0; bb < 4; bb++)
        #pragma unroll
        for (int k = 0; k < NCL; k++)
            #pragma unroll
            for (int o = 16; o; o >>= 1)
                acc[bb][k] += __shfl_xor_sync(0xffffffffu, acc[bb][k], o);
    __shared__ float red[8][4][NCL];
    __shared__ float zs[4][NCL];
    if (lane == 0) {
        #pragma unroll
        for (int bb = 0; bb < 4; bb++)
            #pragma unroll
            for (int k = 0; k < NCL; k++) red[warp][bb][k] = acc[bb][k];
    }
    __syncthreads();
    if (tid < 28) {
        int bb = tid / 7, k = tid - bb * 7;
        float z = bcls[k];
        #pragma unroll
        for (int w2 = 0; w2 < 8; w2++) z += red[w2][bb][k];
        zs[bb][k] = z;
    }
    __syncthreads();
    if (tid < 4) {
        float mx = -1e30f;
        #pragma unroll
        for (int k = 0; k < NCL; k++) mx = fmaxf(mx, zs[tid][k]);
        float s = 0.f;
        #pragma unroll
        for (int k = 0; k < NCL; k++) s += expf(zs[tid][k] - mx);
        float ls = logf(s);
        #pragma unroll
        for (int k = 0; k < NCL; k++) out[(b0 + tid) * NCL + k] = zs[tid][k] - mx - ls;
    }
}

// ---------------- launch ----------------
extern "C" void kernel_launch(void* const* d_in, const int* in_sizes, int n_in,
                              void* d_out, int out_size)
{
    const float* x    = (const float*)d_in[0];
    const float* adj  = (const float*)d_in[1];
    const float* Wc1  = (const float*)d_in[2];
    const float* bc1  = (const float*)d_in[3];
    const float* Wc2  = (const float*)d_in[4];
    const float* bc2  = (const float*)d_in[5];
    const float* Wt   = (const float*)d_in[6];
    const float* bt   = (const float*)d_in[7];
    const float* Wa   = (const float*)d_in[8];
    const float* Wm1  = (const float*)d_in[9];
    const float* Wm2  = (const float*)d_in[10];
    const float* Wm3  = (const float*)d_in[11];
    const float* Wg1  = (const float*)d_in[12];
    const float* Wg2  = (const float*)d_in[13];
    const float* wg   = (const float*)d_in[14];
    const float* Wp1  = (const float*)d_in[15];
    const float* Wp2  = (const float*)d_in[16];
    const float* Wp3  = (const float*)d_in[17];
    const float* Wl   = (const float*)d_in[18];
    const float* Wgl  = (const float*)d_in[19];
    const float* Ws1  = (const float*)d_in[20];
    const float* Ws2  = (const float*)d_in[21];
    const float* Wf1  = (const float*)d_in[22];
    const float* Wf2  = (const float*)d_in[23];
    const float* Wcls = (const float*)d_in[24];
    const float* bcls = (const float*)d_in[25];
    float* out = (float*)d_out;

    float *p_h2, *p_F2, *p_tmp, *p_P1, *p_x1, *p_x2, *p_x3, *p_Q, *p_h1s, *p_xsn;
    float *p_gH1, *p_gH2, *p_gH3, *p_AF, *p_Gh, *p_Gv, *p_wch, *p_wft;
    uint4 *p_b4, *p_cw1, *p_cw2;
    cudaGetSymbolAddress((void**)&p_h2,  g_h2);
    cudaGetSymbolAddress((void**)&p_F2,  g_F2);
    cudaGetSymbolAddress((void**)&p_tmp, g_tmp);
    cudaGetSymbolAddress((void**)&p_P1,  g_P1);
    cudaGetSymbolAddress((void**)&p_x1,  g_x1);
    cudaGetSymbolAddress((void**)&p_x2,  g_x2);
    cudaGetSymbolAddress((void**)&p_x3,  g_x3);
    cudaGetSymbolAddress((void**)&p_Q,   g_Q);
    cudaGetSymbolAddress((void**)&p_h1s, g_h1s);
    cudaGetSymbolAddress((void**)&p_xsn, g_xsn);
    cudaGetSymbolAddress((void**)&p_gH1, g_gH1);
    cudaGetSymbolAddress((void**)&p_gH2, g_gH2);
    cudaGetSymbolAddress((void**)&p_gH3, g_gH3);
    cudaGetSymbolAddress((void**)&p_AF,  g_AF);
    cudaGetSymbolAddress((void**)&p_Gh,  g_Gh);
    cudaGetSymbolAddress((void**)&p_Gv,  g_Gv);
    cudaGetSymbolAddress((void**)&p_wch, g_wch);
    cudaGetSymbolAddress((void**)&p_wft, g_wft);
    cudaGetSymbolAddress((void**)&p_b4,  g_bf4);
    cudaGetSymbolAddress((void**)&p_cw1, g_cw1);
    cudaGetSymbolAddress((void**)&p_cw2, g_cw2);

    // fragment pool offsets (uint4 units): count = nT * nks * 32
    const int oWt  = 0;
    const int oWa  = 51200;
    const int oWm1 = 61600, oWm2 = 72000, oWm3 = 82400;
    const int oWg1 = 92800, oWg2 = 103200;
    const int oWp1 = 113600, oWp2 = 119008, oWp3 = 124416;
    const int oWl  = 129824, oWgl = 137728;

    PJobs J;
    const float* Ws[12] = {Wt, Wa, Wm1, Wm2, Wm3, Wg1, Wg2, Wp1, Wp2, Wp3, Wl, Wgl};
    const int   Ks[12] = {1024, 200, 200, 200, 200, 200, 200, 200, 200, 200, 200, 200};
    const int   Nn[12] = {200, 200, 200, 200, 200, 200, 200, 100, 100, 100, 150, 150};
    const int   Tt[12] = {25, 25, 25, 25, 25, 25, 25, 13, 13, 13, 19, 19};
    const int   Kk[12] = {64, 13, 13, 13, 13, 13, 13, 13, 13, 13, 13, 13};
    const int   Of[12] = {oWt, oWa, oWm1, oWm2, oWm3, oWg1, oWg2, oWp1, oWp2, oWp3, oWl, oWgl};
    for (int i = 0; i < 12; i++) {
        J.W[i] = Ws[i]; J.K[i] = Ks[i]; J.N[i] = Nn[i];
        J.nT[i] = Tt[i]; J.nks[i] = Kk[i]; J.off[i] = Of[i];
    }

    const int GBMM_SMEM = 24900 * 4;
    cudaFuncSetAttribute(gbmm_kernel, cudaFuncAttributeMaxDynamicSharedMemorySize, GBMM_SMEM);

    prepall_kernel<<<dim3(200, 12), 256>>>(J, p_b4);
    prepcw_kernel<<<3, 256>>>(Wc1, p_cw1);
    prepcw_kernel<<<3, 256>>>(Wc2, p_cw2);

    const int GM = MROWS / 64;   // 480 CTAs
    dim3 gS(GM, 2);

    // CNN feature extractor (fused HMMA conv, smem-staged x)
    convf_kernel<<<dim3(16, BATCH), 128>>>(x, p_cw1, bc1, p_cw2, bc2, p_h2);
    mgemmS_kernel<<<gS, 128>>>(p_h2, p_b4+oWt, bt, p_F2, 1024, 64, 200, 1);

    // learned adjacency
    mgemmS_kernel<<<gS, 128>>>(p_F2, p_b4+oWa, nullptr, p_tmp, 200, 13, 200, 0);
    af_kernel<<<BATCH, 128>>>(p_tmp, p_F2, p_AF);

    // P1 = A_F@F2, Q = adj@F2 (merged)
    bmm2_kernel<<<dim3(BATCH, 2), 256>>>(p_AF, adj, p_F2, p_P1, p_Q);

    // MGCN 3-order
    mgemmS_kernel<<<gS, 128>>>(p_P1, p_b4+oWm1, nullptr, p_x1, 200, 13, 200, 1);
    bmm30_kernel<<<BATCH, 256>>>(p_AF, p_x1, p_tmp, 1);
    mgemmS_kernel<<<gS, 128>>>(p_tmp, p_b4+oWm2, nullptr, p_x2, 200, 13, 200, 1);
    bmm30_kernel<<<BATCH, 256>>>(p_AF, p_x2, p_tmp, 1);
    mgemmS_kernel<<<gS, 128>>>(p_tmp, p_b4+oWm3, nullptr, p_x3, 200, 13, 200, 1);

    // signal GCN
    mgemmS_kernel<<<gS, 128>>>(p_Q, p_b4+oWg1, nullptr, p_h1s, 200, 13, 200, 1);
    bmm30_kernel<<<BATCH, 256>>>(adj, p_h1s, p_tmp, 0);
    mgemmS_kernel<<<gS, 128>>>(p_tmp, p_b4+oWg2, nullptr, p_xsn, 200, 13, 200, 0);

    // fused gate + adj-aggregation
    gbmm_kernel<<<BATCH, 256, GBMM_SMEM>>>(adj, p_x1, p_x2, p_x3, p_xsn, wg, p_gH1, p_gH2, p_gH3);

    // G_h: 3 projections (merged, N-split)
    mgemm3_kernel<<<dim3(GM, 6), 128>>>(p_gH1, p_gH2, p_gH3, p_b4+oWp1, p_Gh);

    // G_v: LGFM (merged, N-split)
    mgemm2_kernel<<<dim3(GM, 4), 128>>>(p_Q, p_P1, p_b4+oWl, p_Gv);

    // cross SE
    se1_kernel<<<BATCH, 32>>>(p_Gv, Ws1, Ws2, p_wch);
    se2_kernel<<<BATCH / 4, 320>>>(p_Gh, Wf1, Wf2, p_wft);

    // classifier
    cls_kernel<<<BATCH / 4, 256>>>(p_Gh, p_Gv, p_wch, p_wft, Wcls, bcls, out);
}

// round 10
// speedup vs baseline: 1.1402x; 1.1402x over previous
#include <cuda_runtime.h>
#include <cuda_bf16.h>
#include <cstdint>
#include <cstdio>

#define BATCH 1024
#define NS    30
#define NT    1024
#define NFD   200
#define NCL   7
#define MROWS (BATCH*NS)      // 30720

static inline int cdiv(int a, int b) { return (a + b - 1) / b; }

// ---------------- scratch (device globals; no allocation) ----------------
__device__ float g_h2  [BATCH*NS*NT];
__device__ float g_F2  [MROWS*NFD];
__device__ float g_tmp [MROWS*NFD];
__device__ float g_P1  [MROWS*NFD];
__device__ float g_x1  [MROWS*NFD];
__device__ float g_x2  [MROWS*NFD];
__device__ float g_x3  [MROWS*NFD];
__device__ float g_Q   [MROWS*NFD];
__device__ float g_h1s [MROWS*NFD];
__device__ float g_xsn [MROWS*NFD];
__device__ float g_gH1 [MROWS*NFD];
__device__ float g_gH2 [MROWS*NFD];
__device__ float g_gH3 [MROWS*NFD];
__device__ float g_AF  [BATCH*NS*NS];
__device__ float g_Gh  [MROWS*300];
__device__ float g_Gv  [MROWS*300];
__device__ float g_wch [MROWS];
__device__ float g_wft [BATCH*300];

// packed weight fragments: uint4 = {hi_r0, hi_r1, lo_r0, lo_r1}
__device__ uint4 g_bf4[150000];
__device__ uint4 g_cw1[768];
__device__ uint4 g_cw2[768];

// ---------------- mma + split helpers ----------------
__device__ __forceinline__ void mma16816(float* c, uint32_t a0, uint32_t a1, uint32_t a2, uint32_t a3,
                                         uint32_t b0, uint32_t b1) {
    asm volatile("mma.sync.aligned.m16n8k16.row.col.f32.bf16.bf16.f32 "
        "{%0,%1,%2,%3}, {%4,%5,%6,%7}, {%8,%9}, {%0,%1,%2,%3};"
        : "+f"(c[0]), "+f"(c[1]), "+f"(c[2]), "+f"(c[3])
        : "r"(a0), "r"(a1), "r"(a2), "r"(a3), "r"(b0), "r"(b1));
}
__device__ __forceinline__ void split2(float2 v, uint32_t& hi, uint32_t& lo) {
    __nv_bfloat162 h = __floats2bfloat162_rn(v.x, v.y);
    float2 hf = __bfloat1622float2(h);
    __nv_bfloat162 l = __floats2bfloat162_rn(v.x - hf.x, v.y - hf.y);
    hi = reinterpret_cast<uint32_t&>(h);
    lo = reinterpret_cast<uint32_t&>(l);
}

// ---------------- merged weight prep: all 12 GEMM weights in one launch ----------------
struct PJobs {
    const float* W[12];
    int K[12], N[12], nT[12], nks[12], off[12];   // off in uint4 units
};
__global__ void prepall_kernel(PJobs J, uint4* __restrict__ out)
{
    const int j = blockIdx.y;
    const int idx = blockIdx.x * 256 + threadIdx.x;
    const int nks = J.nks[j];
    const int total = J.nT[j] * nks * 32;
    if (idx >= total) return;
    const int K = J.K[j], N = J.N[j];
    const float* W = J.W[j];
    int lane = idx & 31;
    int s = idx >> 5;
    int ks = s % nks;
    int t  = s / nks;
    int n = t * 8 + (lane >> 2);
    float v[4];
    #pragma unroll
    for (int reg = 0; reg < 2; reg++) {
        #pragma unroll
        for (int jj = 0; jj < 2; jj++) {
            int k = ks * 16 + (lane & 3) * 2 + reg * 8 + jj;
            v[reg * 2 + jj] = (n < N && k < K) ? W[(size_t)k * N + n] : 0.f;
        }
    }
    uint32_t h0, l0, h1, l1;
    split2(make_float2(v[0], v[1]), h0, l0);
    split2(make_float2(v[2], v[3]), h1, l1);
    out[J.off[j] + idx] = make_uint4(h0, h1, l0, l1);
}

// ---------------- conv weight prep: Wc[30,30,3] -> 768 uint4 frags, kidx = kk*32 + i ----------------
__global__ void prepcw_kernel(const float* __restrict__ W, uint4* __restrict__ out)
{
    int idx = blockIdx.x * 256 + threadIdx.x;
    if (idx >= 768) return;
    int lane = idx & 31;
    int ks = (idx >> 5) % 6;
    int t  = idx / 192;
    int n = t * 8 + (lane >> 2);
    float v[4];
    #pragma unroll
    for (int reg = 0; reg < 2; reg++) {
        #pragma unroll
        for (int jj = 0; jj < 2; jj++) {
            int kidx = ks * 16 + (lane & 3) * 2 + reg * 8 + jj;
            int kk = kidx >> 5, i = kidx & 31;
            float w = 0.f;
            if (n < 30 && i < 30) w = W[(n * 30 + i) * 3 + kk];
            v[reg * 2 + jj] = w;
        }
    }
    uint32_t h0, l0, h1, l1;
    split2(make_float2(v[0], v[1]), h0, l0);
    split2(make_float2(v[2], v[3]), h1, l1);
    out[idx] = make_uint4(h0, h1, l0, l1);
}

// ---------------- fused conv (HMMA, layer1 -> smem -> layer2), 64 t-rows/block ----------------
// kidx = kk*32 + i for BOTH layers (no integer divides); round-8 proven version
__device__ __forceinline__ float ldx(const float* __restrict__ xb, int r, int kidx)
{
    int i = kidx & 31, kk = kidx >> 5;
    int ts = r + kk - 1;
    return (i < NS && ts >= 0 && ts < NT) ? xb[i * NT + ts] : 0.f;
}
__device__ __forceinline__ void conv_l1_group(
    const float* __restrict__ xb, const uint4* __restrict__ Wf, const float* __restrict__ bc1,
    uint2 (*h1s)[16], int t0, int g, int tlo, int thi, int lane)
{
    const int gq = lane >> 2, kq = (lane & 3) * 2;
    const int r0 = t0 - 8 + g * 16 + gq, r1 = r0 + 8;
    float acc[4][4];
    #pragma unroll
    for (int t = 0; t < 4; t++) { acc[t][0] = 0.f; acc[t][1] = 0.f; acc[t][2] = 0.f; acc[t][3] = 0.f; }
    for (int ks = 0; ks < 6; ks++) {
        int kb = ks * 16 + kq;
        float v00 = ldx(xb, r0, kb),     v01 = ldx(xb, r0, kb + 1);
        float v10 = ldx(xb, r1, kb),     v11 = ldx(xb, r1, kb + 1);
        float v02 = ldx(xb, r0, kb + 8), v03 = ldx(xb, r0, kb + 9);
        float v12 = ldx(xb, r1, kb + 8), v13 = ldx(xb, r1, kb + 9);
        uint32_t ah0, al0, ah1, al1, ah2, al2, ah3, al3;
        split2(make_float2(v00, v01), ah0, al0);
        split2(make_float2(v10, v11), ah1, al1);
        split2(make_float2(v02, v03), ah2, al2);
        split2(make_float2(v12, v13), ah3, al3);
        const uint4* bp = Wf + ks * 32 + lane;
        #pragma unroll
        for (int t = 0; t < 4; t++) {
            if (t < tlo || t >= thi) continue;
            uint4 w = bp[t * 192];
            mma16816(acc[t], ah0, ah1, ah2, ah3, w.x, w.y);
            mma16816(acc[t], ah0, ah1, ah2, ah3, w.z, w.w);
            mma16816(acc[t], al0, al1, al2, al3, w.x, w.y);
        }
    }
    const int sr0 = g * 16 + gq, sr1 = sr0 + 8;
    #pragma unroll
    for (int t = 0; t < 4; t++) {
        if (t < tlo || t >= thi) continue;
        int n0 = t * 8 + kq;
        float bb0 = (n0 < 30) ? bc1[n0] : 0.f;
        float bb1 = (n0 + 1 < 30) ? bc1[n0 + 1] : 0.f;
        float v0 = fmaxf(acc[t][0] + bb0, 0.f), v1 = fmaxf(acc[t][1] + bb1, 0.f);
        float v2 = fmaxf(acc[t][2] + bb0, 0.f), v3 = fmaxf(acc[t][3] + bb1, 0.f);
        uint32_t h, l;
        split2(make_float2(v0, v1), h, l);
        h1s[sr0][t * 4 + (kq >> 1)] = make_uint2(h, l);
        split2(make_float2(v2, v3), h, l);
        h1s[sr1][t * 4 + (kq >> 1)] = make_uint2(h, l);
    }
}

__global__ __launch_bounds__(128) void convf_kernel(
    const float* __restrict__ x, const uint4* __restrict__ Wf1, const float* __restrict__ bc1,
    const uint4* __restrict__ Wf2, const float* __restrict__ bc2, float* __restrict__ out)
{
    __shared__ uint2 h1s[80][16];
    const int b = blockIdx.y;
    const int t0 = blockIdx.x * 64;
    const int lane = threadIdx.x & 31, warp = threadIdx.x >> 5;
    const float* xb = x + (size_t)b * NS * NT;

    // layer 1: 5 row-groups cover t in [t0-8, t0+72)
    conv_l1_group(xb, Wf1, bc1, h1s, t0, warp, 0, 4, lane);
    if (warp < 2) conv_l1_group(xb, Wf1, bc1, h1s, t0, 4, warp * 2, warp * 2 + 2, lane);
    __syncthreads();

    // layer 2: rows t0 + warp*16 ..
    const int gq = lane >> 2, kq = (lane & 3) * 2;
    const int r0 = t0 + warp * 16 + gq, r1 = r0 + 8;
    float acc[4][4];
    #pragma unroll
    for (int t = 0; t < 4; t++) { acc[t][0] = 0.f; acc[t][1] = 0.f; acc[t][2] = 0.f; acc[t][3] = 0.f; }
    for (int ks = 0; ks < 6; ks++) {
        int kb = ks * 16 + kq;
        int kk = kb >> 5;
        int i  = kb & 31;
        int ts0 = r0 + kk - 1, ts1 = r1 + kk - 1;
        int s0 = ts0 - (t0 - 8), s1 = ts1 - (t0 - 8);
        uint2 z = make_uint2(0u, 0u);
        uint2 p00 = (ts0 >= 0 && ts0 < NT) ? h1s[s0][i >> 1]       : z;
        uint2 p01 = (ts0 >= 0 && ts0 < NT) ? h1s[s0][(i + 8) >> 1] : z;
        uint2 p10 = (ts1 >= 0 && ts1 < NT) ? h1s[s1][i >> 1]       : z;
        uint2 p11 = (ts1 >= 0 && ts1 < NT) ? h1s[s1][(i + 8) >> 1] : z;
        const uint4* bp = Wf2 + ks * 32 + lane;
        #pragma unroll
        for (int t = 0; t < 4; t++) {
            uint4 w = bp[t * 192];
            mma16816(acc[t], p00.x, p10.x, p01.x, p11.x, w.x, w.y);
            mma16816(acc[t], p00.x, p10.x, p01.x, p11.x, w.z, w.w);
            mma16816(acc[t], p00.y, p10.y, p01.y, p11.y, w.x, w.y);
        }
    }
    #pragma unroll
    for (int t = 0; t < 4; t++) {
        int n0 = t * 8 + kq;
        if (n0 < 30) {
            float bb = bc2[n0];
            out[((size_t)b * NS + n0) * NT + r0] = fmaxf(acc[t][0] + bb, 0.f);
            out[((size_t)b * NS + n0) * NT + r1] = fmaxf(acc[t][2] + bb, 0.f);
        }
        if (n0 + 1 < 30) {
            float bb = bc2[n0 + 1];
            out[((size_t)b * NS + n0 + 1) * NT + r0] = fmaxf(acc[t][1] + bb, 0.f);
            out[((size_t)b * NS + n0 + 1) * NT + r1] = fmaxf(acc[t][3] + bb, 0.f);
        }
    }
}

// ---------------- HMMA split-bf16 GEMM body ----------------
template<int NTl>
__device__ __forceinline__ void mgemm_body(
    const float* __restrict__ A, const uint4* __restrict__ B4,
    const float* __restrict__ bias, float* __restrict__ C,
    int N, int K, int nks, int ldc, int coloff, int relu)
{
    const int lane = threadIdx.x & 31;
    const int warp = threadIdx.x >> 5;
    const int gq = lane >> 2;
    const int q  = lane & 3;
    const int r0 = blockIdx.x * 64 + warp * 16 + gq;
    const int r1 = r0 + 8;
    const int kq = q * 2;

    float acc[NTl][4];
    #pragma unroll
    for (int t = 0; t < NTl; t++) {
        acc[t][0] = 0.f; acc[t][1] = 0.f; acc[t][2] = 0.f; acc[t][3] = 0.f;
    }

    const float* a0p = A + (size_t)r0 * K;
    const float* a1p = A + (size_t)r1 * K;

    for (int ks = 0; ks < nks; ks++) {
        const int kb = ks * 16 + kq;
        float2 x00 = (kb     < K) ? *reinterpret_cast<const float2*>(a0p + kb)     : make_float2(0.f, 0.f);
        float2 x01 = (kb + 8 < K) ? *reinterpret_cast<const float2*>(a0p + kb + 8) : make_float2(0.f, 0.f);
        float2 x10 = (kb     < K) ? *reinterpret_cast<const float2*>(a1p + kb)     : make_float2(0.f, 0.f);
        float2 x11 = (kb + 8 < K) ? *reinterpret_cast<const float2*>(a1p + kb + 8) : make_float2(0.f, 0.f);
        uint32_t ah0, al0, ah1, al1, ah2, al2, ah3, al3;
        split2(x00, ah0, al0);
        split2(x10, ah1, al1);
        split2(x01, ah2, al2);
        split2(x11, ah3, al3);
        const uint4* bp = B4 + ks * 32 + lane;
        const int stride = nks * 32;
        #pragma unroll
        for (int t = 0; t < NTl; t++) {
            uint4 w = bp[(size_t)t * stride];
            mma16816(acc[t], ah0, ah1, ah2, ah3, w.x, w.y);
            mma16816(acc[t], ah0, ah1, ah2, ah3, w.z, w.w);
            mma16816(acc[t], al0, al1, al2, al3, w.x, w.y);
        }
    }

    #pragma unroll
    for (int t = 0; t < NTl; t++) {
        int n0 = t * 8 + kq;
        if (n0 < N) {
            float b0v = bias ? bias[n0] : 0.f;
            float b1v = bias ? bias[n0 + 1] : 0.f;
            float v0 = acc[t][0] + b0v, v1 = acc[t][1] + b1v;
            float v2 = acc[t][2] + b0v, v3 = acc[t][3] + b1v;
            if (relu) {
                v0 = fmaxf(v0, 0.f); v1 = fmaxf(v1, 0.f);
                v2 = fmaxf(v2, 0.f); v3 = fmaxf(v3, 0.f);
            }
            *reinterpret_cast<float2*>(&C[(size_t)r0 * ldc + coloff + n0]) = make_float2(v0, v1);
            *reinterpret_cast<float2*>(&C[(size_t)r1 * ldc + coloff + n0]) = make_float2(v2, v3);
        }
    }
}

// plain full-N GEMM (for K=1024 F2 projection: A traffic dominates, no N-split)
template<int NTl>
__global__ __launch_bounds__(128, 3) void mgemm_kernel(
    const float* __restrict__ A, const uint4* __restrict__ B4,
    const float* __restrict__ bias, float* __restrict__ C,
    int N, int K, int nks, int ldc, int coloff, int relu)
{
    mgemm_body<NTl>(A, B4, bias, C, N, K, nks, ldc, coloff, relu);
}

// N-split GEMM (200 cols -> 104 + 96), grid (480, 2)
__global__ __launch_bounds__(128, 4) void mgemmS_kernel(
    const float* __restrict__ A, const uint4* __restrict__ B4,
    const float* __restrict__ bias, float* __restrict__ C,
    int K, int nks, int ldc, int relu)
{
    if (blockIdx.y == 0)
        mgemm_body<13>(A, B4, bias, C, 104, K, nks, ldc, 0, relu);
    else
        mgemm_body<12>(A, B4 + 13 * nks * 32, bias ? bias + 104 : nullptr, C, 96, K, nks, ldc, 104, relu);
}

// merged 3x (N=100, K=200), split 56+44, grid (480, 6)
__global__ __launch_bounds__(128, 4) void mgemm3_kernel(
    const float* __restrict__ A0, const float* __restrict__ A1, const float* __restrict__ A2,
    const uint4* __restrict__ B4, float* __restrict__ C)
{
    const int j = blockIdx.y >> 1, h = blockIdx.y & 1;
    const float* A = (j == 0) ? A0 : (j == 1) ? A1 : A2;
    const uint4* B = B4 + j * 5408;
    if (h == 0) mgemm_body<7>(A, B, nullptr, C, 56, 200, 13, 300, j * 100, 0);
    else        mgemm_body<6>(A, B + 7 * 13 * 32, nullptr, C, 44, 200, 13, 300, j * 100 + 56, 0);
}

// merged 2x (N=150, K=200, relu), split 80+70, grid (480, 4)
__global__ __launch_bounds__(128, 4) void mgemm2_kernel(
    const float* __restrict__ A0, const float* __restrict__ A1,
    const uint4* __restrict__ B4, float* __restrict__ C)
{
    const int j = blockIdx.y >> 1, h = blockIdx.y & 1;
    const float* A = j ? A1 : A0;
    const uint4* B = B4 + j * 7904;
    if (h == 0) mgemm_body<10>(A, B, nullptr, C, 80, 200, 13, 300, j * 150, 1);
    else        mgemm_body<9>(A, B + 10 * 13 * 32, nullptr, C, 70, 200, 13, 300, j * 150 + 80, 1);
}

// ---------------- batched small matmul body: Out[b] = A @ X[b] ----------------
__device__ __forceinline__ void bmm30_body(
    const float* __restrict__ Am, const float* __restrict__ X, float* __restrict__ Out,
    int batched, int b, int tid)
{
    __shared__ float As[NS * NS];
    __shared__ float Xs[NS * NFD];
    const float* A = batched ? (Am + (size_t)b * NS * NS) : Am;
    for (int i = tid; i < NS * NS; i += 256) As[i] = A[i];
    for (int i = tid; i < NS * NFD; i += 256) Xs[i] = X[(size_t)b * NS * NFD + i];
    __syncthreads();
    if (tid < 250) {
        int si = tid / 25, fi = tid - (tid / 25) * 25;
        int s0 = si * 3, f0 = fi * 8;
        float acc[3][8];
        #pragma unroll
        for (int r = 0; r < 3; r++)
            #pragma unroll
            for (int q = 0; q < 8; q++) acc[r][q] = 0.f;
        for (int j = 0; j < NS; j++) {
            float a0 = As[(s0 + 0) * NS + j];
            float a1 = As[(s0 + 1) * NS + j];
            float a2 = As[(s0 + 2) * NS + j];
            float4 xA = *reinterpret_cast<const float4*>(&Xs[j * NFD + f0]);
            float4 xB = *reinterpret_cast<const float4*>(&Xs[j * NFD + f0 + 4]);
            float xv[8] = {xA.x, xA.y, xA.z, xA.w, xB.x, xB.y, xB.z, xB.w};
            #pragma unroll
            for (int q = 0; q < 8; q++) {
                acc[0][q] += a0 * xv[q];
                acc[1][q] += a1 * xv[q];
                acc[2][q] += a2 * xv[q];
            }
        }
        #pragma unroll
        for (int r = 0; r < 3; r++)
            #pragma unroll
            for (int q = 0; q < 8; q++)
                Out[(size_t)b * NS * NFD + (s0 + r) * NFD + f0 + q] = acc[r][q];
    }
}

__global__ __launch_bounds__(256) void bmm30_kernel(
    const float* __restrict__ Am, const float* __restrict__ X, float* __restrict__ Out, int batched)
{
    bmm30_body(Am, X, Out, batched, blockIdx.x, threadIdx.x);
}

// merged P1 = A_F@F2 (y=0) and Q = adj@F2 (y=1)
__global__ __launch_bounds__(256) void bmm2_kernel(
    const float* __restrict__ AF, const float* __restrict__ adj,
    const float* __restrict__ F2, float* __restrict__ P1, float* __restrict__ Q)
{
    if (blockIdx.y == 0) bmm30_body(AF, F2, P1, 1, blockIdx.x, threadIdx.x);
    else                 bmm30_body(adj, F2, Q, 0, blockIdx.x, threadIdx.x);
}

// ---------------- fused gate + 3x bmm30(adj, g_k*H_k) ----------------
__global__ __launch_bounds__(256) void gbmm_kernel(
    const float* __restrict__ adj, const float* __restrict__ x1, const float* __restrict__ x2,
    const float* __restrict__ x3, const float* __restrict__ xsn, const float* __restrict__ wg,
    float* __restrict__ o1, float* __restrict__ o2, float* __restrict__ o3)
{
    extern __shared__ float sm[];
    float* As = sm;                                   // 900
    float* X0 = sm + 900;                             // 6000 each
    float* X1 = sm + 6900;
    float* X2 = sm + 12900;
    float* Xs = sm + 18900;
    const int b = blockIdx.x, tid = threadIdx.x;
    const size_t base = (size_t)b * 6000;
    for (int i = tid; i < 900; i += 256) As[i] = adj[i];
    for (int i = tid; i < 6000; i += 256) {
        X0[i] = x1[base + i];
        X1[i] = x2[base + i];
        X2[i] = x3[base + i];
        Xs[i] = xsn[base + i];
    }
    __syncthreads();

    {
        const int warp = tid >> 5, lane = tid & 31;
        for (int rr = 0; rr < 4; rr++) {
            int r = warp * 4 + rr;
            if (r >= NS) break;
            float H0[7], H1[7], H2[7];
            float s0 = 0.f, s1 = 0.f, s2 = 0.f;
            #pragma unroll
            for (int q = 0; q < 7; q++) {
                int f = q * 32 + lane;
                float h0 = 0.f, h1 = 0.f, h2 = 0.f;
                if (f < NFD) {
                    float sv = Xs[r * NFD + f];
                    h0 = (X0[r * NFD + f] + sv) * 0.5f;
                    h1 = (X1[r * NFD + f] + sv) * 0.5f;
                    h2 = (X2[r * NFD + f] + sv) * 0.5f;
                    s0 += h0 * wg[f * 3 + 0];
                    s1 += h1 * wg[f * 3 + 1];
                    s2 += h2 * wg[f * 3 + 2];
                }
                H0[q] = h0; H1[q] = h1; H2[q] = h2;
            }
            #pragma unroll
            for (int o = 16; o; o >>= 1) {
                s0 += __shfl_xor_sync(0xffffffffu, s0, o);
                s1 += __shfl_xor_sync(0xffffffffu, s1, o);
                s2 += __shfl_xor_sync(0xffffffffu, s2, o);
            }
            float mx = fmaxf(s0, fmaxf(s1, s2));
            float e0 = expf(s0 - mx), e1 = expf(s1 - mx), e2 = expf(s2 - mx);
            float inv = 1.f / (e0 + e1 + e2);
            e0 *= inv; e1 *= inv; e2 *= inv;
            #pragma unroll
            for (int q = 0; q < 7; q++) {
                int f = q * 32 + lane;
                if (f < NFD) {
                    X0[r * NFD + f] = e0 * H0[q];
                    X1[r * NFD + f] = e1 * H1[q];
                    X2[r * NFD + f] = e2 * H2[q];
                }
            }
        }
    }
    __syncthreads();

    if (tid < 250) {
        int si = tid / 25, fi = tid - (tid / 25) * 25;
        int s0 = si * 3, f0 = fi * 8;
        float* Xk[3] = {X0, X1, X2};
        float* Ok[3] = {o1, o2, o3};
        #pragma unroll
        for (int k = 0; k < 3; k++) {
            const float* X = Xk[k];
            float acc[3][8];
            #pragma unroll
            for (int r = 0; r < 3; r++)
                #pragma unroll
                for (int q = 0; q < 8; q++) acc[r][q] = 0.f;
            for (int j = 0; j < NS; j++) {
                float a0 = As[(s0 + 0) * NS + j];
                float a1 = As[(s0 + 1) * NS + j];
                float a2 = As[(s0 + 2) * NS + j];
                float4 xA = *reinterpret_cast<const float4*>(&X[j * NFD + f0]);
                float4 xB = *reinterpret_cast<const float4*>(&X[j * NFD + f0 + 4]);
                float xv[8] = {xA.x, xA.y, xA.z, xA.w, xB.x, xB.y, xB.z, xB.w};
                #pragma unroll
                for (int q = 0; q < 8; q++) {
                    acc[0][q] += a0 * xv[q];
                    acc[1][q] += a1 * xv[q];
                    acc[2][q] += a2 * xv[q];
                }
            }
            #pragma unroll
            for (int r = 0; r < 3; r++)
                #pragma unroll
                for (int q = 0; q < 8; q++)
                    Ok[k][base + (s0 + r) * NFD + f0 + q] = acc[r][q];
        }
    }
}

// ---------------- A_F = softmax(relu(tmp @ F2^T)) per batch ----------------
__global__ __launch_bounds__(128) void af_kernel(
    const float* __restrict__ Tm, const float* __restrict__ F2, float* __restrict__ AF)
{
    __shared__ float Ts[NS * NFD];
    __shared__ float Fs[NS * NFD];
    const int b = blockIdx.x;
    const int tid = threadIdx.x;
    for (int i = tid; i < NS * NFD; i += 128) {
        Ts[i] = Tm[(size_t)b * NS * NFD + i];
        Fs[i] = F2[(size_t)b * NS * NFD + i];
    }
    __syncthreads();
    float acc[3][3];
    int ii = 0, jj = 0;
    if (tid < 100) {
        ii = (tid / 10) * 3; jj = (tid % 10) * 3;
        #pragma unroll
        for (int r = 0; r < 3; r++)
            #pragma unroll
            for (int c = 0; c < 3; c++) acc[r][c] = 0.f;
        for (int g = 0; g < NFD; g++) {
            float t0 = Ts[(ii + 0) * NFD + g], t1 = Ts[(ii + 1) * NFD + g], t2 = Ts[(ii + 2) * NFD + g];
            float f0 = Fs[(jj + 0) * NFD + g], f1 = Fs[(jj + 1) * NFD + g], f2 = Fs[(jj + 2) * NFD + g];
            acc[0][0] += t0 * f0; acc[0][1] += t0 * f1; acc[0][2] += t0 * f2;
            acc[1][0] += t1 * f0; acc[1][1] += t1 * f1; acc[1][2] += t1 * f2;
            acc[2][0] += t2 * f0; acc[2][1] += t2 * f1; acc[2][2] += t2 * f2;
        }
    }
    __syncthreads();
    float (*Ms)[31] = reinterpret_cast<float(*)[31]>(Ts);
    if (tid < 100) {
        #pragma unroll
        for (int r = 0; r < 3; r++)
            #pragma unroll
            for (int c = 0; c < 3; c++) Ms[ii + r][jj + c] = fmaxf(acc[r][c], 0.f);
    }
    __syncthreads();
    if (tid < NS) {
        float mx = -1e30f;
        for (int j = 0; j < NS; j++) mx = fmaxf(mx, Ms[tid][j]);
        float s = 0.f;
        for (int j = 0; j < NS; j++) s += expf(Ms[tid][j] - mx);
        float inv = 1.f / s;
        for (int j = 0; j < NS; j++)
            AF[(size_t)b * NS * NS + tid * NS + j] = expf(Ms[tid][j] - mx) * inv;
    }
}

// ---------------- SE blocks ----------------
__global__ void se1_kernel(const float* __restrict__ Gv, const float* __restrict__ Ws1,
                           const float* __restrict__ Ws2, float* __restrict__ wch)
{
    const int b = blockIdx.x;
    const int lane = threadIdx.x;
    __shared__ float mv[NS];
    __shared__ float av[15];
    for (int s = 0; s < NS; s++) {
        float p = 0.f;
        for (int j = lane; j < 300; j += 32) p += Gv[(size_t)b * 9000 + s * 300 + j];
        #pragma unroll
        for (int o = 16; o; o >>= 1) p += __shfl_xor_sync(0xffffffffu, p, o);
        if (lane == 0) mv[s] = p * (1.f / 300.f);
    }
    __syncwarp();
    if (lane < 15) {
        float a = 0.f;
        for (int s = 0; s < NS; s++) a += mv[s] * Ws1[s * 15 + lane];
        av[lane] = fmaxf(a, 0.f);
    }
    __syncwarp();
    if (lane < NS) {
        float a = 0.f;
        for (int h = 0; h < 15; h++) a += av[h] * Ws2[h * NS + lane];
        wch[b * NS + lane] = 1.f / (1.f + expf(-a));
    }
}

__global__ __launch_bounds__(320) void se2_kernel(const float* __restrict__ Gh,
                                                  const float* __restrict__ Wf1,
                                                  const float* __restrict__ Wf2,
                                                  float* __restrict__ wft)
{
    __shared__ float m[4][300];
    __shared__ float t1[4][152];
    const int b0 = blockIdx.x * 4, tid = threadIdx.x;
    if (tid < 300) {
        #pragma unroll
        for (int bb = 0; bb < 4; bb++) {
            float a = 0.f;
            for (int s = 0; s < NS; s++) a += Gh[(size_t)(b0 + bb) * 9000 + s * 300 + tid];
            m[bb][tid] = a * (1.f / 30.f);
        }
    }
    __syncthreads();
    if (tid < 150) {
        float a[4] = {0.f, 0.f, 0.f, 0.f};
        for (int j = 0; j < 300; j++) {
            float w = Wf1[j * 150 + tid];
            #pragma unroll
            for (int bb = 0; bb < 4; bb++) a[bb] += m[bb][j] * w;
        }
        #pragma unroll
        for (int bb = 0; bb < 4; bb++) t1[bb][tid] = fmaxf(a[bb], 0.f);
    }
    __syncthreads();
    if (tid < 300) {
        float a[4] = {0.f, 0.f, 0.f, 0.f};
        for (int h = 0; h < 150; h++) {
            float w = Wf2[h * 300 + tid];
            #pragma unroll
            for (int bb = 0; bb < 4; bb++) a[bb] += t1[bb][h] * w;
        }
        #pragma unroll
        for (int bb = 0; bb < 4; bb++)
            wft[(size_t)(b0 + bb) * 300 + tid] = 1.f / (1.f + expf(-a[bb]));
    }
}

// ---------------- classifier + log_softmax (4 batches per block, direct Wcls) ----------------
__global__ __launch_bounds__(256) void cls_kernel(
    const float* __restrict__ Gh, const float* __restrict__ Gv,
    const float* __restrict__ wch, const float* __restrict__ wft,
    const float* __restrict__ Wcls, const float* __restrict__ bcls, float* __restrict__ out)
{
    const int b0 = blockIdx.x * 4, tid = threadIdx.x;
    const int lane = tid & 31, warp = tid >> 5;
    float acc[4][NCL];
    #pragma unroll
    for (int bb = 0; bb < 4; bb++)
        #pragma unroll
        for (int k = 0; k < NCL; k++) acc[bb][k] = 0.f;

    for (int idx = tid; idx < 18000; idx += 256) {
        int s = idx / 600;
        int c = idx - s * 600;
        float w[NCL];
        #pragma unroll
        for (int k = 0; k < NCL; k++) w[k] = Wcls[(size_t)idx * NCL + k];
        #pragma unroll
        for (int bb = 0; bb < 4; bb++) {
            int b = b0 + bb;
            float val;
            if (c < 300) val = Gh[(size_t)b * 9000 + s * 300 + c] * wch[b * NS + s];
            else {
                int cc = c - 300;
                val = Gv[(size_t)b * 9000 + s * 300 + cc] * wft[(size_t)b * 300 + cc];
            }
            #pragma unroll
            for (int k = 0; k < NCL; k++) acc[bb][k] += val * w[k];
        }
    }
    #pragma unroll
    for (int bb = 0; bb < 4; bb++)
        #pragma unroll
        for (int k = 0; k < NCL; k++)
            #pragma unroll
            for (int o = 16; o; o >>= 1)
                acc[bb][k] += __shfl_xor_sync(0xffffffffu, acc[bb][k], o);
    __shared__ float red[8][4][NCL];
    __shared__ float zs[4][NCL];
    if (lane == 0) {
        #pragma unroll
        for (int bb = 0; bb < 4; bb++)
            #pragma unroll
            for (int k = 0; k < NCL; k++) red[warp][bb][k] = acc[bb][k];
    }
    __syncthreads();
    if (tid < 28) {
        int bb = tid / 7, k = tid - bb * 7;
        float z = bcls[k];
        #pragma unroll
        for (int w2 = 0; w2 < 8; w2++) z += red[w2][bb][k];
        zs[bb][k] = z;
    }
    __syncthreads();
    if (tid < 4) {
        float mx = -1e30f;
        #pragma unroll
        for (int k = 0; k < NCL; k++) mx = fmaxf(mx, zs[tid][k]);
        float s = 0.f;
        #pragma unroll
        for (int k = 0; k < NCL; k++) s += expf(zs[tid][k] - mx);
        float ls = logf(s);
        #pragma unroll
        for (int k = 0; k < NCL; k++) out[(b0 + tid) * NCL + k] = zs[tid][k] - mx - ls;
    }
}

// ---------------- launch ----------------
extern "C" void kernel_launch(void* const* d_in, const int* in_sizes, int n_in,
                              void* d_out, int out_size)
{
    const float* x    = (const float*)d_in[0];
    const float* adj  = (const float*)d_in[1];
    const float* Wc1  = (const float*)d_in[2];
    const float* bc1  = (const float*)d_in[3];
    const float* Wc2  = (const float*)d_in[4];
    const float* bc2  = (const float*)d_in[5];
    const float* Wt   = (const float*)d_in[6];
    const float* bt   = (const float*)d_in[7];
    const float* Wa   = (const float*)d_in[8];
    const float* Wm1  = (const float*)d_in[9];
    const float* Wm2  = (const float*)d_in[10];
    const float* Wm3  = (const float*)d_in[11];
    const float* Wg1  = (const float*)d_in[12];
    const float* Wg2  = (const float*)d_in[13];
    const float* wg   = (const float*)d_in[14];
    const float* Wp1  = (const float*)d_in[15];
    const float* Wp2  = (const float*)d_in[16];
    const float* Wp3  = (const float*)d_in[17];
    const float* Wl   = (const float*)d_in[18];
    const float* Wgl  = (const float*)d_in[19];
    const float* Ws1  = (const float*)d_in[20];
    const float* Ws2  = (const float*)d_in[21];
    const float* Wf1  = (const float*)d_in[22];
    const float* Wf2  = (const float*)d_in[23];
    const float* Wcls = (const float*)d_in[24];
    const float* bcls = (const float*)d_in[25];
    float* out = (float*)d_out;

    float *p_h2, *p_F2, *p_tmp, *p_P1, *p_x1, *p_x2, *p_x3, *p_Q, *p_h1s, *p_xsn;
    float *p_gH1, *p_gH2, *p_gH3, *p_AF, *p_Gh, *p_Gv, *p_wch, *p_wft;
    uint4 *p_b4, *p_cw1, *p_cw2;
    cudaGetSymbolAddress((void**)&p_h2,  g_h2);
    cudaGetSymbolAddress((void**)&p_F2,  g_F2);
    cudaGetSymbolAddress((void**)&p_tmp, g_tmp);
    cudaGetSymbolAddress((void**)&p_P1,  g_P1);
    cudaGetSymbolAddress((void**)&p_x1,  g_x1);
    cudaGetSymbolAddress((void**)&p_x2,  g_x2);
    cudaGetSymbolAddress((void**)&p_x3,  g_x3);
    cudaGetSymbolAddress((void**)&p_Q,   g_Q);
    cudaGetSymbolAddress((void**)&p_h1s, g_h1s);
    cudaGetSymbolAddress((void**)&p_xsn, g_xsn);
    cudaGetSymbolAddress((void**)&p_gH1, g_gH1);
    cudaGetSymbolAddress((void**)&p_gH2, g_gH2);
    cudaGetSymbolAddress((void**)&p_gH3, g_gH3);
    cudaGetSymbolAddress((void**)&p_AF,  g_AF);
    cudaGetSymbolAddress((void**)&p_Gh,  g_Gh);
    cudaGetSymbolAddress((void**)&p_Gv,  g_Gv);
    cudaGetSymbolAddress((void**)&p_wch, g_wch);
    cudaGetSymbolAddress((void**)&p_wft, g_wft);
    cudaGetSymbolAddress((void**)&p_b4,  g_bf4);
    cudaGetSymbolAddress((void**)&p_cw1, g_cw1);
    cudaGetSymbolAddress((void**)&p_cw2, g_cw2);

    // fragment pool offsets (uint4 units): count = nT * nks * 32
    const int oWt  = 0;
    const int oWa  = 51200;
    const int oWm1 = 61600, oWm2 = 72000, oWm3 = 82400;
    const int oWg1 = 92800, oWg2 = 103200;
    const int oWp1 = 113600, oWp2 = 119008, oWp3 = 124416;
    const int oWl  = 129824, oWgl = 137728;

    PJobs J;
    const float* Ws[12] = {Wt, Wa, Wm1, Wm2, Wm3, Wg1, Wg2, Wp1, Wp2, Wp3, Wl, Wgl};
    const int   Ks[12] = {1024, 200, 200, 200, 200, 200, 200, 200, 200, 200, 200, 200};
    const int   Nn[12] = {200, 200, 200, 200, 200, 200, 200, 100, 100, 100, 150, 150};
    const int   Tt[12] = {25, 25, 25, 25, 25, 25, 25, 13, 13, 13, 19, 19};
    const int   Kk[12] = {64, 13, 13, 13, 13, 13, 13, 13, 13, 13, 13, 13};
    const int   Of[12] = {oWt, oWa, oWm1, oWm2, oWm3, oWg1, oWg2, oWp1, oWp2, oWp3, oWl, oWgl};
    for (int i = 0; i < 12; i++) {
        J.W[i] = Ws[i]; J.K[i] = Ks[i]; J.N[i] = Nn[i];
        J.nT[i] = Tt[i]; J.nks[i] = Kk[i]; J.off[i] = Of[i];
    }

    const int GBMM_SMEM = 24900 * 4;
    cudaFuncSetAttribute(gbmm_kernel, cudaFuncAttributeMaxDynamicSharedMemorySize, GBMM_SMEM);

    prepall_kernel<<<dim3(200, 12), 256>>>(J, p_b4);
    prepcw_kernel<<<3, 256>>>(Wc1, p_cw1);
    prepcw_kernel<<<3, 256>>>(Wc2, p_cw2);

    const int GM = MROWS / 64;   // 480 CTAs
    dim3 gS(GM, 2);

    // CNN feature extractor (fused HMMA conv, round-8 formulation)
    convf_kernel<<<dim3(16, BATCH), 128>>>(x, p_cw1, bc1, p_cw2, bc2, p_h2);
    // F2 projection: K=1024 -> A-traffic dominated, full-N (single A pass)
    mgemm_kernel<25><<<GM, 128>>>(p_h2, p_b4+oWt, bt, p_F2, 200, 1024, 64, 200, 0, 1);

    // learned adjacency
    mgemmS_kernel<<<gS, 128>>>(p_F2, p_b4+oWa, nullptr, p_tmp, 200, 13, 200, 0);
    af_kernel<<<BATCH, 128>>>(p_tmp, p_F2, p_AF);

    // P1 = A_F@F2, Q = adj@F2 (merged)
    bmm2_kernel<<<dim3(BATCH, 2), 256>>>(p_AF, adj, p_F2, p_P1, p_Q);

    // MGCN 3-order
    mgemmS_kernel<<<gS, 128>>>(p_P1, p_b4+oWm1, nullptr, p_x1, 200, 13, 200, 1);
    bmm30_kernel<<<BATCH, 256>>>(p_AF, p_x1, p_tmp, 1);
    mgemmS_kernel<<<gS, 128>>>(p_tmp, p_b4+oWm2, nullptr, p_x2, 200, 13, 200, 1);
    bmm30_kernel<<<BATCH, 256>>>(p_AF, p_x2, p_tmp, 1);
    mgemmS_kernel<<<gS, 128>>>(p_tmp, p_b4+oWm3, nullptr, p_x3, 200, 13, 200, 1);

    // signal GCN
    mgemmS_kernel<<<gS, 128>>>(p_Q, p_b4+oWg1, nullptr, p_h1s, 200, 13, 200, 1);
    bmm30_kernel<<<BATCH, 256>>>(adj, p_h1s, p_tmp, 0);
    mgemmS_kernel<<<gS, 128>>>(p_tmp, p_b4+oWg2, nullptr, p_xsn, 200, 13, 200, 0);

    // fused gate + adj-aggregation
    gbmm_kernel<<<BATCH, 256, GBMM_SMEM>>>(adj, p_x1, p_x2, p_x3, p_xsn, wg, p_gH1, p_gH2, p_gH3);

    // G_h: 3 projections (merged, N-split)
    mgemm3_kernel<<<dim3(GM, 6), 128>>>(p_gH1, p_gH2, p_gH3, p_b4+oWp1, p_Gh);

    // G_v: LGFM (merged, N-split)
    mgemm2_kernel<<<dim3(GM, 4), 128>>>(p_Q, p_P1, p_b4+oWl, p_Gv);

    // cross SE
    se1_kernel<<<BATCH, 32>>>(p_Gv, Ws1, Ws2, p_wch);
    se2_kernel<<<BATCH / 4, 320>>>(p_Gh, Wf1, Wf2, p_wft);

    // classifier
    cls_kernel<<<BATCH / 4, 256>>>(p_Gh, p_Gv, p_wch, p_wft, Wcls, bcls, out);
}

// round 11
// speedup vs baseline: 1.3143x; 1.1527x over previous
#include <cuda_runtime.h>
#include <cuda_bf16.h>
#include <cstdint>
#include <cstdio>

#define BATCH 1024
#define NS    30
#define NT    1024
#define NFD   200
#define NCL   7
#define MROWS (BATCH*NS)      // 30720

static inline int cdiv(int a, int b) { return (a + b - 1) / b; }

// ---------------- scratch (device globals; no allocation) ----------------
__device__ float g_h2  [BATCH*NS*NT];
__device__ float g_F2  [MROWS*NFD];
__device__ float g_tmp [MROWS*NFD];
__device__ float g_P1  [MROWS*NFD];
__device__ float g_x1  [MROWS*NFD];
__device__ float g_x2  [MROWS*NFD];
__device__ float g_x3  [MROWS*NFD];
__device__ float g_Q   [MROWS*NFD];
__device__ float g_h1s [MROWS*NFD];
__device__ float g_xsn [MROWS*NFD];
__device__ float g_gH1 [MROWS*NFD];
__device__ float g_gH2 [MROWS*NFD];
__device__ float g_gH3 [MROWS*NFD];
__device__ float g_AF  [BATCH*NS*NS];
__device__ float g_Gh  [MROWS*300];
__device__ float g_Gv  [MROWS*300];
__device__ float g_wch [MROWS];
__device__ float g_wft [BATCH*300];

// packed weight fragments: uint4 = {hi_r0, hi_r1, lo_r0, lo_r1}
__device__ uint4 g_bf4[150000];
__device__ uint4 g_cw1[768];
__device__ uint4 g_cw2[768];

// ---------------- mma + split helpers ----------------
__device__ __forceinline__ void mma16816(float* c, uint32_t a0, uint32_t a1, uint32_t a2, uint32_t a3,
                                         uint32_t b0, uint32_t b1) {
    asm volatile("mma.sync.aligned.m16n8k16.row.col.f32.bf16.bf16.f32 "
        "{%0,%1,%2,%3}, {%4,%5,%6,%7}, {%8,%9}, {%0,%1,%2,%3};"
        : "+f"(c[0]), "+f"(c[1]), "+f"(c[2]), "+f"(c[3])
        : "r"(a0), "r"(a1), "r"(a2), "r"(a3), "r"(b0), "r"(b1));
}
__device__ __forceinline__ void split2(float2 v, uint32_t& hi, uint32_t& lo) {
    __nv_bfloat162 h = __floats2bfloat162_rn(v.x, v.y);
    float2 hf = __bfloat1622float2(h);
    __nv_bfloat162 l = __floats2bfloat162_rn(v.x - hf.x, v.y - hf.y);
    hi = reinterpret_cast<uint32_t&>(h);
    lo = reinterpret_cast<uint32_t&>(l);
}

// ---------------- merged weight prep: all 12 GEMM weights in one launch ----------------
struct PJobs {
    const float* W[12];
    int K[12], N[12], nT[12], nks[12], off[12];   // off in uint4 units
};
__global__ void prepall_kernel(PJobs J, uint4* __restrict__ out)
{
    const int j = blockIdx.y;
    const int idx = blockIdx.x * 256 + threadIdx.x;
    const int nks = J.nks[j];
    const int total = J.nT[j] * nks * 32;
    if (idx >= total) return;
    const int K = J.K[j], N = J.N[j];
    const float* W = J.W[j];
    int lane = idx & 31;
    int s = idx >> 5;
    int ks = s % nks;
    int t  = s / nks;
    int n = t * 8 + (lane >> 2);
    float v[4];
    #pragma unroll
    for (int reg = 0; reg < 2; reg++) {
        #pragma unroll
        for (int jj = 0; jj < 2; jj++) {
            int k = ks * 16 + (lane & 3) * 2 + reg * 8 + jj;
            v[reg * 2 + jj] = (n < N && k < K) ? W[(size_t)k * N + n] : 0.f;
        }
    }
    uint32_t h0, l0, h1, l1;
    split2(make_float2(v[0], v[1]), h0, l0);
    split2(make_float2(v[2], v[3]), h1, l1);
    out[J.off[j] + idx] = make_uint4(h0, h1, l0, l1);
}

// ---------------- conv weight prep: Wc[30,30,3] -> 768 uint4 frags, kidx = kk*32 + i ----------------
__global__ void prepcw_kernel(const float* __restrict__ W, uint4* __restrict__ out)
{
    int idx = blockIdx.x * 256 + threadIdx.x;
    if (idx >= 768) return;
    int lane = idx & 31;
    int ks = (idx >> 5) % 6;
    int t  = idx / 192;
    int n = t * 8 + (lane >> 2);
    float v[4];
    #pragma unroll
    for (int reg = 0; reg < 2; reg++) {
        #pragma unroll
        for (int jj = 0; jj < 2; jj++) {
            int kidx = ks * 16 + (lane & 3) * 2 + reg * 8 + jj;
            int kk = kidx >> 5, i = kidx & 31;
            float w = 0.f;
            if (n < 30 && i < 30) w = W[(n * 30 + i) * 3 + kk];
            v[reg * 2 + jj] = w;
        }
    }
    uint32_t h0, l0, h1, l1;
    split2(make_float2(v[0], v[1]), h0, l0);
    split2(make_float2(v[2], v[3]), h1, l1);
    out[idx] = make_uint4(h0, h1, l0, l1);
}

// ---------------- fused conv (HMMA, layer1 -> smem -> layer2), 64 t-rows/block ----------------
// kidx = kk*32 + i for BOTH layers (no integer divides); round-8 proven version
__device__ __forceinline__ float ldx(const float* __restrict__ xb, int r, int kidx)
{
    int i = kidx & 31, kk = kidx >> 5;
    int ts = r + kk - 1;
    return (i < NS && ts >= 0 && ts < NT) ? xb[i * NT + ts] : 0.f;
}
__device__ __forceinline__ void conv_l1_group(
    const float* __restrict__ xb, const uint4* __restrict__ Wf, const float* __restrict__ bc1,
    uint2 (*h1s)[16], int t0, int g, int tlo, int thi, int lane)
{
    const int gq = lane >> 2, kq = (lane & 3) * 2;
    const int r0 = t0 - 8 + g * 16 + gq, r1 = r0 + 8;
    float acc[4][4];
    #pragma unroll
    for (int t = 0; t < 4; t++) { acc[t][0] = 0.f; acc[t][1] = 0.f; acc[t][2] = 0.f; acc[t][3] = 0.f; }
    for (int ks = 0; ks < 6; ks++) {
        int kb = ks * 16 + kq;
        float v00 = ldx(xb, r0, kb),     v01 = ldx(xb, r0, kb + 1);
        float v10 = ldx(xb, r1, kb),     v11 = ldx(xb, r1, kb + 1);
        float v02 = ldx(xb, r0, kb + 8), v03 = ldx(xb, r0, kb + 9);
        float v12 = ldx(xb, r1, kb + 8), v13 = ldx(xb, r1, kb + 9);
        uint32_t ah0, al0, ah1, al1, ah2, al2, ah3, al3;
        split2(make_float2(v00, v01), ah0, al0);
        split2(make_float2(v10, v11), ah1, al1);
        split2(make_float2(v02, v03), ah2, al2);
        split2(make_float2(v12, v13), ah3, al3);
        const uint4* bp = Wf + ks * 32 + lane;
        #pragma unroll
        for (int t = 0; t < 4; t++) {
            if (t < tlo || t >= thi) continue;
            uint4 w = bp[t * 192];
            mma16816(acc[t], ah0, ah1, ah2, ah3, w.x, w.y);
            mma16816(acc[t], ah0, ah1, ah2, ah3, w.z, w.w);
            mma16816(acc[t], al0, al1, al2, al3, w.x, w.y);
        }
    }
    const int sr0 = g * 16 + gq, sr1 = sr0 + 8;
    #pragma unroll
    for (int t = 0; t < 4; t++) {
        if (t < tlo || t >= thi) continue;
        int n0 = t * 8 + kq;
        float bb0 = (n0 < 30) ? bc1[n0] : 0.f;
        float bb1 = (n0 + 1 < 30) ? bc1[n0 + 1] : 0.f;
        float v0 = fmaxf(acc[t][0] + bb0, 0.f), v1 = fmaxf(acc[t][1] + bb1, 0.f);
        float v2 = fmaxf(acc[t][2] + bb0, 0.f), v3 = fmaxf(acc[t][3] + bb1, 0.f);
        uint32_t h, l;
        split2(make_float2(v0, v1), h, l);
        h1s[sr0][t * 4 + (kq >> 1)] = make_uint2(h, l);
        split2(make_float2(v2, v3), h, l);
        h1s[sr1][t * 4 + (kq >> 1)] = make_uint2(h, l);
    }
}

__global__ __launch_bounds__(128) void convf_kernel(
    const float* __restrict__ x, const uint4* __restrict__ Wf1, const float* __restrict__ bc1,
    const uint4* __restrict__ Wf2, const float* __restrict__ bc2, float* __restrict__ out)
{
    __shared__ uint2 h1s[80][16];
    const int b = blockIdx.y;
    const int t0 = blockIdx.x * 64;
    const int lane = threadIdx.x & 31, warp = threadIdx.x >> 5;
    const float* xb = x + (size_t)b * NS * NT;

    conv_l1_group(xb, Wf1, bc1, h1s, t0, warp, 0, 4, lane);
    if (warp < 2) conv_l1_group(xb, Wf1, bc1, h1s, t0, 4, warp * 2, warp * 2 + 2, lane);
    __syncthreads();

    const int gq = lane >> 2, kq = (lane & 3) * 2;
    const int r0 = t0 + warp * 16 + gq, r1 = r0 + 8;
    float acc[4][4];
    #pragma unroll
    for (int t = 0; t < 4; t++) { acc[t][0] = 0.f; acc[t][1] = 0.f; acc[t][2] = 0.f; acc[t][3] = 0.f; }
    for (int ks = 0; ks < 6; ks++) {
        int kb = ks * 16 + kq;
        int kk = kb >> 5;
        int i  = kb & 31;
        int ts0 = r0 + kk - 1, ts1 = r1 + kk - 1;
        int s0 = ts0 - (t0 - 8), s1 = ts1 - (t0 - 8);
        uint2 z = make_uint2(0u, 0u);
        uint2 p00 = (ts0 >= 0 && ts0 < NT) ? h1s[s0][i >> 1]       : z;
        uint2 p01 = (ts0 >= 0 && ts0 < NT) ? h1s[s0][(i + 8) >> 1] : z;
        uint2 p10 = (ts1 >= 0 && ts1 < NT) ? h1s[s1][i >> 1]       : z;
        uint2 p11 = (ts1 >= 0 && ts1 < NT) ? h1s[s1][(i + 8) >> 1] : z;
        const uint4* bp = Wf2 + ks * 32 + lane;
        #pragma unroll
        for (int t = 0; t < 4; t++) {
            uint4 w = bp[t * 192];
            mma16816(acc[t], p00.x, p10.x, p01.x, p11.x, w.x, w.y);
            mma16816(acc[t], p00.x, p10.x, p01.x, p11.x, w.z, w.w);
            mma16816(acc[t], p00.y, p10.y, p01.y, p11.y, w.x, w.y);
        }
    }
    #pragma unroll
    for (int t = 0; t < 4; t++) {
        int n0 = t * 8 + kq;
        if (n0 < 30) {
            float bb = bc2[n0];
            out[((size_t)b * NS + n0) * NT + r0] = fmaxf(acc[t][0] + bb, 0.f);
            out[((size_t)b * NS + n0) * NT + r1] = fmaxf(acc[t][2] + bb, 0.f);
        }
        if (n0 + 1 < 30) {
            float bb = bc2[n0 + 1];
            out[((size_t)b * NS + n0 + 1) * NT + r0] = fmaxf(acc[t][1] + bb, 0.f);
            out[((size_t)b * NS + n0 + 1) * NT + r1] = fmaxf(acc[t][3] + bb, 0.f);
        }
    }
}

// ---------------- HMMA split-bf16 GEMM body ----------------
template<int NTl>
__device__ __forceinline__ void mgemm_body(
    const float* __restrict__ A, const uint4* __restrict__ B4,
    const float* __restrict__ bias, float* __restrict__ C,
    int N, int K, int nks, int ldc, int coloff, int relu)
{
    const int lane = threadIdx.x & 31;
    const int warp = threadIdx.x >> 5;
    const int gq = lane >> 2;
    const int q  = lane & 3;
    const int r0 = blockIdx.x * 64 + warp * 16 + gq;
    const int r1 = r0 + 8;
    const int kq = q * 2;

    float acc[NTl][4];
    #pragma unroll
    for (int t = 0; t < NTl; t++) {
        acc[t][0] = 0.f; acc[t][1] = 0.f; acc[t][2] = 0.f; acc[t][3] = 0.f;
    }

    const float* a0p = A + (size_t)r0 * K;
    const float* a1p = A + (size_t)r1 * K;

    for (int ks = 0; ks < nks; ks++) {
        const int kb = ks * 16 + kq;
        float2 x00 = (kb     < K) ? *reinterpret_cast<const float2*>(a0p + kb)     : make_float2(0.f, 0.f);
        float2 x01 = (kb + 8 < K) ? *reinterpret_cast<const float2*>(a0p + kb + 8) : make_float2(0.f, 0.f);
        float2 x10 = (kb     < K) ? *reinterpret_cast<const float2*>(a1p + kb)     : make_float2(0.f, 0.f);
        float2 x11 = (kb + 8 < K) ? *reinterpret_cast<const float2*>(a1p + kb + 8) : make_float2(0.f, 0.f);
        uint32_t ah0, al0, ah1, al1, ah2, al2, ah3, al3;
        split2(x00, ah0, al0);
        split2(x10, ah1, al1);
        split2(x01, ah2, al2);
        split2(x11, ah3, al3);
        const uint4* bp = B4 + ks * 32 + lane;
        const int stride = nks * 32;
        #pragma unroll
        for (int t = 0; t < NTl; t++) {
            uint4 w = bp[(size_t)t * stride];
            mma16816(acc[t], ah0, ah1, ah2, ah3, w.x, w.y);
            mma16816(acc[t], ah0, ah1, ah2, ah3, w.z, w.w);
            mma16816(acc[t], al0, al1, al2, al3, w.x, w.y);
        }
    }

    #pragma unroll
    for (int t = 0; t < NTl; t++) {
        int n0 = t * 8 + kq;
        if (n0 < N) {
            float b0v = bias ? bias[n0] : 0.f;
            float b1v = bias ? bias[n0 + 1] : 0.f;
            float v0 = acc[t][0] + b0v, v1 = acc[t][1] + b1v;
            float v2 = acc[t][2] + b0v, v3 = acc[t][3] + b1v;
            if (relu) {
                v0 = fmaxf(v0, 0.f); v1 = fmaxf(v1, 0.f);
                v2 = fmaxf(v2, 0.f); v3 = fmaxf(v3, 0.f);
            }
            *reinterpret_cast<float2*>(&C[(size_t)r0 * ldc + coloff + n0]) = make_float2(v0, v1);
            *reinterpret_cast<float2*>(&C[(size_t)r1 * ldc + coloff + n0]) = make_float2(v2, v3);
        }
    }
}

// N-split GEMM (200 cols -> 104 + 96), grid (480, 2)
__global__ __launch_bounds__(128, 4) void mgemmS_kernel(
    const float* __restrict__ A, const uint4* __restrict__ B4,
    const float* __restrict__ bias, float* __restrict__ C,
    int K, int nks, int ldc, int relu)
{
    if (blockIdx.y == 0)
        mgemm_body<13>(A, B4, bias, C, 104, K, nks, ldc, 0, relu);
    else
        mgemm_body<12>(A, B4 + 13 * nks * 32, bias ? bias + 104 : nullptr, C, 96, K, nks, ldc, 104, relu);
}

// merged 3x (N=100, K=200), split 56+44, grid (480, 6)
__global__ __launch_bounds__(128, 4) void mgemm3_kernel(
    const float* __restrict__ A0, const float* __restrict__ A1, const float* __restrict__ A2,
    const uint4* __restrict__ B4, float* __restrict__ C)
{
    const int j = blockIdx.y >> 1, h = blockIdx.y & 1;
    const float* A = (j == 0) ? A0 : (j == 1) ? A1 : A2;
    const uint4* B = B4 + j * 5408;
    if (h == 0) mgemm_body<7>(A, B, nullptr, C, 56, 200, 13, 300, j * 100, 0);
    else        mgemm_body<6>(A, B + 7 * 13 * 32, nullptr, C, 44, 200, 13, 300, j * 100 + 56, 0);
}

// merged 2x (N=150, K=200, relu), split 80+70, grid (480, 4)
__global__ __launch_bounds__(128, 4) void mgemm2_kernel(
    const float* __restrict__ A0, const float* __restrict__ A1,
    const uint4* __restrict__ B4, float* __restrict__ C)
{
    const int j = blockIdx.y >> 1, h = blockIdx.y & 1;
    const float* A = j ? A1 : A0;
    const uint4* B = B4 + j * 7904;
    if (h == 0) mgemm_body<10>(A, B, nullptr, C, 80, 200, 13, 300, j * 150, 1);
    else        mgemm_body<9>(A, B + 10 * 13 * 32, nullptr, C, 70, 200, 13, 300, j * 150 + 80, 1);
}

// ---------------- batched small matmul body: Out[b] = A @ X[b] ----------------
__device__ __forceinline__ void bmm30_body(
    const float* __restrict__ Am, const float* __restrict__ X, float* __restrict__ Out,
    int batched, int b, int tid)
{
    __shared__ float As[NS * NS];
    __shared__ float Xs[NS * NFD];
    const float* A = batched ? (Am + (size_t)b * NS * NS) : Am;
    for (int i = tid; i < NS * NS; i += 256) As[i] = A[i];
    for (int i = tid; i < NS * NFD; i += 256) Xs[i] = X[(size_t)b * NS * NFD + i];
    __syncthreads();
    if (tid < 250) {
        int si = tid / 25, fi = tid - (tid / 25) * 25;
        int s0 = si * 3, f0 = fi * 8;
        float acc[3][8];
        #pragma unroll
        for (int r = 0; r < 3; r++)
            #pragma unroll
            for (int q = 0; q < 8; q++) acc[r][q] = 0.f;
        for (int j = 0; j < NS; j++) {
            float a0 = As[(s0 + 0) * NS + j];
            float a1 = As[(s0 + 1) * NS + j];
            float a2 = As[(s0 + 2) * NS + j];
            float4 xA = *reinterpret_cast<const float4*>(&Xs[j * NFD + f0]);
            float4 xB = *reinterpret_cast<const float4*>(&Xs[j * NFD + f0 + 4]);
            float xv[8] = {xA.x, xA.y, xA.z, xA.w, xB.x, xB.y, xB.z, xB.w};
            #pragma unroll
            for (int q = 0; q < 8; q++) {
                acc[0][q] += a0 * xv[q];
                acc[1][q] += a1 * xv[q];
                acc[2][q] += a2 * xv[q];
            }
        }
        #pragma unroll
        for (int r = 0; r < 3; r++)
            #pragma unroll
            for (int q = 0; q < 8; q++)
                Out[(size_t)b * NS * NFD + (s0 + r) * NFD + f0 + q] = acc[r][q];
    }
}

__global__ __launch_bounds__(256) void bmm30_kernel(
    const float* __restrict__ Am, const float* __restrict__ X, float* __restrict__ Out, int batched)
{
    bmm30_body(Am, X, Out, batched, blockIdx.x, threadIdx.x);
}

// merged P1 = A_F@F2 (y=0) and Q = adj@F2 (y=1)
__global__ __launch_bounds__(256) void bmm2_kernel(
    const float* __restrict__ AF, const float* __restrict__ adj,
    const float* __restrict__ F2, float* __restrict__ P1, float* __restrict__ Q)
{
    if (blockIdx.y == 0) bmm30_body(AF, F2, P1, 1, blockIdx.x, threadIdx.x);
    else                 bmm30_body(adj, F2, Q, 0, blockIdx.x, threadIdx.x);
}

// ---------------- fused gate + 3x bmm30(adj, g_k*H_k), xsn read from gmem ----------------
__global__ __launch_bounds__(256) void gbmm_kernel(
    const float* __restrict__ adj, const float* __restrict__ x1, const float* __restrict__ x2,
    const float* __restrict__ x3, const float* __restrict__ xsn, const float* __restrict__ wg,
    float* __restrict__ o1, float* __restrict__ o2, float* __restrict__ o3)
{
    extern __shared__ float sm[];
    float* As = sm;                                   // 900
    float* X0 = sm + 900;                             // 6000 each
    float* X1 = sm + 6900;
    float* X2 = sm + 12900;
    const int b = blockIdx.x, tid = threadIdx.x;
    const size_t base = (size_t)b * 6000;
    for (int i = tid; i < 900; i += 256) As[i] = adj[i];
    for (int i = tid; i < 6000; i += 256) {
        X0[i] = x1[base + i];
        X1[i] = x2[base + i];
        X2[i] = x3[base + i];
    }
    __syncthreads();

    {
        const int warp = tid >> 5, lane = tid & 31;
        for (int rr = 0; rr < 4; rr++) {
            int r = warp * 4 + rr;
            if (r >= NS) break;
            float H0[7], H1[7], H2[7];
            float s0 = 0.f, s1 = 0.f, s2 = 0.f;
            #pragma unroll
            for (int q = 0; q < 7; q++) {
                int f = q * 32 + lane;
                float h0 = 0.f, h1 = 0.f, h2 = 0.f;
                if (f < NFD) {
                    float sv = xsn[base + r * NFD + f];
                    h0 = (X0[r * NFD + f] + sv) * 0.5f;
                    h1 = (X1[r * NFD + f] + sv) * 0.5f;
                    h2 = (X2[r * NFD + f] + sv) * 0.5f;
                    s0 += h0 * wg[f * 3 + 0];
                    s1 += h1 * wg[f * 3 + 1];
                    s2 += h2 * wg[f * 3 + 2];
                }
                H0[q] = h0; H1[q] = h1; H2[q] = h2;
            }
            #pragma unroll
            for (int o = 16; o; o >>= 1) {
                s0 += __shfl_xor_sync(0xffffffffu, s0, o);
                s1 += __shfl_xor_sync(0xffffffffu, s1, o);
                s2 += __shfl_xor_sync(0xffffffffu, s2, o);
            }
            float mx = fmaxf(s0, fmaxf(s1, s2));
            float e0 = expf(s0 - mx), e1 = expf(s1 - mx), e2 = expf(s2 - mx);
            float inv = 1.f / (e0 + e1 + e2);
            e0 *= inv; e1 *= inv; e2 *= inv;
            #pragma unroll
            for (int q = 0; q < 7; q++) {
                int f = q * 32 + lane;
                if (f < NFD) {
                    X0[r * NFD + f] = e0 * H0[q];
                    X1[r * NFD + f] = e1 * H1[q];
                    X2[r * NFD + f] = e2 * H2[q];
                }
            }
        }
    }
    __syncthreads();

    if (tid < 250) {
        int si = tid / 25, fi = tid - (tid / 25) * 25;
        int s0 = si * 3, f0 = fi * 8;
        float* Xk[3] = {X0, X1, X2};
        float* Ok[3] = {o1, o2, o3};
        #pragma unroll
        for (int k = 0; k < 3; k++) {
            const float* X = Xk[k];
            float acc[3][8];
            #pragma unroll
            for (int r = 0; r < 3; r++)
                #pragma unroll
                for (int q = 0; q < 8; q++) acc[r][q] = 0.f;
            for (int j = 0; j < NS; j++) {
                float a0 = As[(s0 + 0) * NS + j];
                float a1 = As[(s0 + 1) * NS + j];
                float a2 = As[(s0 + 2) * NS + j];
                float4 xA = *reinterpret_cast<const float4*>(&X[j * NFD + f0]);
                float4 xB = *reinterpret_cast<const float4*>(&X[j * NFD + f0 + 4]);
                float xv[8] = {xA.x, xA.y, xA.z, xA.w, xB.x, xB.y, xB.z, xB.w};
                #pragma unroll
                for (int q = 0; q < 8; q++) {
                    acc[0][q] += a0 * xv[q];
                    acc[1][q] += a1 * xv[q];
                    acc[2][q] += a2 * xv[q];
                }
            }
            #pragma unroll
            for (int r = 0; r < 3; r++)
                #pragma unroll
                for (int q = 0; q < 8; q++)
                    Ok[k][base + (s0 + r) * NFD + f0 + q] = acc[r][q];
        }
    }
}

// ---------------- A_F = softmax(relu(tmp @ F2^T)) per batch ----------------
__global__ __launch_bounds__(128) void af_kernel(
    const float* __restrict__ Tm, const float* __restrict__ F2, float* __restrict__ AF)
{
    __shared__ float Ts[NS * NFD];
    __shared__ float Fs[NS * NFD];
    const int b = blockIdx.x;
    const int tid = threadIdx.x;
    for (int i = tid; i < NS * NFD; i += 128) {
        Ts[i] = Tm[(size_t)b * NS * NFD + i];
        Fs[i] = F2[(size_t)b * NS * NFD + i];
    }
    __syncthreads();
    float acc[3][3];
    int ii = 0, jj = 0;
    if (tid < 100) {
        ii = (tid / 10) * 3; jj = (tid % 10) * 3;
        #pragma unroll
        for (int r = 0; r < 3; r++)
            #pragma unroll
            for (int c = 0; c < 3; c++) acc[r][c] = 0.f;
        for (int g = 0; g < NFD; g++) {
            float t0 = Ts[(ii + 0) * NFD + g], t1 = Ts[(ii + 1) * NFD + g], t2 = Ts[(ii + 2) * NFD + g];
            float f0 = Fs[(jj + 0) * NFD + g], f1 = Fs[(jj + 1) * NFD + g], f2 = Fs[(jj + 2) * NFD + g];
            acc[0][0] += t0 * f0; acc[0][1] += t0 * f1; acc[0][2] += t0 * f2;
            acc[1][0] += t1 * f0; acc[1][1] += t1 * f1; acc[1][2] += t1 * f2;
            acc[2][0] += t2 * f0; acc[2][1] += t2 * f1; acc[2][2] += t2 * f2;
        }
    }
    __syncthreads();
    float (*Ms)[31] = reinterpret_cast<float(*)[31]>(Ts);
    if (tid < 100) {
        #pragma unroll
        for (int r = 0; r < 3; r++)
            #pragma unroll
            for (int c = 0; c < 3; c++) Ms[ii + r][jj + c] = fmaxf(acc[r][c], 0.f);
    }
    __syncthreads();
    if (tid < NS) {
        float mx = -1e30f;
        for (int j = 0; j < NS; j++) mx = fmaxf(mx, Ms[tid][j]);
        float s = 0.f;
        for (int j = 0; j < NS; j++) s += expf(Ms[tid][j] - mx);
        float inv = 1.f / s;
        for (int j = 0; j < NS; j++)
            AF[(size_t)b * NS * NS + tid * NS + j] = expf(Ms[tid][j] - mx) * inv;
    }
}

// ---------------- SE blocks ----------------
// 4 batches per block, one warp per batch
__global__ __launch_bounds__(128) void se1_kernel(
    const float* __restrict__ Gv, const float* __restrict__ Ws1,
    const float* __restrict__ Ws2, float* __restrict__ wch)
{
    const int warp = threadIdx.x >> 5, lane = threadIdx.x & 31;
    const int b = blockIdx.x * 4 + warp;
    __shared__ float mvs[4][NS];
    __shared__ float avs[4][15];
    float* mv = mvs[warp];
    float* av = avs[warp];
    for (int s = 0; s < NS; s++) {
        float p = 0.f;
        for (int j = lane; j < 300; j += 32) p += Gv[(size_t)b * 9000 + s * 300 + j];
        #pragma unroll
        for (int o = 16; o; o >>= 1) p += __shfl_xor_sync(0xffffffffu, p, o);
        if (lane == 0) mv[s] = p * (1.f / 300.f);
    }
    __syncwarp();
    if (lane < 15) {
        float a = 0.f;
        for (int s = 0; s < NS; s++) a += mv[s] * Ws1[s * 15 + lane];
        av[lane] = fmaxf(a, 0.f);
    }
    __syncwarp();
    if (lane < NS) {
        float a = 0.f;
        for (int h = 0; h < 15; h++) a += av[h] * Ws2[h * NS + lane];
        wch[b * NS + lane] = 1.f / (1.f + expf(-a));
    }
}

__global__ __launch_bounds__(320) void se2_kernel(const float* __restrict__ Gh,
                                                  const float* __restrict__ Wf1,
                                                  const float* __restrict__ Wf2,
                                                  float* __restrict__ wft)
{
    __shared__ float m[4][300];
    __shared__ float t1[4][152];
    const int b0 = blockIdx.x * 4, tid = threadIdx.x;
    if (tid < 300) {
        #pragma unroll
        for (int bb = 0; bb < 4; bb++) {
            float a = 0.f;
            for (int s = 0; s < NS; s++) a += Gh[(size_t)(b0 + bb) * 9000 + s * 300 + tid];
            m[bb][tid] = a * (1.f / 30.f);
        }
    }
    __syncthreads();
    if (tid < 150) {
        float a[4] = {0.f, 0.f, 0.f, 0.f};
        for (int j = 0; j < 300; j++) {
            float w = Wf1[j * 150 + tid];
            #pragma unroll
            for (int bb = 0; bb < 4; bb++) a[bb] += m[bb][j] * w;
        }
        #pragma unroll
        for (int bb = 0; bb < 4; bb++) t1[bb][tid] = fmaxf(a[bb], 0.f);
    }
    __syncthreads();
    if (tid < 300) {
        float a[4] = {0.f, 0.f, 0.f, 0.f};
        for (int h = 0; h < 150; h++) {
            float w = Wf2[h * 300 + tid];
            #pragma unroll
            for (int bb = 0; bb < 4; bb++) a[bb] += t1[bb][h] * w;
        }
        #pragma unroll
        for (int bb = 0; bb < 4; bb++)
            wft[(size_t)(b0 + bb) * 300 + tid] = 1.f / (1.f + expf(-a[bb]));
    }
}

// ---------------- classifier + log_softmax (4 batches per block, direct Wcls) ----------------
__global__ __launch_bounds__(256) void cls_kernel(
    const float* __restrict__ Gh, const float* __restrict__ Gv,
    const float* __restrict__ wch, const float* __restrict__ wft,
    const float* __restrict__ Wcls, const float* __restrict__ bcls, float* __restrict__ out)
{
    const int b0 = blockIdx.x * 4, tid = threadIdx.x;
    const int lane = tid & 31, warp = tid >> 5;
    float acc[4][NCL];
    #pragma unroll
    for (int bb = 0; bb < 4; bb++)
        #pragma unroll
        for (int k = 0; k < NCL; k++) acc[bb][k] = 0.f;

    for (int idx = tid; idx < 18000; idx += 256) {
        int s = idx / 600;
        int c = idx - s * 600;
        float w[NCL];
        #pragma unroll
        for (int k = 0; k < NCL; k++) w[k] = Wcls[(size_t)idx * NCL + k];
        #pragma unroll
        for (int bb = 0; bb < 4; bb++) {
            int b = b0 + bb;
            float val;
            if (c < 300) val = Gh[(size_t)b * 9000 + s * 300 + c] * wch[b * NS + s];
            else {
                int cc = c - 300;
                val = Gv[(size_t)b * 9000 + s * 300 + cc] * wft[(size_t)b * 300 + cc];
            }
            #pragma unroll
            for (int k = 0; k < NCL; k++) acc[bb][k] += val * w[k];
        }
    }
    #pragma unroll
    for (int bb = 0; bb < 4; bb++)
        #pragma unroll
        for (int k = 0; k < NCL; k++)
            #pragma unroll
            for (int o = 16; o; o >>= 1)
                acc[bb][k] += __shfl_xor_sync(0xffffffffu, acc[bb][k], o);
    __shared__ float red[8][4][NCL];
    __shared__ float zs[4][NCL];
    if (lane == 0) {
        #pragma unroll
        for (int bb = 0; bb < 4; bb++)
            #pragma unroll
            for (int k = 0; k < NCL; k++) red[warp][bb][k] = acc[bb][k];
    }
    __syncthreads();
    if (tid < 28) {
        int bb = tid / 7, k = tid - bb * 7;
        float z = bcls[k];
        #pragma unroll
        for (int w2 = 0; w2 < 8; w2++) z += red[w2][bb][k];
        zs[bb][k] = z;
    }
    __syncthreads();
    if (tid < 4) {
        float mx = -1e30f;
        #pragma unroll
        for (int k = 0; k < NCL; k++) mx = fmaxf(mx, zs[tid][k]);
        float s = 0.f;
        #pragma unroll
        for (int k = 0; k < NCL; k++) s += expf(zs[tid][k] - mx);
        float ls = logf(s);
        #pragma unroll
        for (int k = 0; k < NCL; k++) out[(b0 + tid) * NCL + k] = zs[tid][k] - mx - ls;
    }
}

// ---------------- launch ----------------
extern "C" void kernel_launch(void* const* d_in, const int* in_sizes, int n_in,
                              void* d_out, int out_size)
{
    const float* x    = (const float*)d_in[0];
    const float* adj  = (const float*)d_in[1];
    const float* Wc1  = (const float*)d_in[2];
    const float* bc1  = (const float*)d_in[3];
    const float* Wc2  = (const float*)d_in[4];
    const float* bc2  = (const float*)d_in[5];
    const float* Wt   = (const float*)d_in[6];
    const float* bt   = (const float*)d_in[7];
    const float* Wa   = (const float*)d_in[8];
    const float* Wm1  = (const float*)d_in[9];
    const float* Wm2  = (const float*)d_in[10];
    const float* Wm3  = (const float*)d_in[11];
    const float* Wg1  = (const float*)d_in[12];
    const float* Wg2  = (const float*)d_in[13];
    const float* wg   = (const float*)d_in[14];
    const float* Wp1  = (const float*)d_in[15];
    const float* Wp2  = (const float*)d_in[16];
    const float* Wp3  = (const float*)d_in[17];
    const float* Wl   = (const float*)d_in[18];
    const float* Wgl  = (const float*)d_in[19];
    const float* Ws1  = (const float*)d_in[20];
    const float* Ws2  = (const float*)d_in[21];
    const float* Wf1  = (const float*)d_in[22];
    const float* Wf2  = (const float*)d_in[23];
    const float* Wcls = (const float*)d_in[24];
    const float* bcls = (const float*)d_in[25];
    float* out = (float*)d_out;

    float *p_h2, *p_F2, *p_tmp, *p_P1, *p_x1, *p_x2, *p_x3, *p_Q, *p_h1s, *p_xsn;
    float *p_gH1, *p_gH2, *p_gH3, *p_AF, *p_Gh, *p_Gv, *p_wch, *p_wft;
    uint4 *p_b4, *p_cw1, *p_cw2;
    cudaGetSymbolAddress((void**)&p_h2,  g_h2);
    cudaGetSymbolAddress((void**)&p_F2,  g_F2);
    cudaGetSymbolAddress((void**)&p_tmp, g_tmp);
    cudaGetSymbolAddress((void**)&p_P1,  g_P1);
    cudaGetSymbolAddress((void**)&p_x1,  g_x1);
    cudaGetSymbolAddress((void**)&p_x2,  g_x2);
    cudaGetSymbolAddress((void**)&p_x3,  g_x3);
    cudaGetSymbolAddress((void**)&p_Q,   g_Q);
    cudaGetSymbolAddress((void**)&p_h1s, g_h1s);
    cudaGetSymbolAddress((void**)&p_xsn, g_xsn);
    cudaGetSymbolAddress((void**)&p_gH1, g_gH1);
    cudaGetSymbolAddress((void**)&p_gH2, g_gH2);
    cudaGetSymbolAddress((void**)&p_gH3, g_gH3);
    cudaGetSymbolAddress((void**)&p_AF,  g_AF);
    cudaGetSymbolAddress((void**)&p_Gh,  g_Gh);
    cudaGetSymbolAddress((void**)&p_Gv,  g_Gv);
    cudaGetSymbolAddress((void**)&p_wch, g_wch);
    cudaGetSymbolAddress((void**)&p_wft, g_wft);
    cudaGetSymbolAddress((void**)&p_b4,  g_bf4);
    cudaGetSymbolAddress((void**)&p_cw1, g_cw1);
    cudaGetSymbolAddress((void**)&p_cw2, g_cw2);

    // fragment pool offsets (uint4 units): count = nT * nks * 32
    const int oWt  = 0;
    const int oWa  = 51200;
    const int oWm1 = 61600, oWm2 = 72000, oWm3 = 82400;
    const int oWg1 = 92800, oWg2 = 103200;
    const int oWp1 = 113600, oWp2 = 119008, oWp3 = 124416;
    const int oWl  = 129824, oWgl = 137728;

    PJobs J;
    const float* Ws[12] = {Wt, Wa, Wm1, Wm2, Wm3, Wg1, Wg2, Wp1, Wp2, Wp3, Wl, Wgl};
    const int   Ks[12] = {1024, 200, 200, 200, 200, 200, 200, 200, 200, 200, 200, 200};
    const int   Nn[12] = {200, 200, 200, 200, 200, 200, 200, 100, 100, 100, 150, 150};
    const int   Tt[12] = {25, 25, 25, 25, 25, 25, 25, 13, 13, 13, 19, 19};
    const int   Kk[12] = {64, 13, 13, 13, 13, 13, 13, 13, 13, 13, 13, 13};
    const int   Of[12] = {oWt, oWa, oWm1, oWm2, oWm3, oWg1, oWg2, oWp1, oWp2, oWp3, oWl, oWgl};
    for (int i = 0; i < 12; i++) {
        J.W[i] = Ws[i]; J.K[i] = Ks[i]; J.N[i] = Nn[i];
        J.nT[i] = Tt[i]; J.nks[i] = Kk[i]; J.off[i] = Of[i];
    }

    const int GBMM_SMEM = 18900 * 4;   // 75.6 KB -> 2 CTAs/SM
    cudaFuncSetAttribute(gbmm_kernel, cudaFuncAttributeMaxDynamicSharedMemorySize, GBMM_SMEM);

    prepall_kernel<<<dim3(200, 12), 256>>>(J, p_b4);
    prepcw_kernel<<<3, 256>>>(Wc1, p_cw1);
    prepcw_kernel<<<3, 256>>>(Wc2, p_cw2);

    const int GM = MROWS / 64;   // 480 CTAs
    dim3 gS(GM, 2);

    // CNN feature extractor (fused HMMA conv, round-8 formulation)
    convf_kernel<<<dim3(16, BATCH), 128>>>(x, p_cw1, bc1, p_cw2, bc2, p_h2);
    mgemmS_kernel<<<gS, 128>>>(p_h2, p_b4+oWt, bt, p_F2, 1024, 64, 200, 1);

    // learned adjacency
    mgemmS_kernel<<<gS, 128>>>(p_F2, p_b4+oWa, nullptr, p_tmp, 200, 13, 200, 0);
    af_kernel<<<BATCH, 128>>>(p_tmp, p_F2, p_AF);

    // P1 = A_F@F2, Q = adj@F2 (merged)
    bmm2_kernel<<<dim3(BATCH, 2), 256>>>(p_AF, adj, p_F2, p_P1, p_Q);

    // MGCN 3-order
    mgemmS_kernel<<<gS, 128>>>(p_P1, p_b4+oWm1, nullptr, p_x1, 200, 13, 200, 1);
    bmm30_kernel<<<BATCH, 256>>>(p_AF, p_x1, p_tmp, 1);
    mgemmS_kernel<<<gS, 128>>>(p_tmp, p_b4+oWm2, nullptr, p_x2, 200, 13, 200, 1);
    bmm30_kernel<<<BATCH, 256>>>(p_AF, p_x2, p_tmp, 1);
    mgemmS_kernel<<<gS, 128>>>(p_tmp, p_b4+oWm3, nullptr, p_x3, 200, 13, 200, 1);

    // signal GCN
    mgemmS_kernel<<<gS, 128>>>(p_Q, p_b4+oWg1, nullptr, p_h1s, 200, 13, 200, 1);
    bmm30_kernel<<<BATCH, 256>>>(adj, p_h1s, p_tmp, 0);
    mgemmS_kernel<<<gS, 128>>>(p_tmp, p_b4+oWg2, nullptr, p_xsn, 200, 13, 200, 0);

    // fused gate + adj-aggregation
    gbmm_kernel<<<BATCH, 256, GBMM_SMEM>>>(adj, p_x1, p_x2, p_x3, p_xsn, wg, p_gH1, p_gH2, p_gH3);

    // G_h: 3 projections (merged, N-split)
    mgemm3_kernel<<<dim3(GM, 6), 128>>>(p_gH1, p_gH2, p_gH3, p_b4+oWp1, p_Gh);

    // G_v: LGFM (merged, N-split)
    mgemm2_kernel<<<dim3(GM, 4), 128>>>(p_Q, p_P1, p_b4+oWl, p_Gv);

    // cross SE
    se1_kernel<<<BATCH / 4, 128>>>(p_Gv, Ws1, Ws2, p_wch);
    se2_kernel<<<BATCH / 4, 320>>>(p_Gh, Wf1, Wf2, p_wft);

    // classifier
    cls_kernel<<<BATCH / 4, 256>>>(p_Gh, p_Gv, p_wch, p_wft, Wcls, bcls, out);
}

// round 12
// speedup vs baseline: 1.3622x; 1.0365x over previous
#include <cuda_runtime.h>
#include <cuda_bf16.h>
#include <cstdint>
#include <cstdio>

#define BATCH 1024
#define NS    30
#define NT    1024
#define NFD   200
#define NCL   7
#define MROWS (BATCH*NS)      // 30720

static inline int cdiv(int a, int b) { return (a + b - 1) / b; }

// ---------------- scratch (device globals; no allocation) ----------------
__device__ float g_h2  [BATCH*NS*NT];
__device__ float g_F2  [MROWS*NFD];
__device__ float g_tmp [MROWS*NFD];
__device__ float g_tmp2[MROWS*NFD];
__device__ float g_P1  [MROWS*NFD];
__device__ float g_x1  [MROWS*NFD];
__device__ float g_x2  [MROWS*NFD];
__device__ float g_x3  [MROWS*NFD];
__device__ float g_Q   [MROWS*NFD];
__device__ float g_h1s [MROWS*NFD];
__device__ float g_xsn [MROWS*NFD];
__device__ float g_gH1 [MROWS*NFD];
__device__ float g_gH2 [MROWS*NFD];
__device__ float g_gH3 [MROWS*NFD];
__device__ float g_AF  [BATCH*NS*NS];
__device__ float g_Gh  [MROWS*300];
__device__ float g_Gv  [MROWS*300];
__device__ float g_wch [MROWS];
__device__ float g_wft [BATCH*300];

// packed weight fragments: uint4 = {hi_r0, hi_r1, lo_r0, lo_r1}
__device__ uint4 g_bf4[150000];
__device__ uint4 g_cw1[768];
__device__ uint4 g_cw2[768];

// ---------------- mma + split helpers ----------------
__device__ __forceinline__ void mma16816(float* c, uint32_t a0, uint32_t a1, uint32_t a2, uint32_t a3,
                                         uint32_t b0, uint32_t b1) {
    asm volatile("mma.sync.aligned.m16n8k16.row.col.f32.bf16.bf16.f32 "
        "{%0,%1,%2,%3}, {%4,%5,%6,%7}, {%8,%9}, {%0,%1,%2,%3};"
        : "+f"(c[0]), "+f"(c[1]), "+f"(c[2]), "+f"(c[3])
        : "r"(a0), "r"(a1), "r"(a2), "r"(a3), "r"(b0), "r"(b1));
}
__device__ __forceinline__ void split2(float2 v, uint32_t& hi, uint32_t& lo) {
    __nv_bfloat162 h = __floats2bfloat162_rn(v.x, v.y);
    float2 hf = __bfloat1622float2(h);
    __nv_bfloat162 l = __floats2bfloat162_rn(v.x - hf.x, v.y - hf.y);
    hi = reinterpret_cast<uint32_t&>(h);
    lo = reinterpret_cast<uint32_t&>(l);
}

// ---------------- merged weight prep ----------------
struct PJobs {
    const float* W[12];
    int K[12], N[12], nT[12], nks[12], off[12];
};
__global__ void prepall_kernel(PJobs J, uint4* __restrict__ out)
{
    const int j = blockIdx.y;
    const int idx = blockIdx.x * 256 + threadIdx.x;
    const int nks = J.nks[j];
    const int total = J.nT[j] * nks * 32;
    if (idx >= total) return;
    const int K = J.K[j], N = J.N[j];
    const float* W = J.W[j];
    int lane = idx & 31;
    int s = idx >> 5;
    int ks = s % nks;
    int t  = s / nks;
    int n = t * 8 + (lane >> 2);
    float v[4];
    #pragma unroll
    for (int reg = 0; reg < 2; reg++) {
        #pragma unroll
        for (int jj = 0; jj < 2; jj++) {
            int k = ks * 16 + (lane & 3) * 2 + reg * 8 + jj;
            v[reg * 2 + jj] = (n < N && k < K) ? W[(size_t)k * N + n] : 0.f;
        }
    }
    uint32_t h0, l0, h1, l1;
    split2(make_float2(v[0], v[1]), h0, l0);
    split2(make_float2(v[2], v[3]), h1, l1);
    out[J.off[j] + idx] = make_uint4(h0, h1, l0, l1);
}

// ---------------- conv weight prep ----------------
__global__ void prepcw_kernel(const float* __restrict__ W, uint4* __restrict__ out)
{
    int idx = blockIdx.x * 256 + threadIdx.x;
    if (idx >= 768) return;
    int lane = idx & 31;
    int ks = (idx >> 5) % 6;
    int t  = idx / 192;
    int n = t * 8 + (lane >> 2);
    float v[4];
    #pragma unroll
    for (int reg = 0; reg < 2; reg++) {
        #pragma unroll
        for (int jj = 0; jj < 2; jj++) {
            int kidx = ks * 16 + (lane & 3) * 2 + reg * 8 + jj;
            int kk = kidx >> 5, i = kidx & 31;
            float w = 0.f;
            if (n < 30 && i < 30) w = W[(n * 30 + i) * 3 + kk];
            v[reg * 2 + jj] = w;
        }
    }
    uint32_t h0, l0, h1, l1;
    split2(make_float2(v[0], v[1]), h0, l0);
    split2(make_float2(v[2], v[3]), h1, l1);
    out[idx] = make_uint4(h0, h1, l0, l1);
}

// ---------------- fused conv (round-8 proven) ----------------
__device__ __forceinline__ float ldx(const float* __restrict__ xb, int r, int kidx)
{
    int i = kidx & 31, kk = kidx >> 5;
    int ts = r + kk - 1;
    return (i < NS && ts >= 0 && ts < NT) ? xb[i * NT + ts] : 0.f;
}
__device__ __forceinline__ void conv_l1_group(
    const float* __restrict__ xb, const uint4* __restrict__ Wf, const float* __restrict__ bc1,
    uint2 (*h1s)[16], int t0, int g, int tlo, int thi, int lane)
{
    const int gq = lane >> 2, kq = (lane & 3) * 2;
    const int r0 = t0 - 8 + g * 16 + gq, r1 = r0 + 8;
    float acc[4][4];
    #pragma unroll
    for (int t = 0; t < 4; t++) { acc[t][0] = 0.f; acc[t][1] = 0.f; acc[t][2] = 0.f; acc[t][3] = 0.f; }
    for (int ks = 0; ks < 6; ks++) {
        int kb = ks * 16 + kq;
        float v00 = ldx(xb, r0, kb),     v01 = ldx(xb, r0, kb + 1);
        float v10 = ldx(xb, r1, kb),     v11 = ldx(xb, r1, kb + 1);
        float v02 = ldx(xb, r0, kb + 8), v03 = ldx(xb, r0, kb + 9);
        float v12 = ldx(xb, r1, kb + 8), v13 = ldx(xb, r1, kb + 9);
        uint32_t ah0, al0, ah1, al1, ah2, al2, ah3, al3;
        split2(make_float2(v00, v01), ah0, al0);
        split2(make_float2(v10, v11), ah1, al1);
        split2(make_float2(v02, v03), ah2, al2);
        split2(make_float2(v12, v13), ah3, al3);
        const uint4* bp = Wf + ks * 32 + lane;
        #pragma unroll
        for (int t = 0; t < 4; t++) {
            if (t < tlo || t >= thi) continue;
            uint4 w = bp[t * 192];
            mma16816(acc[t], ah0, ah1, ah2, ah3, w.x, w.y);
            mma16816(acc[t], ah0, ah1, ah2, ah3, w.z, w.w);
            mma16816(acc[t], al0, al1, al2, al3, w.x, w.y);
        }
    }
    const int sr0 = g * 16 + gq, sr1 = sr0 + 8;
    #pragma unroll
    for (int t = 0; t < 4; t++) {
        if (t < tlo || t >= thi) continue;
        int n0 = t * 8 + kq;
        float bb0 = (n0 < 30) ? bc1[n0] : 0.f;
        float bb1 = (n0 + 1 < 30) ? bc1[n0 + 1] : 0.f;
        float v0 = fmaxf(acc[t][0] + bb0, 0.f), v1 = fmaxf(acc[t][1] + bb1, 0.f);
        float v2 = fmaxf(acc[t][2] + bb0, 0.f), v3 = fmaxf(acc[t][3] + bb1, 0.f);
        uint32_t h, l;
        split2(make_float2(v0, v1), h, l);
        h1s[sr0][t * 4 + (kq >> 1)] = make_uint2(h, l);
        split2(make_float2(v2, v3), h, l);
        h1s[sr1][t * 4 + (kq >> 1)] = make_uint2(h, l);
    }
}

__global__ __launch_bounds__(128) void convf_kernel(
    const float* __restrict__ x, const uint4* __restrict__ Wf1, const float* __restrict__ bc1,
    const uint4* __restrict__ Wf2, const float* __restrict__ bc2, float* __restrict__ out)
{
    __shared__ uint2 h1s[80][16];
    const int b = blockIdx.y;
    const int t0 = blockIdx.x * 64;
    const int lane = threadIdx.x & 31, warp = threadIdx.x >> 5;
    const float* xb = x + (size_t)b * NS * NT;

    conv_l1_group(xb, Wf1, bc1, h1s, t0, warp, 0, 4, lane);
    if (warp < 2) conv_l1_group(xb, Wf1, bc1, h1s, t0, 4, warp * 2, warp * 2 + 2, lane);
    __syncthreads();

    const int gq = lane >> 2, kq = (lane & 3) * 2;
    const int r0 = t0 + warp * 16 + gq, r1 = r0 + 8;
    float acc[4][4];
    #pragma unroll
    for (int t = 0; t < 4; t++) { acc[t][0] = 0.f; acc[t][1] = 0.f; acc[t][2] = 0.f; acc[t][3] = 0.f; }
    for (int ks = 0; ks < 6; ks++) {
        int kb = ks * 16 + kq;
        int kk = kb >> 5;
        int i  = kb & 31;
        int ts0 = r0 + kk - 1, ts1 = r1 + kk - 1;
        int s0 = ts0 - (t0 - 8), s1 = ts1 - (t0 - 8);
        uint2 z = make_uint2(0u, 0u);
        uint2 p00 = (ts0 >= 0 && ts0 < NT) ? h1s[s0][i >> 1]       : z;
        uint2 p01 = (ts0 >= 0 && ts0 < NT) ? h1s[s0][(i + 8) >> 1] : z;
        uint2 p10 = (ts1 >= 0 && ts1 < NT) ? h1s[s1][i >> 1]       : z;
        uint2 p11 = (ts1 >= 0 && ts1 < NT) ? h1s[s1][(i + 8) >> 1] : z;
        const uint4* bp = Wf2 + ks * 32 + lane;
        #pragma unroll
        for (int t = 0; t < 4; t++) {
            uint4 w = bp[t * 192];
            mma16816(acc[t], p00.x, p10.x, p01.x, p11.x, w.x, w.y);
            mma16816(acc[t], p00.x, p10.x, p01.x, p11.x, w.z, w.w);
            mma16816(acc[t], p00.y, p10.y, p01.y, p11.y, w.x, w.y);
        }
    }
    #pragma unroll
    for (int t = 0; t < 4; t++) {
        int n0 = t * 8 + kq;
        if (n0 < 30) {
            float bb = bc2[n0];
            out[((size_t)b * NS + n0) * NT + r0] = fmaxf(acc[t][0] + bb, 0.f);
            out[((size_t)b * NS + n0) * NT + r1] = fmaxf(acc[t][2] + bb, 0.f);
        }
        if (n0 + 1 < 30) {
            float bb = bc2[n0 + 1];
            out[((size_t)b * NS + n0 + 1) * NT + r0] = fmaxf(acc[t][1] + bb, 0.f);
            out[((size_t)b * NS + n0 + 1) * NT + r1] = fmaxf(acc[t][3] + bb, 0.f);
        }
    }
}

// ---------------- HMMA split-bf16 GEMM body ----------------
template<int NTl>
__device__ __forceinline__ void mgemm_body(
    const float* __restrict__ A, const uint4* __restrict__ B4,
    const float* __restrict__ bias, float* __restrict__ C,
    int N, int K, int nks, int ldc, int coloff, int relu)
{
    const int lane = threadIdx.x & 31;
    const int warp = threadIdx.x >> 5;
    const int gq = lane >> 2;
    const int q  = lane & 3;
    const int r0 = blockIdx.x * 64 + warp * 16 + gq;
    const int r1 = r0 + 8;
    const int kq = q * 2;

    float acc[NTl][4];
    #pragma unroll
    for (int t = 0; t < NTl; t++) {
        acc[t][0] = 0.f; acc[t][1] = 0.f; acc[t][2] = 0.f; acc[t][3] = 0.f;
    }

    const float* a0p = A + (size_t)r0 * K;
    const float* a1p = A + (size_t)r1 * K;

    for (int ks = 0; ks < nks; ks++) {
        const int kb = ks * 16 + kq;
        float2 x00 = (kb     < K) ? *reinterpret_cast<const float2*>(a0p + kb)     : make_float2(0.f, 0.f);
        float2 x01 = (kb + 8 < K) ? *reinterpret_cast<const float2*>(a0p + kb + 8) : make_float2(0.f, 0.f);
        float2 x10 = (kb     < K) ? *reinterpret_cast<const float2*>(a1p + kb)     : make_float2(0.f, 0.f);
        float2 x11 = (kb + 8 < K) ? *reinterpret_cast<const float2*>(a1p + kb + 8) : make_float2(0.f, 0.f);
        uint32_t ah0, al0, ah1, al1, ah2, al2, ah3, al3;
        split2(x00, ah0, al0);
        split2(x10, ah1, al1);
        split2(x01, ah2, al2);
        split2(x11, ah3, al3);
        const uint4* bp = B4 + ks * 32 + lane;
        const int stride = nks * 32;
        #pragma unroll
        for (int t = 0; t < NTl; t++) {
            uint4 w = bp[(size_t)t * stride];
            mma16816(acc[t], ah0, ah1, ah2, ah3, w.x, w.y);
            mma16816(acc[t], ah0, ah1, ah2, ah3, w.z, w.w);
            mma16816(acc[t], al0, al1, al2, al3, w.x, w.y);
        }
    }

    #pragma unroll
    for (int t = 0; t < NTl; t++) {
        int n0 = t * 8 + kq;
        if (n0 < N) {
            float b0v = bias ? bias[n0] : 0.f;
            float b1v = bias ? bias[n0 + 1] : 0.f;
            float v0 = acc[t][0] + b0v, v1 = acc[t][1] + b1v;
            float v2 = acc[t][2] + b0v, v3 = acc[t][3] + b1v;
            if (relu) {
                v0 = fmaxf(v0, 0.f); v1 = fmaxf(v1, 0.f);
                v2 = fmaxf(v2, 0.f); v3 = fmaxf(v3, 0.f);
            }
            *reinterpret_cast<float2*>(&C[(size_t)r0 * ldc + coloff + n0]) = make_float2(v0, v1);
            *reinterpret_cast<float2*>(&C[(size_t)r1 * ldc + coloff + n0]) = make_float2(v2, v3);
        }
    }
}

// N-split GEMM (200 cols -> 104 + 96), grid (480, 2)
__global__ __launch_bounds__(128, 4) void mgemmS_kernel(
    const float* __restrict__ A, const uint4* __restrict__ B4,
    const float* __restrict__ bias, float* __restrict__ C,
    int K, int nks, int ldc, int relu)
{
    if (blockIdx.y == 0)
        mgemm_body<13>(A, B4, bias, C, 104, K, nks, ldc, 0, relu);
    else
        mgemm_body<12>(A, B4 + 13 * nks * 32, bias ? bias + 104 : nullptr, C, 96, K, nks, ldc, 104, relu);
}

// MEGA1: x1=relu(P1@Wm1), h1s=relu(Q@Wg1), Gv[:,0:150]=relu(Q@Wl), Gv[:,150:300]=relu(P1@Wgl)
__global__ __launch_bounds__(128, 4) void mega1_kernel(
    const float* __restrict__ P1, const float* __restrict__ Q,
    const uint4* __restrict__ Bm1, const uint4* __restrict__ Bg1,
    const uint4* __restrict__ Bl, const uint4* __restrict__ Bgl,
    float* __restrict__ x1, float* __restrict__ h1s, float* __restrict__ Gv)
{
    switch (blockIdx.y) {
    case 0: mgemm_body<13>(P1, Bm1,        nullptr, x1,  104, 200, 13, 200, 0,   1); break;
    case 1: mgemm_body<12>(P1, Bm1 + 5408, nullptr, x1,  96,  200, 13, 200, 104, 1); break;
    case 2: mgemm_body<13>(Q,  Bg1,        nullptr, h1s, 104, 200, 13, 200, 0,   1); break;
    case 3: mgemm_body<12>(Q,  Bg1 + 5408, nullptr, h1s, 96,  200, 13, 200, 104, 1); break;
    case 4: mgemm_body<10>(Q,  Bl,         nullptr, Gv,  80,  200, 13, 300, 0,   1); break;
    case 5: mgemm_body<9> (Q,  Bl + 4160,  nullptr, Gv,  70,  200, 13, 300, 80,  1); break;
    case 6: mgemm_body<10>(P1, Bgl,        nullptr, Gv,  80,  200, 13, 300, 150, 1); break;
    default: mgemm_body<9>(P1, Bgl + 4160, nullptr, Gv,  70,  200, 13, 300, 230, 1); break;
    }
}

// MEGA3: x2=relu(tA@Wm2), xsn=tC@Wg2
__global__ __launch_bounds__(128, 4) void mega3_kernel(
    const float* __restrict__ tA, const float* __restrict__ tC,
    const uint4* __restrict__ Bm2, const uint4* __restrict__ Bg2,
    float* __restrict__ x2, float* __restrict__ xsn)
{
    switch (blockIdx.y) {
    case 0: mgemm_body<13>(tA, Bm2,        nullptr, x2,  104, 200, 13, 200, 0,   1); break;
    case 1: mgemm_body<12>(tA, Bm2 + 5408, nullptr, x2,  96,  200, 13, 200, 104, 1); break;
    case 2: mgemm_body<13>(tC, Bg2,        nullptr, xsn, 104, 200, 13, 200, 0,   0); break;
    default: mgemm_body<12>(tC, Bg2 + 5408, nullptr, xsn, 96, 200, 13, 200, 104, 0); break;
    }
}

// merged 3x (N=100, K=200), split 56+44, grid (480, 6)
__global__ __launch_bounds__(128, 4) void mgemm3_kernel(
    const float* __restrict__ A0, const float* __restrict__ A1, const float* __restrict__ A2,
    const uint4* __restrict__ B4, float* __restrict__ C)
{
    const int j = blockIdx.y >> 1, h = blockIdx.y & 1;
    const float* A = (j == 0) ? A0 : (j == 1) ? A1 : A2;
    const uint4* B = B4 + j * 5408;
    if (h == 0) mgemm_body<7>(A, B, nullptr, C, 56, 200, 13, 300, j * 100, 0);
    else        mgemm_body<6>(A, B + 7 * 13 * 32, nullptr, C, 44, 200, 13, 300, j * 100 + 56, 0);
}

// ---------------- batched small matmul body ----------------
__device__ __forceinline__ void bmm30_body(
    const float* __restrict__ Am, const float* __restrict__ X, float* __restrict__ Out,
    int batched, int b, int tid)
{
    __shared__ float As[NS * NS];
    __shared__ float Xs[NS * NFD];
    const float* A = batched ? (Am + (size_t)b * NS * NS) : Am;
    for (int i = tid; i < NS * NS; i += 256) As[i] = A[i];
    for (int i = tid; i < NS * NFD; i += 256) Xs[i] = X[(size_t)b * NS * NFD + i];
    __syncthreads();
    if (tid < 250) {
        int si = tid / 25, fi = tid - (tid / 25) * 25;
        int s0 = si * 3, f0 = fi * 8;
        float acc[3][8];
        #pragma unroll
        for (int r = 0; r < 3; r++)
            #pragma unroll
            for (int q = 0; q < 8; q++) acc[r][q] = 0.f;
        for (int j = 0; j < NS; j++) {
            float a0 = As[(s0 + 0) * NS + j];
            float a1 = As[(s0 + 1) * NS + j];
            float a2 = As[(s0 + 2) * NS + j];
            float4 xA = *reinterpret_cast<const float4*>(&Xs[j * NFD + f0]);
            float4 xB = *reinterpret_cast<const float4*>(&Xs[j * NFD + f0 + 4]);
            float xv[8] = {xA.x, xA.y, xA.z, xA.w, xB.x, xB.y, xB.z, xB.w};
            #pragma unroll
            for (int q = 0; q < 8; q++) {
                acc[0][q] += a0 * xv[q];
                acc[1][q] += a1 * xv[q];
                acc[2][q] += a2 * xv[q];
            }
        }
        #pragma unroll
        for (int r = 0; r < 3; r++)
            #pragma unroll
            for (int q = 0; q < 8; q++)
                Out[(size_t)b * NS * NFD + (s0 + r) * NFD + f0 + q] = acc[r][q];
    }
}

__global__ __launch_bounds__(256) void bmm30_kernel(
    const float* __restrict__ Am, const float* __restrict__ X, float* __restrict__ Out, int batched)
{
    bmm30_body(Am, X, Out, batched, blockIdx.x, threadIdx.x);
}

// merged P1 = A_F@F2 (y=0) and Q = adj@F2 (y=1)
__global__ __launch_bounds__(256) void bmm2_kernel(
    const float* __restrict__ AF, const float* __restrict__ adj,
    const float* __restrict__ F2, float* __restrict__ P1, float* __restrict__ Q)
{
    if (blockIdx.y == 0) bmm30_body(AF, F2, P1, 1, blockIdx.x, threadIdx.x);
    else                 bmm30_body(adj, F2, Q, 0, blockIdx.x, threadIdx.x);
}

// merged tA = A_F@x1 (y=0) and tC = adj@h1s (y=1)
__global__ __launch_bounds__(256) void bmmM2_kernel(
    const float* __restrict__ AF, const float* __restrict__ adj,
    const float* __restrict__ x1, const float* __restrict__ h1s,
    float* __restrict__ tA, float* __restrict__ tC)
{
    if (blockIdx.y == 0) bmm30_body(AF, x1, tA, 1, blockIdx.x, threadIdx.x);
    else                 bmm30_body(adj, h1s, tC, 0, blockIdx.x, threadIdx.x);
}

// ---------------- fused gate + 3x bmm30(adj, g_k*H_k), xsn from gmem ----------------
__global__ __launch_bounds__(256) void gbmm_kernel(
    const float* __restrict__ adj, const float* __restrict__ x1, const float* __restrict__ x2,
    const float* __restrict__ x3, const float* __restrict__ xsn, const float* __restrict__ wg,
    float* __restrict__ o1, float* __restrict__ o2, float* __restrict__ o3)
{
    extern __shared__ float sm[];
    float* As = sm;
    float* X0 = sm + 900;
    float* X1 = sm + 6900;
    float* X2 = sm + 12900;
    const int b = blockIdx.x, tid = threadIdx.x;
    const size_t base = (size_t)b * 6000;
    for (int i = tid; i < 900; i += 256) As[i] = adj[i];
    for (int i = tid; i < 6000; i += 256) {
        X0[i] = x1[base + i];
        X1[i] = x2[base + i];
        X2[i] = x3[base + i];
    }
    __syncthreads();

    {
        const int warp = tid >> 5, lane = tid & 31;
        for (int rr = 0; rr < 4; rr++) {
            int r = warp * 4 + rr;
            if (r >= NS) break;
            float H0[7], H1[7], H2[7];
            float s0 = 0.f, s1 = 0.f, s2 = 0.f;
            #pragma unroll
            for (int q = 0; q < 7; q++) {
                int f = q * 32 + lane;
                float h0 = 0.f, h1 = 0.f, h2 = 0.f;
                if (f < NFD) {
                    float sv = xsn[base + r * NFD + f];
                    h0 = (X0[r * NFD + f] + sv) * 0.5f;
                    h1 = (X1[r * NFD + f] + sv) * 0.5f;
                    h2 = (X2[r * NFD + f] + sv) * 0.5f;
                    s0 += h0 * wg[f * 3 + 0];
                    s1 += h1 * wg[f * 3 + 1];
                    s2 += h2 * wg[f * 3 + 2];
                }
                H0[q] = h0; H1[q] = h1; H2[q] = h2;
            }
            #pragma unroll
            for (int o = 16; o; o >>= 1) {
                s0 += __shfl_xor_sync(0xffffffffu, s0, o);
                s1 += __shfl_xor_sync(0xffffffffu, s1, o);
                s2 += __shfl_xor_sync(0xffffffffu, s2, o);
            }
            float mx = fmaxf(s0, fmaxf(s1, s2));
            float e0 = expf(s0 - mx), e1 = expf(s1 - mx), e2 = expf(s2 - mx);
            float inv = 1.f / (e0 + e1 + e2);
            e0 *= inv; e1 *= inv; e2 *= inv;
            #pragma unroll
            for (int q = 0; q < 7; q++) {
                int f = q * 32 + lane;
                if (f < NFD) {
                    X0[r * NFD + f] = e0 * H0[q];
                    X1[r * NFD + f] = e1 * H1[q];
                    X2[r * NFD + f] = e2 * H2[q];
                }
            }
        }
    }
    __syncthreads();

    if (tid < 250) {
        int si = tid / 25, fi = tid - (tid / 25) * 25;
        int s0 = si * 3, f0 = fi * 8;
        float* Xk[3] = {X0, X1, X2};
        float* Ok[3] = {o1, o2, o3};
        #pragma unroll
        for (int k = 0; k < 3; k++) {
            const float* X = Xk[k];
            float acc[3][8];
            #pragma unroll
            for (int r = 0; r < 3; r++)
                #pragma unroll
                for (int q = 0; q < 8; q++) acc[r][q] = 0.f;
            for (int j = 0; j < NS; j++) {
                float a0 = As[(s0 + 0) * NS + j];
                float a1 = As[(s0 + 1) * NS + j];
                float a2 = As[(s0 + 2) * NS + j];
                float4 xA = *reinterpret_cast<const float4*>(&X[j * NFD + f0]);
                float4 xB = *reinterpret_cast<const float4*>(&X[j * NFD + f0 + 4]);
                float xv[8] = {xA.x, xA.y, xA.z, xA.w, xB.x, xB.y, xB.z, xB.w};
                #pragma unroll
                for (int q = 0; q < 8; q++) {
                    acc[0][q] += a0 * xv[q];
                    acc[1][q] += a1 * xv[q];
                    acc[2][q] += a2 * xv[q];
                }
            }
            #pragma unroll
            for (int r = 0; r < 3; r++)
                #pragma unroll
                for (int q = 0; q < 8; q++)
                    Ok[k][base + (s0 + r) * NFD + f0 + q] = acc[r][q];
        }
    }
}

// ---------------- A_F = softmax(relu(tmp @ F2^T)) per batch ----------------
__global__ __launch_bounds__(128) void af_kernel(
    const float* __restrict__ Tm, const float* __restrict__ F2, float* __restrict__ AF)
{
    __shared__ float Ts[NS * NFD];
    __shared__ float Fs[NS * NFD];
    const int b = blockIdx.x;
    const int tid = threadIdx.x;
    for (int i = tid; i < NS * NFD; i += 128) {
        Ts[i] = Tm[(size_t)b * NS * NFD + i];
        Fs[i] = F2[(size_t)b * NS * NFD + i];
    }
    __syncthreads();
    float acc[3][3];
    int ii = 0, jj = 0;
    if (tid < 100) {
        ii = (tid / 10) * 3; jj = (tid % 10) * 3;
        #pragma unroll
        for (int r = 0; r < 3; r++)
            #pragma unroll
            for (int c = 0; c < 3; c++) acc[r][c] = 0.f;
        for (int g = 0; g < NFD; g++) {
            float t0 = Ts[(ii + 0) * NFD + g], t1 = Ts[(ii + 1) * NFD + g], t2 = Ts[(ii + 2) * NFD + g];
            float f0 = Fs[(jj + 0) * NFD + g], f1 = Fs[(jj + 1) * NFD + g], f2 = Fs[(jj + 2) * NFD + g];
            acc[0][0] += t0 * f0; acc[0][1] += t0 * f1; acc[0][2] += t0 * f2;
            acc[1][0] += t1 * f0; acc[1][1] += t1 * f1; acc[1][2] += t1 * f2;
            acc[2][0] += t2 * f0; acc[2][1] += t2 * f1; acc[2][2] += t2 * f2;
        }
    }
    __syncthreads();
    float (*Ms)[31] = reinterpret_cast<float(*)[31]>(Ts);
    if (tid < 100) {
        #pragma unroll
        for (int r = 0; r < 3; r++)
            #pragma unroll
            for (int c = 0; c < 3; c++) Ms[ii + r][jj + c] = fmaxf(acc[r][c], 0.f);
    }
    __syncthreads();
    if (tid < NS) {
        float mx = -1e30f;
        for (int j = 0; j < NS; j++) mx = fmaxf(mx, Ms[tid][j]);
        float s = 0.f;
        for (int j = 0; j < NS; j++) s += expf(Ms[tid][j] - mx);
        float inv = 1.f / s;
        for (int j = 0; j < NS; j++)
            AF[(size_t)b * NS * NS + tid * NS + j] = expf(Ms[tid][j] - mx) * inv;
    }
}

// ---------------- SE blocks ----------------
__global__ __launch_bounds__(128) void se1_kernel(
    const float* __restrict__ Gv, const float* __restrict__ Ws1,
    const float* __restrict__ Ws2, float* __restrict__ wch)
{
    const int warp = threadIdx.x >> 5, lane = threadIdx.x & 31;
    const int b = blockIdx.x * 4 + warp;
    __shared__ float mvs[4][NS];
    __shared__ float avs[4][15];
    float* mv = mvs[warp];
    float* av = avs[warp];
    for (int s = 0; s < NS; s++) {
        float p = 0.f;
        for (int j = lane; j < 300; j += 32) p += Gv[(size_t)b * 9000 + s * 300 + j];
        #pragma unroll
        for (int o = 16; o; o >>= 1) p += __shfl_xor_sync(0xffffffffu, p, o);
        if (lane == 0) mv[s] = p * (1.f / 300.f);
    }
    __syncwarp();
    if (lane < 15) {
        float a = 0.f;
        for (int s = 0; s < NS; s++) a += mv[s] * Ws1[s * 15 + lane];
        av[lane] = fmaxf(a, 0.f);
    }
    __syncwarp();
    if (lane < NS) {
        float a = 0.f;
        for (int h = 0; h < 15; h++) a += av[h] * Ws2[h * NS + lane];
        wch[b * NS + lane] = 1.f / (1.f + expf(-a));
    }
}

__global__ __launch_bounds__(320) void se2_kernel(const float* __restrict__ Gh,
                                                  const float* __restrict__ Wf1,
                                                  const float* __restrict__ Wf2,
                                                  float* __restrict__ wft)
{
    __shared__ float m[4][300];
    __shared__ float t1[4][152];
    const int b0 = blockIdx.x * 4, tid = threadIdx.x;
    if (tid < 300) {
        #pragma unroll
        for (int bb = 0; bb < 4; bb++) {
            float a = 0.f;
            for (int s = 0; s < NS; s++) a += Gh[(size_t)(b0 + bb) * 9000 + s * 300 + tid];
            m[bb][tid] = a * (1.f / 30.f);
        }
    }
    __syncthreads();
    if (tid < 150) {
        float a[4] = {0.f, 0.f, 0.f, 0.f};
        for (int j = 0; j < 300; j++) {
            float w = Wf1[j * 150 + tid];
            #pragma unroll
            for (int bb = 0; bb < 4; bb++) a[bb] += m[bb][j] * w;
        }
        #pragma unroll
        for (int bb = 0; bb < 4; bb++) t1[bb][tid] = fmaxf(a[bb], 0.f);
    }
    __syncthreads();
    if (tid < 300) {
        float a[4] = {0.f, 0.f, 0.f, 0.f};
        for (int h = 0; h < 150; h++) {
            float w = Wf2[h * 300 + tid];
            #pragma unroll
            for (int bb = 0; bb < 4; bb++) a[bb] += t1[bb][h] * w;
        }
        #pragma unroll
        for (int bb = 0; bb < 4; bb++)
            wft[(size_t)(b0 + bb) * 300 + tid] = 1.f / (1.f + expf(-a[bb]));
    }
}

// ---------------- classifier + log_softmax ----------------
__global__ __launch_bounds__(256) void cls_kernel(
    const float* __restrict__ Gh, const float* __restrict__ Gv,
    const float* __restrict__ wch, const float* __restrict__ wft,
    const float* __restrict__ Wcls, const float* __restrict__ bcls, float* __restrict__ out)
{
    const int b0 = blockIdx.x * 4, tid = threadIdx.x;
    const int lane = tid & 31, warp = tid >> 5;
    float acc[4][NCL];
    #pragma unroll
    for (int bb = 0; bb < 4; bb++)
        #pragma unroll
        for (int k = 0; k < NCL; k++) acc[bb][k] = 0.f;

    for (int idx = tid; idx < 18000; idx += 256) {
        int s = idx / 600;
        int c = idx - s * 600;
        float w[NCL];
        #pragma unroll
        for (int k = 0; k < NCL; k++) w[k] = Wcls[(size_t)idx * NCL + k];
        #pragma unroll
        for (int bb = 0; bb < 4; bb++) {
            int b = b0 + bb;
            float val;
            if (c < 300) val = Gh[(size_t)b * 9000 + s * 300 + c] * wch[b * NS + s];
            else {
                int cc = c - 300;
                val = Gv[(size_t)b * 9000 + s * 300 + cc] * wft[(size_t)b * 300 + cc];
            }
            #pragma unroll
            for (int k = 0; k < NCL; k++) acc[bb][k] += val * w[k];
        }
    }
    #pragma unroll
    for (int bb = 0; bb < 4; bb++)
        #pragma unroll
        for (int k = 0; k < NCL; k++)
            #pragma unroll
            for (int o = 16; o; o >>= 1)
                acc[bb][k] += __shfl_xor_sync(0xffffffffu, acc[bb][k], o);
    __shared__ float red[8][4][NCL];
    __shared__ float zs[4][NCL];
    if (lane == 0) {
        #pragma unroll
        for (int bb = 0; bb < 4; bb++)
            #pragma unroll
            for (int k = 0; k < NCL; k++) red[warp][bb][k] = acc[bb][k];
    }
    __syncthreads();
    if (tid < 28) {
        int bb = tid / 7, k = tid - bb * 7;
        float z = bcls[k];
        #pragma unroll
        for (int w2 = 0; w2 < 8; w2++) z += red[w2][bb][k];
        zs[bb][k] = z;
    }
    __syncthreads();
    if (tid < 4) {
        float mx = -1e30f;
        #pragma unroll
        for (int k = 0; k < NCL; k++) mx = fmaxf(mx, zs[tid][k]);
        float s = 0.f;
        #pragma unroll
        for (int k = 0; k < NCL; k++) s += expf(zs[tid][k] - mx);
        float ls = logf(s);
        #pragma unroll
        for (int k = 0; k < NCL; k++) out[(b0 + tid) * NCL + k] = zs[tid][k] - mx - ls;
    }
}

// ---------------- launch ----------------
extern "C" void kernel_launch(void* const* d_in, const int* in_sizes, int n_in,
                              void* d_out, int out_size)
{
    const float* x    = (const float*)d_in[0];
    const float* adj  = (const float*)d_in[1];
    const float* Wc1  = (const float*)d_in[2];
    const float* bc1  = (const float*)d_in[3];
    const float* Wc2  = (const float*)d_in[4];
    const float* bc2  = (const float*)d_in[5];
    const float* Wt   = (const float*)d_in[6];
    const float* bt   = (const float*)d_in[7];
    const float* Wa   = (const float*)d_in[8];
    const float* Wm1  = (const float*)d_in[9];
    const float* Wm2  = (const float*)d_in[10];
    const float* Wm3  = (const float*)d_in[11];
    const float* Wg1  = (const float*)d_in[12];
    const float* Wg2  = (const float*)d_in[13];
    const float* wg   = (const float*)d_in[14];
    const float* Wp1  = (const float*)d_in[15];
    const float* Wp2  = (const float*)d_in[16];
    const float* Wp3  = (const float*)d_in[17];
    const float* Wl   = (const float*)d_in[18];
    const float* Wgl  = (const float*)d_in[19];
    const float* Ws1  = (const float*)d_in[20];
    const float* Ws2  = (const float*)d_in[21];
    const float* Wf1  = (const float*)d_in[22];
    const float* Wf2  = (const float*)d_in[23];
    const float* Wcls = (const float*)d_in[24];
    const float* bcls = (const float*)d_in[25];
    float* out = (float*)d_out;

    float *p_h2, *p_F2, *p_tmp, *p_tmp2, *p_P1, *p_x1, *p_x2, *p_x3, *p_Q, *p_h1s, *p_xsn;
    float *p_gH1, *p_gH2, *p_gH3, *p_AF, *p_Gh, *p_Gv, *p_wch, *p_wft;
    uint4 *p_b4, *p_cw1, *p_cw2;
    cudaGetSymbolAddress((void**)&p_h2,   g_h2);
    cudaGetSymbolAddress((void**)&p_F2,   g_F2);
    cudaGetSymbolAddress((void**)&p_tmp,  g_tmp);
    cudaGetSymbolAddress((void**)&p_tmp2, g_tmp2);
    cudaGetSymbolAddress((void**)&p_P1,   g_P1);
    cudaGetSymbolAddress((void**)&p_x1,   g_x1);
    cudaGetSymbolAddress((void**)&p_x2,   g_x2);
    cudaGetSymbolAddress((void**)&p_x3,   g_x3);
    cudaGetSymbolAddress((void**)&p_Q,    g_Q);
    cudaGetSymbolAddress((void**)&p_h1s,  g_h1s);
    cudaGetSymbolAddress((void**)&p_xsn,  g_xsn);
    cudaGetSymbolAddress((void**)&p_gH1,  g_gH1);
    cudaGetSymbolAddress((void**)&p_gH2,  g_gH2);
    cudaGetSymbolAddress((void**)&p_gH3,  g_gH3);
    cudaGetSymbolAddress((void**)&p_AF,   g_AF);
    cudaGetSymbolAddress((void**)&p_Gh,   g_Gh);
    cudaGetSymbolAddress((void**)&p_Gv,   g_Gv);
    cudaGetSymbolAddress((void**)&p_wch,  g_wch);
    cudaGetSymbolAddress((void**)&p_wft,  g_wft);
    cudaGetSymbolAddress((void**)&p_b4,   g_bf4);
    cudaGetSymbolAddress((void**)&p_cw1,  g_cw1);
    cudaGetSymbolAddress((void**)&p_cw2,  g_cw2);

    // fragment pool offsets (uint4 units)
    const int oWt  = 0;
    const int oWa  = 51200;
    const int oWm1 = 61600, oWm2 = 72000, oWm3 = 82400;
    const int oWg1 = 92800, oWg2 = 103200;
    const int oWp1 = 113600, oWp2 = 119008, oWp3 = 124416;
    const int oWl  = 129824, oWgl = 137728;

    PJobs J;
    const float* Ws[12] = {Wt, Wa, Wm1, Wm2, Wm3, Wg1, Wg2, Wp1, Wp2, Wp3, Wl, Wgl};
    const int   Ks[12] = {1024, 200, 200, 200, 200, 200, 200, 200, 200, 200, 200, 200};
    const int   Nn[12] = {200, 200, 200, 200, 200, 200, 200, 100, 100, 100, 150, 150};
    const int   Tt[12] = {25, 25, 25, 25, 25, 25, 25, 13, 13, 13, 19, 19};
    const int   Kk[12] = {64, 13, 13, 13, 13, 13, 13, 13, 13, 13, 13, 13};
    const int   Of[12] = {oWt, oWa, oWm1, oWm2, oWm3, oWg1, oWg2, oWp1, oWp2, oWp3, oWl, oWgl};
    for (int i = 0; i < 12; i++) {
        J.W[i] = Ws[i]; J.K[i] = Ks[i]; J.N[i] = Nn[i];
        J.nT[i] = Tt[i]; J.nks[i] = Kk[i]; J.off[i] = Of[i];
    }

    const int GBMM_SMEM = 18900 * 4;   // 75.6 KB -> 2 CTAs/SM
    cudaFuncSetAttribute(gbmm_kernel, cudaFuncAttributeMaxDynamicSharedMemorySize, GBMM_SMEM);

    prepall_kernel<<<dim3(200, 12), 256>>>(J, p_b4);
    prepcw_kernel<<<3, 256>>>(Wc1, p_cw1);
    prepcw_kernel<<<3, 256>>>(Wc2, p_cw2);

    const int GM = MROWS / 64;   // 480 CTAs
    dim3 gS(GM, 2);

    // CNN feature extractor
    convf_kernel<<<dim3(16, BATCH), 128>>>(x, p_cw1, bc1, p_cw2, bc2, p_h2);
    mgemmS_kernel<<<gS, 128>>>(p_h2, p_b4+oWt, bt, p_F2, 1024, 64, 200, 1);

    // learned adjacency
    mgemmS_kernel<<<gS, 128>>>(p_F2, p_b4+oWa, nullptr, p_tmp, 200, 13, 200, 0);
    af_kernel<<<BATCH, 128>>>(p_tmp, p_F2, p_AF);

    // P1 = A_F@F2, Q = adj@F2 (merged)
    bmm2_kernel<<<dim3(BATCH, 2), 256>>>(p_AF, adj, p_F2, p_P1, p_Q);

    // MEGA1: x1, h1s, and both LGFM halves of G_v (all ready after bmm2)
    mega1_kernel<<<dim3(GM, 8), 128>>>(p_P1, p_Q, p_b4+oWm1, p_b4+oWg1, p_b4+oWl, p_b4+oWgl,
                                       p_x1, p_h1s, p_Gv);

    // se1 only needs G_v
    se1_kernel<<<BATCH / 4, 128>>>(p_Gv, Ws1, Ws2, p_wch);

    // MEGA2: tA = A_F@x1, tC = adj@h1s
    bmmM2_kernel<<<dim3(BATCH, 2), 256>>>(p_AF, adj, p_x1, p_h1s, p_tmp, p_tmp2);

    // MEGA3: x2 = relu(tA@Wm2), xsn = tC@Wg2
    mega3_kernel<<<dim3(GM, 4), 128>>>(p_tmp, p_tmp2, p_b4+oWm2, p_b4+oWg2, p_x2, p_xsn);

    // x3 chain
    bmm30_kernel<<<BATCH, 256>>>(p_AF, p_x2, p_tmp, 1);
    mgemmS_kernel<<<gS, 128>>>(p_tmp, p_b4+oWm3, nullptr, p_x3, 200, 13, 200, 1);

    // fused gate + adj-aggregation
    gbmm_kernel<<<BATCH, 256, GBMM_SMEM>>>(adj, p_x1, p_x2, p_x3, p_xsn, wg, p_gH1, p_gH2, p_gH3);

    // G_h: 3 projections (merged, N-split)
    mgemm3_kernel<<<dim3(GM, 6), 128>>>(p_gH1, p_gH2, p_gH3, p_b4+oWp1, p_Gh);

    // se2 + classifier
    se2_kernel<<<BATCH / 4, 320>>>(p_Gh, Wf1, Wf2, p_wft);
    cls_kernel<<<BATCH / 4, 256>>>(p_Gh, p_Gv, p_wch, p_wft, Wcls, bcls, out);
}

// round 13
// speedup vs baseline: 1.3741x; 1.0087x over previous
#include <cuda_runtime.h>
#include <cuda_bf16.h>
#include <cstdint>
#include <cstdio>

#define BATCH 1024
#define NS    30
#define NT    1024
#define NFD   200
#define NCL   7
#define MROWS (BATCH*NS)      // 30720

static inline int cdiv(int a, int b) { return (a + b - 1) / b; }

// ---------------- scratch (device globals; no allocation) ----------------
__device__ float g_h2  [BATCH*NS*NT];
__device__ float g_F2  [MROWS*NFD];
__device__ float g_tmp [MROWS*NFD];
__device__ float g_tmp2[MROWS*NFD];
__device__ float g_P1  [MROWS*NFD];
__device__ float g_x1  [MROWS*NFD];
__device__ float g_x2  [MROWS*NFD];
__device__ float g_x3  [MROWS*NFD];
__device__ float g_Q   [MROWS*NFD];
__device__ float g_h1s [MROWS*NFD];
__device__ float g_xsn [MROWS*NFD];
__device__ float g_gH1 [MROWS*NFD];
__device__ float g_gH2 [MROWS*NFD];
__device__ float g_gH3 [MROWS*NFD];
__device__ float g_AF  [BATCH*NS*NS];
__device__ float g_Gh  [MROWS*300];
__device__ float g_Gv  [MROWS*300];
__device__ float g_wch [MROWS];
__device__ float g_wft [BATCH*300];

// packed weight fragments: uint4 = {hi_r0, hi_r1, lo_r0, lo_r1}
__device__ uint4 g_bf4[150000];
__device__ uint4 g_cw1[768];
__device__ uint4 g_cw2[768];

// ---------------- mma + split helpers ----------------
__device__ __forceinline__ void mma16816(float* c, uint32_t a0, uint32_t a1, uint32_t a2, uint32_t a3,
                                         uint32_t b0, uint32_t b1) {
    asm volatile("mma.sync.aligned.m16n8k16.row.col.f32.bf16.bf16.f32 "
        "{%0,%1,%2,%3}, {%4,%5,%6,%7}, {%8,%9}, {%0,%1,%2,%3};"
        : "+f"(c[0]), "+f"(c[1]), "+f"(c[2]), "+f"(c[3])
        : "r"(a0), "r"(a1), "r"(a2), "r"(a3), "r"(b0), "r"(b1));
}
__device__ __forceinline__ void split2(float2 v, uint32_t& hi, uint32_t& lo) {
    __nv_bfloat162 h = __floats2bfloat162_rn(v.x, v.y);
    float2 hf = __bfloat1622float2(h);
    __nv_bfloat162 l = __floats2bfloat162_rn(v.x - hf.x, v.y - hf.y);
    hi = reinterpret_cast<uint32_t&>(h);
    lo = reinterpret_cast<uint32_t&>(l);
}

// ---------------- merged weight prep ----------------
struct PJobs {
    const float* W[12];
    int K[12], N[12], nT[12], nks[12], off[12];
};
__global__ void prepall_kernel(PJobs J, uint4* __restrict__ out)
{
    const int j = blockIdx.y;
    const int idx = blockIdx.x * 256 + threadIdx.x;
    const int nks = J.nks[j];
    const int total = J.nT[j] * nks * 32;
    if (idx >= total) return;
    const int K = J.K[j], N = J.N[j];
    const float* W = J.W[j];
    int lane = idx & 31;
    int s = idx >> 5;
    int ks = s % nks;
    int t  = s / nks;
    int n = t * 8 + (lane >> 2);
    float v[4];
    #pragma unroll
    for (int reg = 0; reg < 2; reg++) {
        #pragma unroll
        for (int jj = 0; jj < 2; jj++) {
            int k = ks * 16 + (lane & 3) * 2 + reg * 8 + jj;
            v[reg * 2 + jj] = (n < N && k < K) ? W[(size_t)k * N + n] : 0.f;
        }
    }
    uint32_t h0, l0, h1, l1;
    split2(make_float2(v[0], v[1]), h0, l0);
    split2(make_float2(v[2], v[3]), h1, l1);
    out[J.off[j] + idx] = make_uint4(h0, h1, l0, l1);
}

// ---------------- conv weight prep (both layers, grid.y selects) ----------------
__global__ void prepcw_kernel(const float* __restrict__ W1, const float* __restrict__ W2,
                              uint4* __restrict__ out1, uint4* __restrict__ out2)
{
    int idx = blockIdx.x * 256 + threadIdx.x;
    if (idx >= 768) return;
    const float* W = blockIdx.y ? W2 : W1;
    uint4* out = blockIdx.y ? out2 : out1;
    int lane = idx & 31;
    int ks = (idx >> 5) % 6;
    int t  = idx / 192;
    int n = t * 8 + (lane >> 2);
    float v[4];
    #pragma unroll
    for (int reg = 0; reg < 2; reg++) {
        #pragma unroll
        for (int jj = 0; jj < 2; jj++) {
            int kidx = ks * 16 + (lane & 3) * 2 + reg * 8 + jj;
            int kk = kidx >> 5, i = kidx & 31;
            float w = 0.f;
            if (n < 30 && i < 30) w = W[(n * 30 + i) * 3 + kk];
            v[reg * 2 + jj] = w;
        }
    }
    uint32_t h0, l0, h1, l1;
    split2(make_float2(v[0], v[1]), h0, l0);
    split2(make_float2(v[2], v[3]), h1, l1);
    out[idx] = make_uint4(h0, h1, l0, l1);
}

// ---------------- fused conv (round-8 proven) ----------------
__device__ __forceinline__ float ldx(const float* __restrict__ xb, int r, int kidx)
{
    int i = kidx & 31, kk = kidx >> 5;
    int ts = r + kk - 1;
    return (i < NS && ts >= 0 && ts < NT) ? xb[i * NT + ts] : 0.f;
}
__device__ __forceinline__ void conv_l1_group(
    const float* __restrict__ xb, const uint4* __restrict__ Wf, const float* __restrict__ bc1,
    uint2 (*h1s)[16], int t0, int g, int tlo, int thi, int lane)
{
    const int gq = lane >> 2, kq = (lane & 3) * 2;
    const int r0 = t0 - 8 + g * 16 + gq, r1 = r0 + 8;
    float acc[4][4];
    #pragma unroll
    for (int t = 0; t < 4; t++) { acc[t][0] = 0.f; acc[t][1] = 0.f; acc[t][2] = 0.f; acc[t][3] = 0.f; }
    for (int ks = 0; ks < 6; ks++) {
        int kb = ks * 16 + kq;
        float v00 = ldx(xb, r0, kb),     v01 = ldx(xb, r0, kb + 1);
        float v10 = ldx(xb, r1, kb),     v11 = ldx(xb, r1, kb + 1);
        float v02 = ldx(xb, r0, kb + 8), v03 = ldx(xb, r0, kb + 9);
        float v12 = ldx(xb, r1, kb + 8), v13 = ldx(xb, r1, kb + 9);
        uint32_t ah0, al0, ah1, al1, ah2, al2, ah3, al3;
        split2(make_float2(v00, v01), ah0, al0);
        split2(make_float2(v10, v11), ah1, al1);
        split2(make_float2(v02, v03), ah2, al2);
        split2(make_float2(v12, v13), ah3, al3);
        const uint4* bp = Wf + ks * 32 + lane;
        #pragma unroll
        for (int t = 0; t < 4; t++) {
            if (t < tlo || t >= thi) continue;
            uint4 w = bp[t * 192];
            mma16816(acc[t], ah0, ah1, ah2, ah3, w.x, w.y);
            mma16816(acc[t], ah0, ah1, ah2, ah3, w.z, w.w);
            mma16816(acc[t], al0, al1, al2, al3, w.x, w.y);
        }
    }
    const int sr0 = g * 16 + gq, sr1 = sr0 + 8;
    #pragma unroll
    for (int t = 0; t < 4; t++) {
        if (t < tlo || t >= thi) continue;
        int n0 = t * 8 + kq;
        float bb0 = (n0 < 30) ? bc1[n0] : 0.f;
        float bb1 = (n0 + 1 < 30) ? bc1[n0 + 1] : 0.f;
        float v0 = fmaxf(acc[t][0] + bb0, 0.f), v1 = fmaxf(acc[t][1] + bb1, 0.f);
        float v2 = fmaxf(acc[t][2] + bb0, 0.f), v3 = fmaxf(acc[t][3] + bb1, 0.f);
        uint32_t h, l;
        split2(make_float2(v0, v1), h, l);
        h1s[sr0][t * 4 + (kq >> 1)] = make_uint2(h, l);
        split2(make_float2(v2, v3), h, l);
        h1s[sr1][t * 4 + (kq >> 1)] = make_uint2(h, l);
    }
}

__global__ __launch_bounds__(128) void convf_kernel(
    const float* __restrict__ x, const uint4* __restrict__ Wf1, const float* __restrict__ bc1,
    const uint4* __restrict__ Wf2, const float* __restrict__ bc2, float* __restrict__ out)
{
    __shared__ uint2 h1s[80][16];
    const int b = blockIdx.y;
    const int t0 = blockIdx.x * 64;
    const int lane = threadIdx.x & 31, warp = threadIdx.x >> 5;
    const float* xb = x + (size_t)b * NS * NT;

    conv_l1_group(xb, Wf1, bc1, h1s, t0, warp, 0, 4, lane);
    if (warp < 2) conv_l1_group(xb, Wf1, bc1, h1s, t0, 4, warp * 2, warp * 2 + 2, lane);
    __syncthreads();

    const int gq = lane >> 2, kq = (lane & 3) * 2;
    const int r0 = t0 + warp * 16 + gq, r1 = r0 + 8;
    float acc[4][4];
    #pragma unroll
    for (int t = 0; t < 4; t++) { acc[t][0] = 0.f; acc[t][1] = 0.f; acc[t][2] = 0.f; acc[t][3] = 0.f; }
    for (int ks = 0; ks < 6; ks++) {
        int kb = ks * 16 + kq;
        int kk = kb >> 5;
        int i  = kb & 31;
        int ts0 = r0 + kk - 1, ts1 = r1 + kk - 1;
        int s0 = ts0 - (t0 - 8), s1 = ts1 - (t0 - 8);
        uint2 z = make_uint2(0u, 0u);
        uint2 p00 = (ts0 >= 0 && ts0 < NT) ? h1s[s0][i >> 1]       : z;
        uint2 p01 = (ts0 >= 0 && ts0 < NT) ? h1s[s0][(i + 8) >> 1] : z;
        uint2 p10 = (ts1 >= 0 && ts1 < NT) ? h1s[s1][i >> 1]       : z;
        uint2 p11 = (ts1 >= 0 && ts1 < NT) ? h1s[s1][(i + 8) >> 1] : z;
        const uint4* bp = Wf2 + ks * 32 + lane;
        #pragma unroll
        for (int t = 0; t < 4; t++) {
            uint4 w = bp[t * 192];
            mma16816(acc[t], p00.x, p10.x, p01.x, p11.x, w.x, w.y);
            mma16816(acc[t], p00.x, p10.x, p01.x, p11.x, w.z, w.w);
            mma16816(acc[t], p00.y, p10.y, p01.y, p11.y, w.x, w.y);
        }
    }
    #pragma unroll
    for (int t = 0; t < 4; t++) {
        int n0 = t * 8 + kq;
        if (n0 < 30) {
            float bb = bc2[n0];
            out[((size_t)b * NS + n0) * NT + r0] = fmaxf(acc[t][0] + bb, 0.f);
            out[((size_t)b * NS + n0) * NT + r1] = fmaxf(acc[t][2] + bb, 0.f);
        }
        if (n0 + 1 < 30) {
            float bb = bc2[n0 + 1];
            out[((size_t)b * NS + n0 + 1) * NT + r0] = fmaxf(acc[t][1] + bb, 0.f);
            out[((size_t)b * NS + n0 + 1) * NT + r1] = fmaxf(acc[t][3] + bb, 0.f);
        }
    }
}

// ---------------- HMMA split-bf16 GEMM body ----------------
template<int NTl>
__device__ __forceinline__ void mgemm_body(
    const float* __restrict__ A, const uint4* __restrict__ B4,
    const float* __restrict__ bias, float* __restrict__ C,
    int N, int K, int nks, int ldc, int coloff, int relu)
{
    const int lane = threadIdx.x & 31;
    const int warp = threadIdx.x >> 5;
    const int gq = lane >> 2;
    const int q  = lane & 3;
    const int r0 = blockIdx.x * 64 + warp * 16 + gq;
    const int r1 = r0 + 8;
    const int kq = q * 2;

    float acc[NTl][4];
    #pragma unroll
    for (int t = 0; t < NTl; t++) {
        acc[t][0] = 0.f; acc[t][1] = 0.f; acc[t][2] = 0.f; acc[t][3] = 0.f;
    }

    const float* a0p = A + (size_t)r0 * K;
    const float* a1p = A + (size_t)r1 * K;

    for (int ks = 0; ks < nks; ks++) {
        const int kb = ks * 16 + kq;
        float2 x00 = (kb     < K) ? *reinterpret_cast<const float2*>(a0p + kb)     : make_float2(0.f, 0.f);
        float2 x01 = (kb + 8 < K) ? *reinterpret_cast<const float2*>(a0p + kb + 8) : make_float2(0.f, 0.f);
        float2 x10 = (kb     < K) ? *reinterpret_cast<const float2*>(a1p + kb)     : make_float2(0.f, 0.f);
        float2 x11 = (kb + 8 < K) ? *reinterpret_cast<const float2*>(a1p + kb + 8) : make_float2(0.f, 0.f);
        uint32_t ah0, al0, ah1, al1, ah2, al2, ah3, al3;
        split2(x00, ah0, al0);
        split2(x10, ah1, al1);
        split2(x01, ah2, al2);
        split2(x11, ah3, al3);
        const uint4* bp = B4 + ks * 32 + lane;
        const int stride = nks * 32;
        #pragma unroll
        for (int t = 0; t < NTl; t++) {
            uint4 w = bp[(size_t)t * stride];
            mma16816(acc[t], ah0, ah1, ah2, ah3, w.x, w.y);
            mma16816(acc[t], ah0, ah1, ah2, ah3, w.z, w.w);
            mma16816(acc[t], al0, al1, al2, al3, w.x, w.y);
        }
    }

    #pragma unroll
    for (int t = 0; t < NTl; t++) {
        int n0 = t * 8 + kq;
        if (n0 < N) {
            float b0v = bias ? bias[n0] : 0.f;
            float b1v = bias ? bias[n0 + 1] : 0.f;
            float v0 = acc[t][0] + b0v, v1 = acc[t][1] + b1v;
            float v2 = acc[t][2] + b0v, v3 = acc[t][3] + b1v;
            if (relu) {
                v0 = fmaxf(v0, 0.f); v1 = fmaxf(v1, 0.f);
                v2 = fmaxf(v2, 0.f); v3 = fmaxf(v3, 0.f);
            }
            *reinterpret_cast<float2*>(&C[(size_t)r0 * ldc + coloff + n0]) = make_float2(v0, v1);
            *reinterpret_cast<float2*>(&C[(size_t)r1 * ldc + coloff + n0]) = make_float2(v2, v3);
        }
    }
}

// N-split GEMM (200 cols -> 104 + 96), grid (480, 2)
__global__ __launch_bounds__(128, 4) void mgemmS_kernel(
    const float* __restrict__ A, const uint4* __restrict__ B4,
    const float* __restrict__ bias, float* __restrict__ C,
    int K, int nks, int ldc, int relu)
{
    if (blockIdx.y == 0)
        mgemm_body<13>(A, B4, bias, C, 104, K, nks, ldc, 0, relu);
    else
        mgemm_body<12>(A, B4 + 13 * nks * 32, bias ? bias + 104 : nullptr, C, 96, K, nks, ldc, 104, relu);
}

// MEGA1: x1=relu(P1@Wm1), h1s=relu(Q@Wg1), Gv[:,0:150]=relu(Q@Wl), Gv[:,150:300]=relu(P1@Wgl)
__global__ __launch_bounds__(128, 4) void mega1_kernel(
    const float* __restrict__ P1, const float* __restrict__ Q,
    const uint4* __restrict__ Bm1, const uint4* __restrict__ Bg1,
    const uint4* __restrict__ Bl, const uint4* __restrict__ Bgl,
    float* __restrict__ x1, float* __restrict__ h1s, float* __restrict__ Gv)
{
    switch (blockIdx.y) {
    case 0: mgemm_body<13>(P1, Bm1,        nullptr, x1,  104, 200, 13, 200, 0,   1); break;
    case 1: mgemm_body<12>(P1, Bm1 + 5408, nullptr, x1,  96,  200, 13, 200, 104, 1); break;
    case 2: mgemm_body<13>(Q,  Bg1,        nullptr, h1s, 104, 200, 13, 200, 0,   1); break;
    case 3: mgemm_body<12>(Q,  Bg1 + 5408, nullptr, h1s, 96,  200, 13, 200, 104, 1); break;
    case 4: mgemm_body<10>(Q,  Bl,         nullptr, Gv,  80,  200, 13, 300, 0,   1); break;
    case 5: mgemm_body<9> (Q,  Bl + 4160,  nullptr, Gv,  70,  200, 13, 300, 80,  1); break;
    case 6: mgemm_body<10>(P1, Bgl,        nullptr, Gv,  80,  200, 13, 300, 150, 1); break;
    default: mgemm_body<9>(P1, Bgl + 4160, nullptr, Gv,  70,  200, 13, 300, 230, 1); break;
    }
}

// MEGA3: x2=relu(tA@Wm2), xsn=tC@Wg2
__global__ __launch_bounds__(128, 4) void mega3_kernel(
    const float* __restrict__ tA, const float* __restrict__ tC,
    const uint4* __restrict__ Bm2, const uint4* __restrict__ Bg2,
    float* __restrict__ x2, float* __restrict__ xsn)
{
    switch (blockIdx.y) {
    case 0: mgemm_body<13>(tA, Bm2,        nullptr, x2,  104, 200, 13, 200, 0,   1); break;
    case 1: mgemm_body<12>(tA, Bm2 + 5408, nullptr, x2,  96,  200, 13, 200, 104, 1); break;
    case 2: mgemm_body<13>(tC, Bg2,        nullptr, xsn, 104, 200, 13, 200, 0,   0); break;
    default: mgemm_body<12>(tC, Bg2 + 5408, nullptr, xsn, 96, 200, 13, 200, 104, 0); break;
    }
}

// merged 3x (N=100, K=200), split 56+44, grid (480, 6)
__global__ __launch_bounds__(128, 4) void mgemm3_kernel(
    const float* __restrict__ A0, const float* __restrict__ A1, const float* __restrict__ A2,
    const uint4* __restrict__ B4, float* __restrict__ C)
{
    const int j = blockIdx.y >> 1, h = blockIdx.y & 1;
    const float* A = (j == 0) ? A0 : (j == 1) ? A1 : A2;
    const uint4* B = B4 + j * 5408;
    if (h == 0) mgemm_body<7>(A, B, nullptr, C, 56, 200, 13, 300, j * 100, 0);
    else        mgemm_body<6>(A, B + 7 * 13 * 32, nullptr, C, 44, 200, 13, 300, j * 100 + 56, 0);
}

// ---------------- batched small matmul body ----------------
__device__ __forceinline__ void bmm30_body(
    const float* __restrict__ Am, const float* __restrict__ X, float* __restrict__ Out,
    int batched, int b, int tid)
{
    __shared__ float As[NS * NS];
    __shared__ float Xs[NS * NFD];
    const float* A = batched ? (Am + (size_t)b * NS * NS) : Am;
    for (int i = tid; i < NS * NS; i += 256) As[i] = A[i];
    for (int i = tid; i < NS * NFD; i += 256) Xs[i] = X[(size_t)b * NS * NFD + i];
    __syncthreads();
    if (tid < 250) {
        int si = tid / 25, fi = tid - (tid / 25) * 25;
        int s0 = si * 3, f0 = fi * 8;
        float acc[3][8];
        #pragma unroll
        for (int r = 0; r < 3; r++)
            #pragma unroll
            for (int q = 0; q < 8; q++) acc[r][q] = 0.f;
        for (int j = 0; j < NS; j++) {
            float a0 = As[(s0 + 0) * NS + j];
            float a1 = As[(s0 + 1) * NS + j];
            float a2 = As[(s0 + 2) * NS + j];
            float4 xA = *reinterpret_cast<const float4*>(&Xs[j * NFD + f0]);
            float4 xB = *reinterpret_cast<const float4*>(&Xs[j * NFD + f0 + 4]);
            float xv[8] = {xA.x, xA.y, xA.z, xA.w, xB.x, xB.y, xB.z, xB.w};
            #pragma unroll
            for (int q = 0; q < 8; q++) {
                acc[0][q] += a0 * xv[q];
                acc[1][q] += a1 * xv[q];
                acc[2][q] += a2 * xv[q];
            }
        }
        #pragma unroll
        for (int r = 0; r < 3; r++)
            #pragma unroll
            for (int q = 0; q < 8; q++)
                Out[(size_t)b * NS * NFD + (s0 + r) * NFD + f0 + q] = acc[r][q];
    }
}

__global__ __launch_bounds__(256) void bmm30_kernel(
    const float* __restrict__ Am, const float* __restrict__ X, float* __restrict__ Out, int batched)
{
    bmm30_body(Am, X, Out, batched, blockIdx.x, threadIdx.x);
}

// merged tA = A_F@x1 (y=0) and tC = adj@h1s (y=1)
__global__ __launch_bounds__(256) void bmmM2_kernel(
    const float* __restrict__ AF, const float* __restrict__ adj,
    const float* __restrict__ x1, const float* __restrict__ h1s,
    float* __restrict__ tA, float* __restrict__ tC)
{
    if (blockIdx.y == 0) bmm30_body(AF, x1, tA, 1, blockIdx.x, threadIdx.x);
    else                 bmm30_body(adj, h1s, tC, 0, blockIdx.x, threadIdx.x);
}

// ---------------- fused A_F + P1 + Q: softmax(relu(tmp@F2^T)), P1=AF@F2, Q=adj@F2 ----------------
__global__ __launch_bounds__(256) void afpq_kernel(
    const float* __restrict__ Tm, const float* __restrict__ F2, const float* __restrict__ adj,
    float* __restrict__ AF, float* __restrict__ P1, float* __restrict__ Q)
{
    extern __shared__ float sm[];
    float* Ts  = sm;            // 6000 (reused as Ms after scores)
    float* Fs  = sm + 6000;     // 6000
    float* As  = sm + 12000;    // 900
    float* AFs = sm + 12900;    // 900
    const int b = blockIdx.x;
    const int tid = threadIdx.x;
    const size_t base = (size_t)b * 6000;
    for (int i = tid; i < 6000; i += 256) {
        Ts[i] = Tm[base + i];
        Fs[i] = F2[base + i];
    }
    for (int i = tid; i < 900; i += 256) As[i] = adj[i];
    __syncthreads();

    // scores: 3x3 tiles over (i,j), 100 active threads
    float acc[3][3];
    int ii = 0, jj = 0;
    if (tid < 100) {
        ii = (tid / 10) * 3; jj = (tid % 10) * 3;
        #pragma unroll
        for (int r = 0; r < 3; r++)
            #pragma unroll
            for (int c = 0; c < 3; c++) acc[r][c] = 0.f;
        for (int g = 0; g < NFD; g++) {
            float t0 = Ts[(ii + 0) * NFD + g], t1 = Ts[(ii + 1) * NFD + g], t2 = Ts[(ii + 2) * NFD + g];
            float f0 = Fs[(jj + 0) * NFD + g], f1 = Fs[(jj + 1) * NFD + g], f2 = Fs[(jj + 2) * NFD + g];
            acc[0][0] += t0 * f0; acc[0][1] += t0 * f1; acc[0][2] += t0 * f2;
            acc[1][0] += t1 * f0; acc[1][1] += t1 * f1; acc[1][2] += t1 * f2;
            acc[2][0] += t2 * f0; acc[2][1] += t2 * f1; acc[2][2] += t2 * f2;
        }
    }
    __syncthreads();
    float (*Ms)[31] = reinterpret_cast<float(*)[31]>(Ts);
    if (tid < 100) {
        #pragma unroll
        for (int r = 0; r < 3; r++)
            #pragma unroll
            for (int c = 0; c < 3; c++) Ms[ii + r][jj + c] = fmaxf(acc[r][c], 0.f);
    }
    __syncthreads();
    if (tid < NS) {
        float mx = -1e30f;
        for (int j = 0; j < NS; j++) mx = fmaxf(mx, Ms[tid][j]);
        float s = 0.f;
        for (int j = 0; j < NS; j++) s += expf(Ms[tid][j] - mx);
        float inv = 1.f / s;
        for (int j = 0; j < NS; j++) {
            float v = expf(Ms[tid][j] - mx) * inv;
            AFs[tid * NS + j] = v;
            AF[(size_t)b * NS * NS + tid * NS + j] = v;
        }
    }
    __syncthreads();

    // P1 = AFs @ Fs, Q = As @ Fs (shared xv loads)
    if (tid < 250) {
        int si = tid / 25, fi = tid - (tid / 25) * 25;
        int s0 = si * 3, f0 = fi * 8;
        float accP[3][8], accQ[3][8];
        #pragma unroll
        for (int r = 0; r < 3; r++)
            #pragma unroll
            for (int q = 0; q < 8; q++) { accP[r][q] = 0.f; accQ[r][q] = 0.f; }
        for (int j = 0; j < NS; j++) {
            float p0 = AFs[(s0 + 0) * NS + j];
            float p1 = AFs[(s0 + 1) * NS + j];
            float p2 = AFs[(s0 + 2) * NS + j];
            float a0 = As[(s0 + 0) * NS + j];
            float a1 = As[(s0 + 1) * NS + j];
            float a2 = As[(s0 + 2) * NS + j];
            float4 xA = *reinterpret_cast<const float4*>(&Fs[j * NFD + f0]);
            float4 xB = *reinterpret_cast<const float4*>(&Fs[j * NFD + f0 + 4]);
            float xv[8] = {xA.x, xA.y, xA.z, xA.w, xB.x, xB.y, xB.z, xB.w};
            #pragma unroll
            for (int q = 0; q < 8; q++) {
                accP[0][q] += p0 * xv[q];
                accP[1][q] += p1 * xv[q];
                accP[2][q] += p2 * xv[q];
                accQ[0][q] += a0 * xv[q];
                accQ[1][q] += a1 * xv[q];
                accQ[2][q] += a2 * xv[q];
            }
        }
        #pragma unroll
        for (int r = 0; r < 3; r++)
            #pragma unroll
            for (int q = 0; q < 8; q++) {
                P1[base + (s0 + r) * NFD + f0 + q] = accP[r][q];
                Q [base + (s0 + r) * NFD + f0 + q] = accQ[r][q];
            }
    }
}

// ---------------- fused gate + 3x bmm30(adj, g_k*H_k), xsn from gmem ----------------
__global__ __launch_bounds__(256) void gbmm_kernel(
    const float* __restrict__ adj, const float* __restrict__ x1, const float* __restrict__ x2,
    const float* __restrict__ x3, const float* __restrict__ xsn, const float* __restrict__ wg,
    float* __restrict__ o1, float* __restrict__ o2, float* __restrict__ o3)
{
    extern __shared__ float sm[];
    float* As = sm;
    float* X0 = sm + 900;
    float* X1 = sm + 6900;
    float* X2 = sm + 12900;
    const int b = blockIdx.x, tid = threadIdx.x;
    const size_t base = (size_t)b * 6000;
    for (int i = tid; i < 900; i += 256) As[i] = adj[i];
    for (int i = tid; i < 6000; i += 256) {
        X0[i] = x1[base + i];
        X1[i] = x2[base + i];
        X2[i] = x3[base + i];
    }
    __syncthreads();

    {
        const int warp = tid >> 5, lane = tid & 31;
        for (int rr = 0; rr < 4; rr++) {
            int r = warp * 4 + rr;
            if (r >= NS) break;
            float H0[7], H1[7], H2[7];
            float s0 = 0.f, s1 = 0.f, s2 = 0.f;
            #pragma unroll
            for (int q = 0; q < 7; q++) {
                int f = q * 32 + lane;
                float h0 = 0.f, h1 = 0.f, h2 = 0.f;
                if (f < NFD) {
                    float sv = xsn[base + r * NFD + f];
                    h0 = (X0[r * NFD + f] + sv) * 0.5f;
                    h1 = (X1[r * NFD + f] + sv) * 0.5f;
                    h2 = (X2[r * NFD + f] + sv) * 0.5f;
                    s0 += h0 * wg[f * 3 + 0];
                    s1 += h1 * wg[f * 3 + 1];
                    s2 += h2 * wg[f * 3 + 2];
                }
                H0[q] = h0; H1[q] = h1; H2[q] = h2;
            }
            #pragma unroll
            for (int o = 16; o; o >>= 1) {
                s0 += __shfl_xor_sync(0xffffffffu, s0, o);
                s1 += __shfl_xor_sync(0xffffffffu, s1, o);
                s2 += __shfl_xor_sync(0xffffffffu, s2, o);
            }
            float mx = fmaxf(s0, fmaxf(s1, s2));
            float e0 = expf(s0 - mx), e1 = expf(s1 - mx), e2 = expf(s2 - mx);
            float inv = 1.f / (e0 + e1 + e2);
            e0 *= inv; e1 *= inv; e2 *= inv;
            #pragma unroll
            for (int q = 0; q < 7; q++) {
                int f = q * 32 + lane;
                if (f < NFD) {
                    X0[r * NFD + f] = e0 * H0[q];
                    X1[r * NFD + f] = e1 * H1[q];
                    X2[r * NFD + f] = e2 * H2[q];
                }
            }
        }
    }
    __syncthreads();

    if (tid < 250) {
        int si = tid / 25, fi = tid - (tid / 25) * 25;
        int s0 = si * 3, f0 = fi * 8;
        float* Xk[3] = {X0, X1, X2};
        float* Ok[3] = {o1, o2, o3};
        #pragma unroll
        for (int k = 0; k < 3; k++) {
            const float* X = Xk[k];
            float acc[3][8];
            #pragma unroll
            for (int r = 0; r < 3; r++)
                #pragma unroll
                for (int q = 0; q < 8; q++) acc[r][q] = 0.f;
            for (int j = 0; j < NS; j++) {
                float a0 = As[(s0 + 0) * NS + j];
                float a1 = As[(s0 + 1) * NS + j];
                float a2 = As[(s0 + 2) * NS + j];
                float4 xA = *reinterpret_cast<const float4*>(&X[j * NFD + f0]);
                float4 xB = *reinterpret_cast<const float4*>(&X[j * NFD + f0 + 4]);
                float xv[8] = {xA.x, xA.y, xA.z, xA.w, xB.x, xB.y, xB.z, xB.w};
                #pragma unroll
                for (int q = 0; q < 8; q++) {
                    acc[0][q] += a0 * xv[q];
                    acc[1][q] += a1 * xv[q];
                    acc[2][q] += a2 * xv[q];
                }
            }
            #pragma unroll
            for (int r = 0; r < 3; r++)
                #pragma unroll
                for (int q = 0; q < 8; q++)
                    Ok[k][base + (s0 + r) * NFD + f0 + q] = acc[r][q];
        }
    }
}

// ---------------- SE blocks ----------------
__global__ __launch_bounds__(128) void se1_kernel(
    const float* __restrict__ Gv, const float* __restrict__ Ws1,
    const float* __restrict__ Ws2, float* __restrict__ wch)
{
    const int warp = threadIdx.x >> 5, lane = threadIdx.x & 31;
    const int b = blockIdx.x * 4 + warp;
    __shared__ float mvs[4][NS];
    __shared__ float avs[4][15];
    float* mv = mvs[warp];
    float* av = avs[warp];
    for (int s = 0; s < NS; s++) {
        float p = 0.f;
        for (int j = lane; j < 300; j += 32) p += Gv[(size_t)b * 9000 + s * 300 + j];
        #pragma unroll
        for (int o = 16; o; o >>= 1) p += __shfl_xor_sync(0xffffffffu, p, o);
        if (lane == 0) mv[s] = p * (1.f / 300.f);
    }
    __syncwarp();
    if (lane < 15) {
        float a = 0.f;
        for (int s = 0; s < NS; s++) a += mv[s] * Ws1[s * 15 + lane];
        av[lane] = fmaxf(a, 0.f);
    }
    __syncwarp();
    if (lane < NS) {
        float a = 0.f;
        for (int h = 0; h < 15; h++) a += av[h] * Ws2[h * NS + lane];
        wch[b * NS + lane] = 1.f / (1.f + expf(-a));
    }
}

__global__ __launch_bounds__(320) void se2_kernel(const float* __restrict__ Gh,
                                                  const float* __restrict__ Wf1,
                                                  const float* __restrict__ Wf2,
                                                  float* __restrict__ wft)
{
    __shared__ float m[4][300];
    __shared__ float t1[4][152];
    const int b0 = blockIdx.x * 4, tid = threadIdx.x;
    if (tid < 300) {
        #pragma unroll
        for (int bb = 0; bb < 4; bb++) {
            float a = 0.f;
            for (int s = 0; s < NS; s++) a += Gh[(size_t)(b0 + bb) * 9000 + s * 300 + tid];
            m[bb][tid] = a * (1.f / 30.f);
        }
    }
    __syncthreads();
    if (tid < 150) {
        float a[4] = {0.f, 0.f, 0.f, 0.f};
        for (int j = 0; j < 300; j++) {
            float w = Wf1[j * 150 + tid];
            #pragma unroll
            for (int bb = 0; bb < 4; bb++) a[bb] += m[bb][j] * w;
        }
        #pragma unroll
        for (int bb = 0; bb < 4; bb++) t1[bb][tid] = fmaxf(a[bb], 0.f);
    }
    __syncthreads();
    if (tid < 300) {
        float a[4] = {0.f, 0.f, 0.f, 0.f};
        for (int h = 0; h < 150; h++) {
            float w = Wf2[h * 300 + tid];
            #pragma unroll
            for (int bb = 0; bb < 4; bb++) a[bb] += t1[bb][h] * w;
        }
        #pragma unroll
        for (int bb = 0; bb < 4; bb++)
            wft[(size_t)(b0 + bb) * 300 + tid] = 1.f / (1.f + expf(-a[bb]));
    }
}

// ---------------- classifier + log_softmax ----------------
__global__ __launch_bounds__(256) void cls_kernel(
    const float* __restrict__ Gh, const float* __restrict__ Gv,
    const float* __restrict__ wch, const float* __restrict__ wft,
    const float* __restrict__ Wcls, const float* __restrict__ bcls, float* __restrict__ out)
{
    const int b0 = blockIdx.x * 4, tid = threadIdx.x;
    const int lane = tid & 31, warp = tid >> 5;
    float acc[4][NCL];
    #pragma unroll
    for (int bb = 0; bb < 4; bb++)
        #pragma unroll
        for (int k = 0; k < NCL; k++) acc[bb][k] = 0.f;

    for (int idx = tid; idx < 18000; idx += 256) {
        int s = idx / 600;
        int c = idx - s * 600;
        float w[NCL];
        #pragma unroll
        for (int k = 0; k < NCL; k++) w[k] = Wcls[(size_t)idx * NCL + k];
        #pragma unroll
        for (int bb = 0; bb < 4; bb++) {
            int b = b0 + bb;
            float val;
            if (c < 300) val = Gh[(size_t)b * 9000 + s * 300 + c] * wch[b * NS + s];
            else {
                int cc = c - 300;
                val = Gv[(size_t)b * 9000 + s * 300 + cc] * wft[(size_t)b * 300 + cc];
            }
            #pragma unroll
            for (int k = 0; k < NCL; k++) acc[bb][k] += val * w[k];
        }
    }
    #pragma unroll
    for (int bb = 0; bb < 4; bb++)
        #pragma unroll
        for (int k = 0; k < NCL; k++)
            #pragma unroll
            for (int o = 16; o; o >>= 1)
                acc[bb][k] += __shfl_xor_sync(0xffffffffu, acc[bb][k], o);
    __shared__ float red[8][4][NCL];
    __shared__ float zs[4][NCL];
    if (lane == 0) {
        #pragma unroll
        for (int bb = 0; bb < 4; bb++)
            #pragma unroll
            for (int k = 0; k < NCL; k++) red[warp][bb][k] = acc[bb][k];
    }
    __syncthreads();
    if (tid < 28) {
        int bb = tid / 7, k = tid - bb * 7;
        float z = bcls[k];
        #pragma unroll
        for (int w2 = 0; w2 < 8; w2++) z += red[w2][bb][k];
        zs[bb][k] = z;
    }
    __syncthreads();
    if (tid < 4) {
        float mx = -1e30f;
        #pragma unroll
        for (int k = 0; k < NCL; k++) mx = fmaxf(mx, zs[tid][k]);
        float s = 0.f;
        #pragma unroll
        for (int k = 0; k < NCL; k++) s += expf(zs[tid][k] - mx);
        float ls = logf(s);
        #pragma unroll
        for (int k = 0; k < NCL; k++) out[(b0 + tid) * NCL + k] = zs[tid][k] - mx - ls;
    }
}

// ---------------- launch ----------------
extern "C" void kernel_launch(void* const* d_in, const int* in_sizes, int n_in,
                              void* d_out, int out_size)
{
    const float* x    = (const float*)d_in[0];
    const float* adj  = (const float*)d_in[1];
    const float* Wc1  = (const float*)d_in[2];
    const float* bc1  = (const float*)d_in[3];
    const float* Wc2  = (const float*)d_in[4];
    const float* bc2  = (const float*)d_in[5];
    const float* Wt   = (const float*)d_in[6];
    const float* bt   = (const float*)d_in[7];
    const float* Wa   = (const float*)d_in[8];
    const float* Wm1  = (const float*)d_in[9];
    const float* Wm2  = (const float*)d_in[10];
    const float* Wm3  = (const float*)d_in[11];
    const float* Wg1  = (const float*)d_in[12];
    const float* Wg2  = (const float*)d_in[13];
    const float* wg   = (const float*)d_in[14];
    const float* Wp1  = (const float*)d_in[15];
    const float* Wp2  = (const float*)d_in[16];
    const float* Wp3  = (const float*)d_in[17];
    const float* Wl   = (const float*)d_in[18];
    const float* Wgl  = (const float*)d_in[19];
    const float* Ws1  = (const float*)d_in[20];
    const float* Ws2  = (const float*)d_in[21];
    const float* Wf1  = (const float*)d_in[22];
    const float* Wf2  = (const float*)d_in[23];
    const float* Wcls = (const float*)d_in[24];
    const float* bcls = (const float*)d_in[25];
    float* out = (float*)d_out;

    float *p_h2, *p_F2, *p_tmp, *p_tmp2, *p_P1, *p_x1, *p_x2, *p_x3, *p_Q, *p_h1s, *p_xsn;
    float *p_gH1, *p_gH2, *p_gH3, *p_AF, *p_Gh, *p_Gv, *p_wch, *p_wft;
    uint4 *p_b4, *p_cw1, *p_cw2;
    cudaGetSymbolAddress((void**)&p_h2,   g_h2);
    cudaGetSymbolAddress((void**)&p_F2,   g_F2);
    cudaGetSymbolAddress((void**)&p_tmp,  g_tmp);
    cudaGetSymbolAddress((void**)&p_tmp2, g_tmp2);
    cudaGetSymbolAddress((void**)&p_P1,   g_P1);
    cudaGetSymbolAddress((void**)&p_x1,   g_x1);
    cudaGetSymbolAddress((void**)&p_x2,   g_x2);
    cudaGetSymbolAddress((void**)&p_x3,   g_x3);
    cudaGetSymbolAddress((void**)&p_Q,    g_Q);
    cudaGetSymbolAddress((void**)&p_h1s,  g_h1s);
    cudaGetSymbolAddress((void**)&p_xsn,  g_xsn);
    cudaGetSymbolAddress((void**)&p_gH1,  g_gH1);
    cudaGetSymbolAddress((void**)&p_gH2,  g_gH2);
    cudaGetSymbolAddress((void**)&p_gH3,  g_gH3);
    cudaGetSymbolAddress((void**)&p_AF,   g_AF);
    cudaGetSymbolAddress((void**)&p_Gh,   g_Gh);
    cudaGetSymbolAddress((void**)&p_Gv,   g_Gv);
    cudaGetSymbolAddress((void**)&p_wch,  g_wch);
    cudaGetSymbolAddress((void**)&p_wft,  g_wft);
    cudaGetSymbolAddress((void**)&p_b4,   g_bf4);
    cudaGetSymbolAddress((void**)&p_cw1,  g_cw1);
    cudaGetSymbolAddress((void**)&p_cw2,  g_cw2);

    // fragment pool offsets (uint4 units)
    const int oWt  = 0;
    const int oWa  = 51200;
    const int oWm1 = 61600, oWm2 = 72000, oWm3 = 82400;
    const int oWg1 = 92800, oWg2 = 103200;
    const int oWp1 = 113600, oWp2 = 119008, oWp3 = 124416;
    const int oWl  = 129824, oWgl = 137728;

    PJobs J;
    const float* Ws[12] = {Wt, Wa, Wm1, Wm2, Wm3, Wg1, Wg2, Wp1, Wp2, Wp3, Wl, Wgl};
    const int   Ks[12] = {1024, 200, 200, 200, 200, 200, 200, 200, 200, 200, 200, 200};
    const int   Nn[12] = {200, 200, 200, 200, 200, 200, 200, 100, 100, 100, 150, 150};
    const int   Tt[12] = {25, 25, 25, 25, 25, 25, 25, 13, 13, 13, 19, 19};
    const int   Kk[12] = {64, 13, 13, 13, 13, 13, 13, 13, 13, 13, 13, 13};
    const int   Of[12] = {oWt, oWa, oWm1, oWm2, oWm3, oWg1, oWg2, oWp1, oWp2, oWp3, oWl, oWgl};
    for (int i = 0; i < 12; i++) {
        J.W[i] = Ws[i]; J.K[i] = Ks[i]; J.N[i] = Nn[i];
        J.nT[i] = Tt[i]; J.nks[i] = Kk[i]; J.off[i] = Of[i];
    }

    const int GBMM_SMEM = 18900 * 4;   // 75.6 KB -> 2 CTAs/SM
    const int AFPQ_SMEM = 13800 * 4;   // 55.2 KB
    cudaFuncSetAttribute(gbmm_kernel, cudaFuncAttributeMaxDynamicSharedMemorySize, GBMM_SMEM);
    cudaFuncSetAttribute(afpq_kernel, cudaFuncAttributeMaxDynamicSharedMemorySize, AFPQ_SMEM);

    prepall_kernel<<<dim3(200, 12), 256>>>(J, p_b4);
    prepcw_kernel<<<dim3(3, 2), 256>>>(Wc1, Wc2, p_cw1, p_cw2);

    const int GM = MROWS / 64;   // 480 CTAs
    dim3 gS(GM, 2);

    // CNN feature extractor
    convf_kernel<<<dim3(16, BATCH), 128>>>(x, p_cw1, bc1, p_cw2, bc2, p_h2);
    mgemmS_kernel<<<gS, 128>>>(p_h2, p_b4+oWt, bt, p_F2, 1024, 64, 200, 1);

    // learned adjacency scores
    mgemmS_kernel<<<gS, 128>>>(p_F2, p_b4+oWa, nullptr, p_tmp, 200, 13, 200, 0);

    // fused: A_F softmax + P1 = A_F@F2 + Q = adj@F2
    afpq_kernel<<<BATCH, 256, AFPQ_SMEM>>>(p_tmp, p_F2, adj, p_AF, p_P1, p_Q);

    // MEGA1: x1, h1s, and both LGFM halves of G_v
    mega1_kernel<<<dim3(GM, 8), 128>>>(p_P1, p_Q, p_b4+oWm1, p_b4+oWg1, p_b4+oWl, p_b4+oWgl,
                                       p_x1, p_h1s, p_Gv);

    // se1 only needs G_v
    se1_kernel<<<BATCH / 4, 128>>>(p_Gv, Ws1, Ws2, p_wch);

    // MEGA2: tA = A_F@x1, tC = adj@h1s
    bmmM2_kernel<<<dim3(BATCH, 2), 256>>>(p_AF, adj, p_x1, p_h1s, p_tmp, p_tmp2);

    // MEGA3: x2 = relu(tA@Wm2), xsn = tC@Wg2
    mega3_kernel<<<dim3(GM, 4), 128>>>(p_tmp, p_tmp2, p_b4+oWm2, p_b4+oWg2, p_x2, p_xsn);

    // x3 chain
    bmm30_kernel<<<BATCH, 256>>>(p_AF, p_x2, p_tmp, 1);
    mgemmS_kernel<<<gS, 128>>>(p_tmp, p_b4+oWm3, nullptr, p_x3, 200, 13, 200, 1);

    // fused gate + adj-aggregation
    gbmm_kernel<<<BATCH, 256, GBMM_SMEM>>>(adj, p_x1, p_x2, p_x3, p_xsn, wg, p_gH1, p_gH2, p_gH3);

    // G_h: 3 projections (merged, N-split)
    mgemm3_kernel<<<dim3(GM, 6), 128>>>(p_gH1, p_gH2, p_gH3, p_b4+oWp1, p_Gh);

    // se2 + classifier
    se2_kernel<<<BATCH / 4, 320>>>(p_Gh, Wf1, Wf2, p_wft);
    cls_kernel<<<BATCH / 4, 256>>>(p_Gh, p_Gv, p_wch, p_wft, Wcls, bcls, out);
}

// round 14
// speedup vs baseline: 1.3802x; 1.0045x over previous
#include <cuda_runtime.h>
#include <cuda_bf16.h>
#include <cstdint>
#include <cstdio>

#define BATCH 1024
#define NS    30
#define NT    1024
#define NFD   200
#define NCL   7
#define MROWS (BATCH*NS)      // 30720

static inline int cdiv(int a, int b) { return (a + b - 1) / b; }

// ---------------- scratch (device globals; no allocation) ----------------
__device__ float g_h2  [BATCH*NS*NT];
__device__ float g_F2  [MROWS*NFD];
__device__ float g_tmp [MROWS*NFD];
__device__ float g_tmp2[MROWS*NFD];
__device__ float g_P1  [MROWS*NFD];
__device__ float g_x1  [MROWS*NFD];
__device__ float g_x2  [MROWS*NFD];
__device__ float g_x3  [MROWS*NFD];
__device__ float g_Q   [MROWS*NFD];
__device__ float g_h1s [MROWS*NFD];
__device__ float g_xsn [MROWS*NFD];
__device__ float g_gH1 [MROWS*NFD];
__device__ float g_gH2 [MROWS*NFD];
__device__ float g_gH3 [MROWS*NFD];
__device__ float g_AF  [BATCH*NS*NS];
__device__ float g_Gh  [MROWS*300];
__device__ float g_Gv  [MROWS*300];
__device__ float g_wch [MROWS];
__device__ float g_wft [BATCH*300];

// packed weight fragments: uint4 = {hi_r0, hi_r1, lo_r0, lo_r1}
__device__ uint4 g_bf4[150000];
__device__ uint4 g_cw1[768];
__device__ uint4 g_cw2[768];

// ---------------- mma + split helpers ----------------
__device__ __forceinline__ void mma16816(float* c, uint32_t a0, uint32_t a1, uint32_t a2, uint32_t a3,
                                         uint32_t b0, uint32_t b1) {
    asm volatile("mma.sync.aligned.m16n8k16.row.col.f32.bf16.bf16.f32 "
        "{%0,%1,%2,%3}, {%4,%5,%6,%7}, {%8,%9}, {%0,%1,%2,%3};"
        : "+f"(c[0]), "+f"(c[1]), "+f"(c[2]), "+f"(c[3])
        : "r"(a0), "r"(a1), "r"(a2), "r"(a3), "r"(b0), "r"(b1));
}
__device__ __forceinline__ void split2(float2 v, uint32_t& hi, uint32_t& lo) {
    __nv_bfloat162 h = __floats2bfloat162_rn(v.x, v.y);
    float2 hf = __bfloat1622float2(h);
    __nv_bfloat162 l = __floats2bfloat162_rn(v.x - hf.x, v.y - hf.y);
    hi = reinterpret_cast<uint32_t&>(h);
    lo = reinterpret_cast<uint32_t&>(l);
}

// ---------------- merged weight prep ----------------
struct PJobs {
    const float* W[12];
    int K[12], N[12], nT[12], nks[12], off[12];
};
__global__ void prepall_kernel(PJobs J, uint4* __restrict__ out)
{
    const int j = blockIdx.y;
    const int idx = blockIdx.x * 256 + threadIdx.x;
    const int nks = J.nks[j];
    const int total = J.nT[j] * nks * 32;
    if (idx >= total) return;
    const int K = J.K[j], N = J.N[j];
    const float* W = J.W[j];
    int lane = idx & 31;
    int s = idx >> 5;
    int ks = s % nks;
    int t  = s / nks;
    int n = t * 8 + (lane >> 2);
    float v[4];
    #pragma unroll
    for (int reg = 0; reg < 2; reg++) {
        #pragma unroll
        for (int jj = 0; jj < 2; jj++) {
            int k = ks * 16 + (lane & 3) * 2 + reg * 8 + jj;
            v[reg * 2 + jj] = (n < N && k < K) ? W[(size_t)k * N + n] : 0.f;
        }
    }
    uint32_t h0, l0, h1, l1;
    split2(make_float2(v[0], v[1]), h0, l0);
    split2(make_float2(v[2], v[3]), h1, l1);
    out[J.off[j] + idx] = make_uint4(h0, h1, l0, l1);
}

// ---------------- conv weight prep (both layers, grid.y selects) ----------------
__global__ void prepcw_kernel(const float* __restrict__ W1, const float* __restrict__ W2,
                              uint4* __restrict__ out1, uint4* __restrict__ out2)
{
    int idx = blockIdx.x * 256 + threadIdx.x;
    if (idx >= 768) return;
    const float* W = blockIdx.y ? W2 : W1;
    uint4* out = blockIdx.y ? out2 : out1;
    int lane = idx & 31;
    int ks = (idx >> 5) % 6;
    int t  = idx / 192;
    int n = t * 8 + (lane >> 2);
    float v[4];
    #pragma unroll
    for (int reg = 0; reg < 2; reg++) {
        #pragma unroll
        for (int jj = 0; jj < 2; jj++) {
            int kidx = ks * 16 + (lane & 3) * 2 + reg * 8 + jj;
            int kk = kidx >> 5, i = kidx & 31;
            float w = 0.f;
            if (n < 30 && i < 30) w = W[(n * 30 + i) * 3 + kk];
            v[reg * 2 + jj] = w;
        }
    }
    uint32_t h0, l0, h1, l1;
    split2(make_float2(v[0], v[1]), h0, l0);
    split2(make_float2(v[2], v[3]), h1, l1);
    out[idx] = make_uint4(h0, h1, l0, l1);
}

// ---------------- fused conv (round-8 proven) ----------------
__device__ __forceinline__ float ldx(const float* __restrict__ xb, int r, int kidx)
{
    int i = kidx & 31, kk = kidx >> 5;
    int ts = r + kk - 1;
    return (i < NS && ts >= 0 && ts < NT) ? xb[i * NT + ts] : 0.f;
}
__device__ __forceinline__ void conv_l1_group(
    const float* __restrict__ xb, const uint4* __restrict__ Wf, const float* __restrict__ bc1,
    uint2 (*h1s)[16], int t0, int g, int tlo, int thi, int lane)
{
    const int gq = lane >> 2, kq = (lane & 3) * 2;
    const int r0 = t0 - 8 + g * 16 + gq, r1 = r0 + 8;
    float acc[4][4];
    #pragma unroll
    for (int t = 0; t < 4; t++) { acc[t][0] = 0.f; acc[t][1] = 0.f; acc[t][2] = 0.f; acc[t][3] = 0.f; }
    for (int ks = 0; ks < 6; ks++) {
        int kb = ks * 16 + kq;
        float v00 = ldx(xb, r0, kb),     v01 = ldx(xb, r0, kb + 1);
        float v10 = ldx(xb, r1, kb),     v11 = ldx(xb, r1, kb + 1);
        float v02 = ldx(xb, r0, kb + 8), v03 = ldx(xb, r0, kb + 9);
        float v12 = ldx(xb, r1, kb + 8), v13 = ldx(xb, r1, kb + 9);
        uint32_t ah0, al0, ah1, al1, ah2, al2, ah3, al3;
        split2(make_float2(v00, v01), ah0, al0);
        split2(make_float2(v10, v11), ah1, al1);
        split2(make_float2(v02, v03), ah2, al2);
        split2(make_float2(v12, v13), ah3, al3);
        const uint4* bp = Wf + ks * 32 + lane;
        #pragma unroll
        for (int t = 0; t < 4; t++) {
            if (t < tlo || t >= thi) continue;
            uint4 w = bp[t * 192];
            mma16816(acc[t], ah0, ah1, ah2, ah3, w.x, w.y);
            mma16816(acc[t], ah0, ah1, ah2, ah3, w.z, w.w);
            mma16816(acc[t], al0, al1, al2, al3, w.x, w.y);
        }
    }
    const int sr0 = g * 16 + gq, sr1 = sr0 + 8;
    #pragma unroll
    for (int t = 0; t < 4; t++) {
        if (t < tlo || t >= thi) continue;
        int n0 = t * 8 + kq;
        float bb0 = (n0 < 30) ? bc1[n0] : 0.f;
        float bb1 = (n0 + 1 < 30) ? bc1[n0 + 1] : 0.f;
        float v0 = fmaxf(acc[t][0] + bb0, 0.f), v1 = fmaxf(acc[t][1] + bb1, 0.f);
        float v2 = fmaxf(acc[t][2] + bb0, 0.f), v3 = fmaxf(acc[t][3] + bb1, 0.f);
        uint32_t h, l;
        split2(make_float2(v0, v1), h, l);
        h1s[sr0][t * 4 + (kq >> 1)] = make_uint2(h, l);
        split2(make_float2(v2, v3), h, l);
        h1s[sr1][t * 4 + (kq >> 1)] = make_uint2(h, l);
    }
}

__global__ __launch_bounds__(128) void convf_kernel(
    const float* __restrict__ x, const uint4* __restrict__ Wf1, const float* __restrict__ bc1,
    const uint4* __restrict__ Wf2, const float* __restrict__ bc2, float* __restrict__ out)
{
    __shared__ uint2 h1s[80][16];
    const int b = blockIdx.y;
    const int t0 = blockIdx.x * 64;
    const int lane = threadIdx.x & 31, warp = threadIdx.x >> 5;
    const float* xb = x + (size_t)b * NS * NT;

    conv_l1_group(xb, Wf1, bc1, h1s, t0, warp, 0, 4, lane);
    if (warp < 2) conv_l1_group(xb, Wf1, bc1, h1s, t0, 4, warp * 2, warp * 2 + 2, lane);
    __syncthreads();

    const int gq = lane >> 2, kq = (lane & 3) * 2;
    const int r0 = t0 + warp * 16 + gq, r1 = r0 + 8;
    float acc[4][4];
    #pragma unroll
    for (int t = 0; t < 4; t++) { acc[t][0] = 0.f; acc[t][1] = 0.f; acc[t][2] = 0.f; acc[t][3] = 0.f; }
    for (int ks = 0; ks < 6; ks++) {
        int kb = ks * 16 + kq;
        int kk = kb >> 5;
        int i  = kb & 31;
        int ts0 = r0 + kk - 1, ts1 = r1 + kk - 1;
        int s0 = ts0 - (t0 - 8), s1 = ts1 - (t0 - 8);
        uint2 z = make_uint2(0u, 0u);
        uint2 p00 = (ts0 >= 0 && ts0 < NT) ? h1s[s0][i >> 1]       : z;
        uint2 p01 = (ts0 >= 0 && ts0 < NT) ? h1s[s0][(i + 8) >> 1] : z;
        uint2 p10 = (ts1 >= 0 && ts1 < NT) ? h1s[s1][i >> 1]       : z;
        uint2 p11 = (ts1 >= 0 && ts1 < NT) ? h1s[s1][(i + 8) >> 1] : z;
        const uint4* bp = Wf2 + ks * 32 + lane;
        #pragma unroll
        for (int t = 0; t < 4; t++) {
            uint4 w = bp[t * 192];
            mma16816(acc[t], p00.x, p10.x, p01.x, p11.x, w.x, w.y);
            mma16816(acc[t], p00.x, p10.x, p01.x, p11.x, w.z, w.w);
            mma16816(acc[t], p00.y, p10.y, p01.y, p11.y, w.x, w.y);
        }
    }
    #pragma unroll
    for (int t = 0; t < 4; t++) {
        int n0 = t * 8 + kq;
        if (n0 < 30) {
            float bb = bc2[n0];
            out[((size_t)b * NS + n0) * NT + r0] = fmaxf(acc[t][0] + bb, 0.f);
            out[((size_t)b * NS + n0) * NT + r1] = fmaxf(acc[t][2] + bb, 0.f);
        }
        if (n0 + 1 < 30) {
            float bb = bc2[n0 + 1];
            out[((size_t)b * NS + n0 + 1) * NT + r0] = fmaxf(acc[t][1] + bb, 0.f);
            out[((size_t)b * NS + n0 + 1) * NT + r1] = fmaxf(acc[t][3] + bb, 0.f);
        }
    }
}

// ---------------- HMMA split-bf16 GEMM body (generic) ----------------
template<int NTl>
__device__ __forceinline__ void mgemm_body(
    const float* __restrict__ A, const uint4* __restrict__ B4,
    const float* __restrict__ bias, float* __restrict__ C,
    int N, int K, int nks, int ldc, int coloff, int relu)
{
    const int lane = threadIdx.x & 31;
    const int warp = threadIdx.x >> 5;
    const int gq = lane >> 2;
    const int q  = lane & 3;
    const int r0 = blockIdx.x * 64 + warp * 16 + gq;
    const int r1 = r0 + 8;
    const int kq = q * 2;

    float acc[NTl][4];
    #pragma unroll
    for (int t = 0; t < NTl; t++) {
        acc[t][0] = 0.f; acc[t][1] = 0.f; acc[t][2] = 0.f; acc[t][3] = 0.f;
    }

    const float* a0p = A + (size_t)r0 * K;
    const float* a1p = A + (size_t)r1 * K;

    for (int ks = 0; ks < nks; ks++) {
        const int kb = ks * 16 + kq;
        float2 x00 = (kb     < K) ? *reinterpret_cast<const float2*>(a0p + kb)     : make_float2(0.f, 0.f);
        float2 x01 = (kb + 8 < K) ? *reinterpret_cast<const float2*>(a0p + kb + 8) : make_float2(0.f, 0.f);
        float2 x10 = (kb     < K) ? *reinterpret_cast<const float2*>(a1p + kb)     : make_float2(0.f, 0.f);
        float2 x11 = (kb + 8 < K) ? *reinterpret_cast<const float2*>(a1p + kb + 8) : make_float2(0.f, 0.f);
        uint32_t ah0, al0, ah1, al1, ah2, al2, ah3, al3;
        split2(x00, ah0, al0);
        split2(x10, ah1, al1);
        split2(x01, ah2, al2);
        split2(x11, ah3, al3);
        const uint4* bp = B4 + ks * 32 + lane;
        const int stride = nks * 32;
        #pragma unroll
        for (int t = 0; t < NTl; t++) {
            uint4 w = bp[(size_t)t * stride];
            mma16816(acc[t], ah0, ah1, ah2, ah3, w.x, w.y);
            mma16816(acc[t], ah0, ah1, ah2, ah3, w.z, w.w);
            mma16816(acc[t], al0, al1, al2, al3, w.x, w.y);
        }
    }

    #pragma unroll
    for (int t = 0; t < NTl; t++) {
        int n0 = t * 8 + kq;
        if (n0 < N) {
            float b0v = bias ? bias[n0] : 0.f;
            float b1v = bias ? bias[n0 + 1] : 0.f;
            float v0 = acc[t][0] + b0v, v1 = acc[t][1] + b1v;
            float v2 = acc[t][2] + b0v, v3 = acc[t][3] + b1v;
            if (relu) {
                v0 = fmaxf(v0, 0.f); v1 = fmaxf(v1, 0.f);
                v2 = fmaxf(v2, 0.f); v3 = fmaxf(v3, 0.f);
            }
            *reinterpret_cast<float2*>(&C[(size_t)r0 * ldc + coloff + n0]) = make_float2(v0, v1);
            *reinterpret_cast<float2*>(&C[(size_t)r1 * ldc + coloff + n0]) = make_float2(v2, v3);
        }
    }
}

// ---------------- dedicated F2 GEMM: K=1024 compile-time, prefetch double-buffer ----------------
template<int NTl>
__device__ __forceinline__ void f2_body(
    const float* __restrict__ A, const uint4* __restrict__ B4,
    const float* __restrict__ bias, float* __restrict__ C, int coloff)
{
    constexpr int K = 1024, nks = 64;
    const int lane = threadIdx.x & 31;
    const int warp = threadIdx.x >> 5;
    const int gq = lane >> 2;
    const int kq = (lane & 3) * 2;
    const int r0 = blockIdx.x * 64 + warp * 16 + gq;
    const int r1 = r0 + 8;

    float acc[NTl][4];
    #pragma unroll
    for (int t = 0; t < NTl; t++) {
        acc[t][0] = 0.f; acc[t][1] = 0.f; acc[t][2] = 0.f; acc[t][3] = 0.f;
    }

    const float* a0p = A + (size_t)r0 * K + kq;
    const float* a1p = A + (size_t)r1 * K + kq;

    float2 c0 = *reinterpret_cast<const float2*>(a0p);
    float2 c1 = *reinterpret_cast<const float2*>(a0p + 8);
    float2 c2 = *reinterpret_cast<const float2*>(a1p);
    float2 c3 = *reinterpret_cast<const float2*>(a1p + 8);

    for (int ks = 0; ks < nks; ks++) {
        float2 n0, n1, n2, n3;
        if (ks < nks - 1) {
            const int kb = (ks + 1) * 16;
            n0 = *reinterpret_cast<const float2*>(a0p + kb);
            n1 = *reinterpret_cast<const float2*>(a0p + kb + 8);
            n2 = *reinterpret_cast<const float2*>(a1p + kb);
            n3 = *reinterpret_cast<const float2*>(a1p + kb + 8);
        }
        uint32_t ah0, al0, ah1, al1, ah2, al2, ah3, al3;
        split2(c0, ah0, al0);
        split2(c2, ah1, al1);
        split2(c1, ah2, al2);
        split2(c3, ah3, al3);
        const uint4* bp = B4 + ks * 32 + lane;
        #pragma unroll
        for (int t = 0; t < NTl; t++) {
            uint4 w = bp[t * (nks * 32)];
            mma16816(acc[t], ah0, ah1, ah2, ah3, w.x, w.y);
            mma16816(acc[t], ah0, ah1, ah2, ah3, w.z, w.w);
            mma16816(acc[t], al0, al1, al2, al3, w.x, w.y);
        }
        c0 = n0; c1 = n1; c2 = n2; c3 = n3;
    }

    #pragma unroll
    for (int t = 0; t < NTl; t++) {
        int n0 = t * 8 + kq;
        float b0v = bias[n0], b1v = bias[n0 + 1];
        float v0 = fmaxf(acc[t][0] + b0v, 0.f), v1 = fmaxf(acc[t][1] + b1v, 0.f);
        float v2 = fmaxf(acc[t][2] + b0v, 0.f), v3 = fmaxf(acc[t][3] + b1v, 0.f);
        *reinterpret_cast<float2*>(&C[(size_t)r0 * 200 + coloff + n0]) = make_float2(v0, v1);
        *reinterpret_cast<float2*>(&C[(size_t)r1 * 200 + coloff + n0]) = make_float2(v2, v3);
    }
}

__global__ __launch_bounds__(128, 4) void f2gemm_kernel(
    const float* __restrict__ A, const uint4* __restrict__ B4,
    const float* __restrict__ bias, float* __restrict__ C)
{
    if (blockIdx.y == 0)
        f2_body<13>(A, B4, bias, C, 0);
    else
        f2_body<12>(A, B4 + 13 * 64 * 32, bias + 104, C, 104);
}

// N-split GEMM (200 cols -> 104 + 96), grid (480, 2)
__global__ __launch_bounds__(128, 4) void mgemmS_kernel(
    const float* __restrict__ A, const uint4* __restrict__ B4,
    const float* __restrict__ bias, float* __restrict__ C,
    int K, int nks, int ldc, int relu)
{
    if (blockIdx.y == 0)
        mgemm_body<13>(A, B4, bias, C, 104, K, nks, ldc, 0, relu);
    else
        mgemm_body<12>(A, B4 + 13 * nks * 32, bias ? bias + 104 : nullptr, C, 96, K, nks, ldc, 104, relu);
}

// MEGA1: x1=relu(P1@Wm1), h1s=relu(Q@Wg1), Gv[:,0:150]=relu(Q@Wl), Gv[:,150:300]=relu(P1@Wgl)
__global__ __launch_bounds__(128, 4) void mega1_kernel(
    const float* __restrict__ P1, const float* __restrict__ Q,
    const uint4* __restrict__ Bm1, const uint4* __restrict__ Bg1,
    const uint4* __restrict__ Bl, const uint4* __restrict__ Bgl,
    float* __restrict__ x1, float* __restrict__ h1s, float* __restrict__ Gv)
{
    switch (blockIdx.y) {
    case 0: mgemm_body<13>(P1, Bm1,        nullptr, x1,  104, 200, 13, 200, 0,   1); break;
    case 1: mgemm_body<12>(P1, Bm1 + 5408, nullptr, x1,  96,  200, 13, 200, 104, 1); break;
    case 2: mgemm_body<13>(Q,  Bg1,        nullptr, h1s, 104, 200, 13, 200, 0,   1); break;
    case 3: mgemm_body<12>(Q,  Bg1 + 5408, nullptr, h1s, 96,  200, 13, 200, 104, 1); break;
    case 4: mgemm_body<10>(Q,  Bl,         nullptr, Gv,  80,  200, 13, 300, 0,   1); break;
    case 5: mgemm_body<9> (Q,  Bl + 4160,  nullptr, Gv,  70,  200, 13, 300, 80,  1); break;
    case 6: mgemm_body<10>(P1, Bgl,        nullptr, Gv,  80,  200, 13, 300, 150, 1); break;
    default: mgemm_body<9>(P1, Bgl + 4160, nullptr, Gv,  70,  200, 13, 300, 230, 1); break;
    }
}

// MEGA3: x2=relu(tA@Wm2), xsn=tC@Wg2
__global__ __launch_bounds__(128, 4) void mega3_kernel(
    const float* __restrict__ tA, const float* __restrict__ tC,
    const uint4* __restrict__ Bm2, const uint4* __restrict__ Bg2,
    float* __restrict__ x2, float* __restrict__ xsn)
{
    switch (blockIdx.y) {
    case 0: mgemm_body<13>(tA, Bm2,        nullptr, x2,  104, 200, 13, 200, 0,   1); break;
    case 1: mgemm_body<12>(tA, Bm2 + 5408, nullptr, x2,  96,  200, 13, 200, 104, 1); break;
    case 2: mgemm_body<13>(tC, Bg2,        nullptr, xsn, 104, 200, 13, 200, 0,   0); break;
    default: mgemm_body<12>(tC, Bg2 + 5408, nullptr, xsn, 96, 200, 13, 200, 104, 0); break;
    }
}

// merged 3x (N=100, K=200), split 56+44, grid (480, 6)
__global__ __launch_bounds__(128, 4) void mgemm3_kernel(
    const float* __restrict__ A0, const float* __restrict__ A1, const float* __restrict__ A2,
    const uint4* __restrict__ B4, float* __restrict__ C)
{
    const int j = blockIdx.y >> 1, h = blockIdx.y & 1;
    const float* A = (j == 0) ? A0 : (j == 1) ? A1 : A2;
    const uint4* B = B4 + j * 5408;
    if (h == 0) mgemm_body<7>(A, B, nullptr, C, 56, 200, 13, 300, j * 100, 0);
    else        mgemm_body<6>(A, B + 7 * 13 * 32, nullptr, C, 44, 200, 13, 300, j * 100 + 56, 0);
}

// ---------------- batched small matmul body ----------------
__device__ __forceinline__ void bmm30_body(
    const float* __restrict__ Am, const float* __restrict__ X, float* __restrict__ Out,
    int batched, int b, int tid)
{
    __shared__ float As[NS * NS];
    __shared__ float Xs[NS * NFD];
    const float* A = batched ? (Am + (size_t)b * NS * NS) : Am;
    for (int i = tid; i < NS * NS; i += 256) As[i] = A[i];
    for (int i = tid; i < NS * NFD; i += 256) Xs[i] = X[(size_t)b * NS * NFD + i];
    __syncthreads();
    if (tid < 250) {
        int si = tid / 25, fi = tid - (tid / 25) * 25;
        int s0 = si * 3, f0 = fi * 8;
        float acc[3][8];
        #pragma unroll
        for (int r = 0; r < 3; r++)
            #pragma unroll
            for (int q = 0; q < 8; q++) acc[r][q] = 0.f;
        for (int j = 0; j < NS; j++) {
            float a0 = As[(s0 + 0) * NS + j];
            float a1 = As[(s0 + 1) * NS + j];
            float a2 = As[(s0 + 2) * NS + j];
            float4 xA = *reinterpret_cast<const float4*>(&Xs[j * NFD + f0]);
            float4 xB = *reinterpret_cast<const float4*>(&Xs[j * NFD + f0 + 4]);
            float xv[8] = {xA.x, xA.y, xA.z, xA.w, xB.x, xB.y, xB.z, xB.w};
            #pragma unroll
            for (int q = 0; q < 8; q++) {
                acc[0][q] += a0 * xv[q];
                acc[1][q] += a1 * xv[q];
                acc[2][q] += a2 * xv[q];
            }
        }
        #pragma unroll
        for (int r = 0; r < 3; r++)
            #pragma unroll
            for (int q = 0; q < 8; q++)
                Out[(size_t)b * NS * NFD + (s0 + r) * NFD + f0 + q] = acc[r][q];
    }
}

__global__ __launch_bounds__(256) void bmm30_kernel(
    const float* __restrict__ Am, const float* __restrict__ X, float* __restrict__ Out, int batched)
{
    bmm30_body(Am, X, Out, batched, blockIdx.x, threadIdx.x);
}

// merged tA = A_F@x1 (y=0) and tC = adj@h1s (y=1)
__global__ __launch_bounds__(256) void bmmM2_kernel(
    const float* __restrict__ AF, const float* __restrict__ adj,
    const float* __restrict__ x1, const float* __restrict__ h1s,
    float* __restrict__ tA, float* __restrict__ tC)
{
    if (blockIdx.y == 0) bmm30_body(AF, x1, tA, 1, blockIdx.x, threadIdx.x);
    else                 bmm30_body(adj, h1s, tC, 0, blockIdx.x, threadIdx.x);
}

// ---------------- fused A_F + P1 + Q ----------------
__global__ __launch_bounds__(256) void afpq_kernel(
    const float* __restrict__ Tm, const float* __restrict__ F2, const float* __restrict__ adj,
    float* __restrict__ AF, float* __restrict__ P1, float* __restrict__ Q)
{
    extern __shared__ float sm[];
    float* Ts  = sm;
    float* Fs  = sm + 6000;
    float* As  = sm + 12000;
    float* AFs = sm + 12900;
    const int b = blockIdx.x;
    const int tid = threadIdx.x;
    const size_t base = (size_t)b * 6000;
    for (int i = tid; i < 6000; i += 256) {
        Ts[i] = Tm[base + i];
        Fs[i] = F2[base + i];
    }
    for (int i = tid; i < 900; i += 256) As[i] = adj[i];
    __syncthreads();

    float acc[3][3];
    int ii = 0, jj = 0;
    if (tid < 100) {
        ii = (tid / 10) * 3; jj = (tid % 10) * 3;
        #pragma unroll
        for (int r = 0; r < 3; r++)
            #pragma unroll
            for (int c = 0; c < 3; c++) acc[r][c] = 0.f;
        for (int g = 0; g < NFD; g++) {
            float t0 = Ts[(ii + 0) * NFD + g], t1 = Ts[(ii + 1) * NFD + g], t2 = Ts[(ii + 2) * NFD + g];
            float f0 = Fs[(jj + 0) * NFD + g], f1 = Fs[(jj + 1) * NFD + g], f2 = Fs[(jj + 2) * NFD + g];
            acc[0][0] += t0 * f0; acc[0][1] += t0 * f1; acc[0][2] += t0 * f2;
            acc[1][0] += t1 * f0; acc[1][1] += t1 * f1; acc[1][2] += t1 * f2;
            acc[2][0] += t2 * f0; acc[2][1] += t2 * f1; acc[2][2] += t2 * f2;
        }
    }
    __syncthreads();
    float (*Ms)[31] = reinterpret_cast<float(*)[31]>(Ts);
    if (tid < 100) {
        #pragma unroll
        for (int r = 0; r < 3; r++)
            #pragma unroll
            for (int c = 0; c < 3; c++) Ms[ii + r][jj + c] = fmaxf(acc[r][c], 0.f);
    }
    __syncthreads();
    if (tid < NS) {
        float mx = -1e30f;
        for (int j = 0; j < NS; j++) mx = fmaxf(mx, Ms[tid][j]);
        float s = 0.f;
        for (int j = 0; j < NS; j++) s += expf(Ms[tid][j] - mx);
        float inv = 1.f / s;
        for (int j = 0; j < NS; j++) {
            float v = expf(Ms[tid][j] - mx) * inv;
            AFs[tid * NS + j] = v;
            AF[(size_t)b * NS * NS + tid * NS + j] = v;
        }
    }
    __syncthreads();

    if (tid < 250) {
        int si = tid / 25, fi = tid - (tid / 25) * 25;
        int s0 = si * 3, f0 = fi * 8;
        float accP[3][8], accQ[3][8];
        #pragma unroll
        for (int r = 0; r < 3; r++)
            #pragma unroll
            for (int q = 0; q < 8; q++) { accP[r][q] = 0.f; accQ[r][q] = 0.f; }
        for (int j = 0; j < NS; j++) {
            float p0 = AFs[(s0 + 0) * NS + j];
            float p1 = AFs[(s0 + 1) * NS + j];
            float p2 = AFs[(s0 + 2) * NS + j];
            float a0 = As[(s0 + 0) * NS + j];
            float a1 = As[(s0 + 1) * NS + j];
            float a2 = As[(s0 + 2) * NS + j];
            float4 xA = *reinterpret_cast<const float4*>(&Fs[j * NFD + f0]);
            float4 xB = *reinterpret_cast<const float4*>(&Fs[j * NFD + f0 + 4]);
            float xv[8] = {xA.x, xA.y, xA.z, xA.w, xB.x, xB.y, xB.z, xB.w};
            #pragma unroll
            for (int q = 0; q < 8; q++) {
                accP[0][q] += p0 * xv[q];
                accP[1][q] += p1 * xv[q];
                accP[2][q] += p2 * xv[q];
                accQ[0][q] += a0 * xv[q];
                accQ[1][q] += a1 * xv[q];
                accQ[2][q] += a2 * xv[q];
            }
        }
        #pragma unroll
        for (int r = 0; r < 3; r++)
            #pragma unroll
            for (int q = 0; q < 8; q++) {
                P1[base + (s0 + r) * NFD + f0 + q] = accP[r][q];
                Q [base + (s0 + r) * NFD + f0 + q] = accQ[r][q];
            }
    }
}

// ---------------- fused gate + 3x bmm30(adj, g_k*H_k), xsn from gmem ----------------
__global__ __launch_bounds__(256) void gbmm_kernel(
    const float* __restrict__ adj, const float* __restrict__ x1, const float* __restrict__ x2,
    const float* __restrict__ x3, const float* __restrict__ xsn, const float* __restrict__ wg,
    float* __restrict__ o1, float* __restrict__ o2, float* __restrict__ o3)
{
    extern __shared__ float sm[];
    float* As = sm;
    float* X0 = sm + 900;
    float* X1 = sm + 6900;
    float* X2 = sm + 12900;
    const int b = blockIdx.x, tid = threadIdx.x;
    const size_t base = (size_t)b * 6000;
    for (int i = tid; i < 900; i += 256) As[i] = adj[i];
    for (int i = tid; i < 6000; i += 256) {
        X0[i] = x1[base + i];
        X1[i] = x2[base + i];
        X2[i] = x3[base + i];
    }
    __syncthreads();

    {
        const int warp = tid >> 5, lane = tid & 31;
        for (int rr = 0; rr < 4; rr++) {
            int r = warp * 4 + rr;
            if (r >= NS) break;
            float H0[7], H1[7], H2[7];
            float s0 = 0.f, s1 = 0.f, s2 = 0.f;
            #pragma unroll
            for (int q = 0; q < 7; q++) {
                int f = q * 32 + lane;
                float h0 = 0.f, h1 = 0.f, h2 = 0.f;
                if (f < NFD) {
                    float sv = xsn[base + r * NFD + f];
                    h0 = (X0[r * NFD + f] + sv) * 0.5f;
                    h1 = (X1[r * NFD + f] + sv) * 0.5f;
                    h2 = (X2[r * NFD + f] + sv) * 0.5f;
                    s0 += h0 * wg[f * 3 + 0];
                    s1 += h1 * wg[f * 3 + 1];
                    s2 += h2 * wg[f * 3 + 2];
                }
                H0[q] = h0; H1[q] = h1; H2[q] = h2;
            }
            #pragma unroll
            for (int o = 16; o; o >>= 1) {
                s0 += __shfl_xor_sync(0xffffffffu, s0, o);
                s1 += __shfl_xor_sync(0xffffffffu, s1, o);
                s2 += __shfl_xor_sync(0xffffffffu, s2, o);
            }
            float mx = fmaxf(s0, fmaxf(s1, s2));
            float e0 = expf(s0 - mx), e1 = expf(s1 - mx), e2 = expf(s2 - mx);
            float inv = 1.f / (e0 + e1 + e2);
            e0 *= inv; e1 *= inv; e2 *= inv;
            #pragma unroll
            for (int q = 0; q < 7; q++) {
                int f = q * 32 + lane;
                if (f < NFD) {
                    X0[r * NFD + f] = e0 * H0[q];
                    X1[r * NFD + f] = e1 * H1[q];
                    X2[r * NFD + f] = e2 * H2[q];
                }
            }
        }
    }
    __syncthreads();

    if (tid < 250) {
        int si = tid / 25, fi = tid - (tid / 25) * 25;
        int s0 = si * 3, f0 = fi * 8;
        float* Xk[3] = {X0, X1, X2};
        float* Ok[3] = {o1, o2, o3};
        #pragma unroll
        for (int k = 0; k < 3; k++) {
            const float* X = Xk[k];
            float acc[3][8];
            #pragma unroll
            for (int r = 0; r < 3; r++)
                #pragma unroll
                for (int q = 0; q < 8; q++) acc[r][q] = 0.f;
            for (int j = 0; j < NS; j++) {
                float a0 = As[(s0 + 0) * NS + j];
                float a1 = As[(s0 + 1) * NS + j];
                float a2 = As[(s0 + 2) * NS + j];
                float4 xA = *reinterpret_cast<const float4*>(&X[j * NFD + f0]);
                float4 xB = *reinterpret_cast<const float4*>(&X[j * NFD + f0 + 4]);
                float xv[8] = {xA.x, xA.y, xA.z, xA.w, xB.x, xB.y, xB.z, xB.w};
                #pragma unroll
                for (int q = 0; q < 8; q++) {
                    acc[0][q] += a0 * xv[q];
                    acc[1][q] += a1 * xv[q];
                    acc[2][q] += a2 * xv[q];
                }
            }
            #pragma unroll
            for (int r = 0; r < 3; r++)
                #pragma unroll
                for (int q = 0; q < 8; q++)
                    Ok[k][base + (s0 + r) * NFD + f0 + q] = acc[r][q];
        }
    }
}

// ---------------- SE blocks ----------------
__global__ __launch_bounds__(128) void se1_kernel(
    const float* __restrict__ Gv, const float* __restrict__ Ws1,
    const float* __restrict__ Ws2, float* __restrict__ wch)
{
    const int warp = threadIdx.x >> 5, lane = threadIdx.x & 31;
    const int b = blockIdx.x * 4 + warp;
    __shared__ float mvs[4][NS];
    __shared__ float avs[4][15];
    float* mv = mvs[warp];
    float* av = avs[warp];
    for (int s = 0; s < NS; s++) {
        float p = 0.f;
        for (int j = lane; j < 300; j += 32) p += Gv[(size_t)b * 9000 + s * 300 + j];
        #pragma unroll
        for (int o = 16; o; o >>= 1) p += __shfl_xor_sync(0xffffffffu, p, o);
        if (lane == 0) mv[s] = p * (1.f / 300.f);
    }
    __syncwarp();
    if (lane < 15) {
        float a = 0.f;
        for (int s = 0; s < NS; s++) a += mv[s] * Ws1[s * 15 + lane];
        av[lane] = fmaxf(a, 0.f);
    }
    __syncwarp();
    if (lane < NS) {
        float a = 0.f;
        for (int h = 0; h < 15; h++) a += av[h] * Ws2[h * NS + lane];
        wch[b * NS + lane] = 1.f / (1.f + expf(-a));
    }
}

__global__ __launch_bounds__(320) void se2_kernel(const float* __restrict__ Gh,
                                                  const float* __restrict__ Wf1,
                                                  const float* __restrict__ Wf2,
                                                  float* __restrict__ wft)
{
    __shared__ float m[4][300];
    __shared__ float t1[4][152];
    const int b0 = blockIdx.x * 4, tid = threadIdx.x;
    if (tid < 300) {
        #pragma unroll
        for (int bb = 0; bb < 4; bb++) {
            float a = 0.f;
            for (int s = 0; s < NS; s++) a += Gh[(size_t)(b0 + bb) * 9000 + s * 300 + tid];
            m[bb][tid] = a * (1.f / 30.f);
        }
    }
    __syncthreads();
    if (tid < 150) {
        float a[4] = {0.f, 0.f, 0.f, 0.f};
        for (int j = 0; j < 300; j++) {
            float w = Wf1[j * 150 + tid];
            #pragma unroll
            for (int bb = 0; bb < 4; bb++) a[bb] += m[bb][j] * w;
        }
        #pragma unroll
        for (int bb = 0; bb < 4; bb++) t1[bb][tid] = fmaxf(a[bb], 0.f);
    }
    __syncthreads();
    if (tid < 300) {
        float a[4] = {0.f, 0.f, 0.f, 0.f};
        for (int h = 0; h < 150; h++) {
            float w = Wf2[h * 300 + tid];
            #pragma unroll
            for (int bb = 0; bb < 4; bb++) a[bb] += t1[bb][h] * w;
        }
        #pragma unroll
        for (int bb = 0; bb < 4; bb++)
            wft[(size_t)(b0 + bb) * 300 + tid] = 1.f / (1.f + expf(-a[bb]));
    }
}

// ---------------- classifier + log_softmax ----------------
__global__ __launch_bounds__(256) void cls_kernel(
    const float* __restrict__ Gh, const float* __restrict__ Gv,
    const float* __restrict__ wch, const float* __restrict__ wft,
    const float* __restrict__ Wcls, const float* __restrict__ bcls, float* __restrict__ out)
{
    const int b0 = blockIdx.x * 4, tid = threadIdx.x;
    const int lane = tid & 31, warp = tid >> 5;
    float acc[4][NCL];
    #pragma unroll
    for (int bb = 0; bb < 4; bb++)
        #pragma unroll
        for (int k = 0; k < NCL; k++) acc[bb][k] = 0.f;

    for (int idx = tid; idx < 18000; idx += 256) {
        int s = idx / 600;
        int c = idx - s * 600;
        float w[NCL];
        #pragma unroll
        for (int k = 0; k < NCL; k++) w[k] = Wcls[(size_t)idx * NCL + k];
        #pragma unroll
        for (int bb = 0; bb < 4; bb++) {
            int b = b0 + bb;
            float val;
            if (c < 300) val = Gh[(size_t)b * 9000 + s * 300 + c] * wch[b * NS + s];
            else {
                int cc = c - 300;
                val = Gv[(size_t)b * 9000 + s * 300 + cc] * wft[(size_t)b * 300 + cc];
            }
            #pragma unroll
            for (int k = 0; k < NCL; k++) acc[bb][k] += val * w[k];
        }
    }
    #pragma unroll
    for (int bb = 0; bb < 4; bb++)
        #pragma unroll
        for (int k = 0; k < NCL; k++)
            #pragma unroll
            for (int o = 16; o; o >>= 1)
                acc[bb][k] += __shfl_xor_sync(0xffffffffu, acc[bb][k], o);
    __shared__ float red[8][4][NCL];
    __shared__ float zs[4][NCL];
    if (lane == 0) {
        #pragma unroll
        for (int bb = 0; bb < 4; bb++)
            #pragma unroll
            for (int k = 0; k < NCL; k++) red[warp][bb][k] = acc[bb][k];
    }
    __syncthreads();
    if (tid < 28) {
        int bb = tid / 7, k = tid - bb * 7;
        float z = bcls[k];
        #pragma unroll
        for (int w2 = 0; w2 < 8; w2++) z += red[w2][bb][k];
        zs[bb][k] = z;
    }
    __syncthreads();
    if (tid < 4) {
        float mx = -1e30f;
        #pragma unroll
        for (int k = 0; k < NCL; k++) mx = fmaxf(mx, zs[tid][k]);
        float s = 0.f;
        #pragma unroll
        for (int k = 0; k < NCL; k++) s += expf(zs[tid][k] - mx);
        float ls = logf(s);
        #pragma unroll
        for (int k = 0; k < NCL; k++) out[(b0 + tid) * NCL + k] = zs[tid][k] - mx - ls;
    }
}

// ---------------- launch ----------------
extern "C" void kernel_launch(void* const* d_in, const int* in_sizes, int n_in,
                              void* d_out, int out_size)
{
    const float* x    = (const float*)d_in[0];
    const float* adj  = (const float*)d_in[1];
    const float* Wc1  = (const float*)d_in[2];
    const float* bc1  = (const float*)d_in[3];
    const float* Wc2  = (const float*)d_in[4];
    const float* bc2  = (const float*)d_in[5];
    const float* Wt   = (const float*)d_in[6];
    const float* bt   = (const float*)d_in[7];
    const float* Wa   = (const float*)d_in[8];
    const float* Wm1  = (const float*)d_in[9];
    const float* Wm2  = (const float*)d_in[10];
    const float* Wm3  = (const float*)d_in[11];
    const float* Wg1  = (const float*)d_in[12];
    const float* Wg2  = (const float*)d_in[13];
    const float* wg   = (const float*)d_in[14];
    const float* Wp1  = (const float*)d_in[15];
    const float* Wp2  = (const float*)d_in[16];
    const float* Wp3  = (const float*)d_in[17];
    const float* Wl   = (const float*)d_in[18];
    const float* Wgl  = (const float*)d_in[19];
    const float* Ws1  = (const float*)d_in[20];
    const float* Ws2  = (const float*)d_in[21];
    const float* Wf1  = (const float*)d_in[22];
    const float* Wf2  = (const float*)d_in[23];
    const float* Wcls = (const float*)d_in[24];
    const float* bcls = (const float*)d_in[25];
    float* out = (float*)d_out;

    float *p_h2, *p_F2, *p_tmp, *p_tmp2, *p_P1, *p_x1, *p_x2, *p_x3, *p_Q, *p_h1s, *p_xsn;
    float *p_gH1, *p_gH2, *p_gH3, *p_AF, *p_Gh, *p_Gv, *p_wch, *p_wft;
    uint4 *p_b4, *p_cw1, *p_cw2;
    cudaGetSymbolAddress((void**)&p_h2,   g_h2);
    cudaGetSymbolAddress((void**)&p_F2,   g_F2);
    cudaGetSymbolAddress((void**)&p_tmp,  g_tmp);
    cudaGetSymbolAddress((void**)&p_tmp2, g_tmp2);
    cudaGetSymbolAddress((void**)&p_P1,   g_P1);
    cudaGetSymbolAddress((void**)&p_x1,   g_x1);
    cudaGetSymbolAddress((void**)&p_x2,   g_x2);
    cudaGetSymbolAddress((void**)&p_x3,   g_x3);
    cudaGetSymbolAddress((void**)&p_Q,    g_Q);
    cudaGetSymbolAddress((void**)&p_h1s,  g_h1s);
    cudaGetSymbolAddress((void**)&p_xsn,  g_xsn);
    cudaGetSymbolAddress((void**)&p_gH1,  g_gH1);
    cudaGetSymbolAddress((void**)&p_gH2,  g_gH2);
    cudaGetSymbolAddress((void**)&p_gH3,  g_gH3);
    cudaGetSymbolAddress((void**)&p_AF,   g_AF);
    cudaGetSymbolAddress((void**)&p_Gh,   g_Gh);
    cudaGetSymbolAddress((void**)&p_Gv,   g_Gv);
    cudaGetSymbolAddress((void**)&p_wch,  g_wch);
    cudaGetSymbolAddress((void**)&p_wft,  g_wft);
    cudaGetSymbolAddress((void**)&p_b4,   g_bf4);
    cudaGetSymbolAddress((void**)&p_cw1,  g_cw1);
    cudaGetSymbolAddress((void**)&p_cw2,  g_cw2);

    // fragment pool offsets (uint4 units)
    const int oWt  = 0;
    const int oWa  = 51200;
    const int oWm1 = 61600, oWm2 = 72000, oWm3 = 82400;
    const int oWg1 = 92800, oWg2 = 103200;
    const int oWp1 = 113600, oWp2 = 119008, oWp3 = 124416;
    const int oWl  = 129824, oWgl = 137728;

    PJobs J;
    const float* Ws[12] = {Wt, Wa, Wm1, Wm2, Wm3, Wg1, Wg2, Wp1, Wp2, Wp3, Wl, Wgl};
    const int   Ks[12] = {1024, 200, 200, 200, 200, 200, 200, 200, 200, 200, 200, 200};
    const int   Nn[12] = {200, 200, 200, 200, 200, 200, 200, 100, 100, 100, 150, 150};
    const int   Tt[12] = {25, 25, 25, 25, 25, 25, 25, 13, 13, 13, 19, 19};
    const int   Kk[12] = {64, 13, 13, 13, 13, 13, 13, 13, 13, 13, 13, 13};
    const int   Of[12] = {oWt, oWa, oWm1, oWm2, oWm3, oWg1, oWg2, oWp1, oWp2, oWp3, oWl, oWgl};
    for (int i = 0; i < 12; i++) {
        J.W[i] = Ws[i]; J.K[i] = Ks[i]; J.N[i] = Nn[i];
        J.nT[i] = Tt[i]; J.nks[i] = Kk[i]; J.off[i] = Of[i];
    }

    const int GBMM_SMEM = 18900 * 4;   // 75.6 KB -> 2 CTAs/SM
    const int AFPQ_SMEM = 13800 * 4;   // 55.2 KB
    cudaFuncSetAttribute(gbmm_kernel, cudaFuncAttributeMaxDynamicSharedMemorySize, GBMM_SMEM);
    cudaFuncSetAttribute(afpq_kernel, cudaFuncAttributeMaxDynamicSharedMemorySize, AFPQ_SMEM);

    prepall_kernel<<<dim3(200, 12), 256>>>(J, p_b4);
    prepcw_kernel<<<dim3(3, 2), 256>>>(Wc1, Wc2, p_cw1, p_cw2);

    const int GM = MROWS / 64;   // 480 CTAs
    dim3 gS(GM, 2);

    // CNN feature extractor
    convf_kernel<<<dim3(16, BATCH), 128>>>(x, p_cw1, bc1, p_cw2, bc2, p_h2);
    // F2 projection: dedicated prefetch kernel, K=1024 compile-time
    f2gemm_kernel<<<gS, 128>>>(p_h2, p_b4+oWt, bt, p_F2);

    // learned adjacency scores
    mgemmS_kernel<<<gS, 128>>>(p_F2, p_b4+oWa, nullptr, p_tmp, 200, 13, 200, 0);

    // fused: A_F softmax + P1 = A_F@F2 + Q = adj@F2
    afpq_kernel<<<BATCH, 256, AFPQ_SMEM>>>(p_tmp, p_F2, adj, p_AF, p_P1, p_Q);

    // MEGA1: x1, h1s, and both LGFM halves of G_v
    mega1_kernel<<<dim3(GM, 8), 128>>>(p_P1, p_Q, p_b4+oWm1, p_b4+oWg1, p_b4+oWl, p_b4+oWgl,
                                       p_x1, p_h1s, p_Gv);

    // se1 only needs G_v
    se1_kernel<<<BATCH / 4, 128>>>(p_Gv, Ws1, Ws2, p_wch);

    // MEGA2: tA = A_F@x1, tC = adj@h1s
    bmmM2_kernel<<<dim3(BATCH, 2), 256>>>(p_AF, adj, p_x1, p_h1s, p_tmp, p_tmp2);

    // MEGA3: x2 = relu(tA@Wm2), xsn = tC@Wg2
    mega3_kernel<<<dim3(GM, 4), 128>>>(p_tmp, p_tmp2, p_b4+oWm2, p_b4+oWg2, p_x2, p_xsn);

    // x3 chain
    bmm30_kernel<<<BATCH, 256>>>(p_AF, p_x2, p_tmp, 1);
    mgemmS_kernel<<<gS, 128>>>(p_tmp, p_b4+oWm3, nullptr, p_x3, 200, 13, 200, 1);

    // fused gate + adj-aggregation
    gbmm_kernel<<<BATCH, 256, GBMM_SMEM>>>(adj, p_x1, p_x2, p_x3, p_xsn, wg, p_gH1, p_gH2, p_gH3);

    // G_h: 3 projections (merged, N-split)
    mgemm3_kernel<<<dim3(GM, 6), 128>>>(p_gH1, p_gH2, p_gH3, p_b4+oWp1, p_Gh);

    // se2 + classifier
    se2_kernel<<<BATCH / 4, 320>>>(p_Gh, Wf1, Wf2, p_wft);
    cls_kernel<<<BATCH / 4, 256>>>(p_Gh, p_Gv, p_wch, p_wft, Wcls, bcls, out);
}

// round 15
// speedup vs baseline: 1.3803x; 1.0001x over previous
#include <cuda_runtime.h>
#include <cuda_bf16.h>
#include <cstdint>
#include <cstdio>

#define BATCH 1024
#define NS    30
#define NT    1024
#define NFD   200
#define NCL   7
#define MROWS (BATCH*NS)      // 30720

static inline int cdiv(int a, int b) { return (a + b - 1) / b; }

// ---------------- scratch (device globals; no allocation) ----------------
__device__ float g_h2  [BATCH*NS*NT];
__device__ float g_F2  [MROWS*NFD];
__device__ float g_tmp [MROWS*NFD];
__device__ float g_tmp2[MROWS*NFD];
__device__ float g_P1  [MROWS*NFD];
__device__ float g_x1  [MROWS*NFD];
__device__ float g_x2  [MROWS*NFD];
__device__ float g_x3  [MROWS*NFD];
__device__ float g_Q   [MROWS*NFD];
__device__ float g_h1s [MROWS*NFD];
__device__ float g_xsn [MROWS*NFD];
__device__ float g_gH1 [MROWS*NFD];
__device__ float g_gH2 [MROWS*NFD];
__device__ float g_gH3 [MROWS*NFD];
__device__ float g_AF  [BATCH*NS*NS];
__device__ float g_Gh  [MROWS*300];
__device__ float g_Gv  [MROWS*300];
__device__ float g_wch [MROWS];
__device__ float g_wft [BATCH*300];

// packed weight fragments: uint4 = {hi_r0, hi_r1, lo_r0, lo_r1}
__device__ uint4 g_bf4[150000];
__device__ uint4 g_cw1[768];
__device__ uint4 g_cw2[768];

// ---------------- mma + split helpers ----------------
__device__ __forceinline__ void mma16816(float* c, uint32_t a0, uint32_t a1, uint32_t a2, uint32_t a3,
                                         uint32_t b0, uint32_t b1) {
    asm volatile("mma.sync.aligned.m16n8k16.row.col.f32.bf16.bf16.f32 "
        "{%0,%1,%2,%3}, {%4,%5,%6,%7}, {%8,%9}, {%0,%1,%2,%3};"
        : "+f"(c[0]), "+f"(c[1]), "+f"(c[2]), "+f"(c[3])
        : "r"(a0), "r"(a1), "r"(a2), "r"(a3), "r"(b0), "r"(b1));
}
__device__ __forceinline__ void split2(float2 v, uint32_t& hi, uint32_t& lo) {
    __nv_bfloat162 h = __floats2bfloat162_rn(v.x, v.y);
    float2 hf = __bfloat1622float2(h);
    __nv_bfloat162 l = __floats2bfloat162_rn(v.x - hf.x, v.y - hf.y);
    hi = reinterpret_cast<uint32_t&>(h);
    lo = reinterpret_cast<uint32_t&>(l);
}

// ---------------- merged weight prep ----------------
struct PJobs {
    const float* W[12];
    int K[12], N[12], nT[12], nks[12], off[12];
};
__global__ void prepall_kernel(PJobs J, uint4* __restrict__ out)
{
    const int j = blockIdx.y;
    const int idx = blockIdx.x * 256 + threadIdx.x;
    const int nks = J.nks[j];
    const int total = J.nT[j] * nks * 32;
    if (idx >= total) return;
    const int K = J.K[j], N = J.N[j];
    const float* W = J.W[j];
    int lane = idx & 31;
    int s = idx >> 5;
    int ks = s % nks;
    int t  = s / nks;
    int n = t * 8 + (lane >> 2);
    float v[4];
    #pragma unroll
    for (int reg = 0; reg < 2; reg++) {
        #pragma unroll
        for (int jj = 0; jj < 2; jj++) {
            int k = ks * 16 + (lane & 3) * 2 + reg * 8 + jj;
            v[reg * 2 + jj] = (n < N && k < K) ? W[(size_t)k * N + n] : 0.f;
        }
    }
    uint32_t h0, l0, h1, l1;
    split2(make_float2(v[0], v[1]), h0, l0);
    split2(make_float2(v[2], v[3]), h1, l1);
    out[J.off[j] + idx] = make_uint4(h0, h1, l0, l1);
}

// ---------------- conv weight prep (both layers, grid.y selects) ----------------
__global__ void prepcw_kernel(const float* __restrict__ W1, const float* __restrict__ W2,
                              uint4* __restrict__ out1, uint4* __restrict__ out2)
{
    int idx = blockIdx.x * 256 + threadIdx.x;
    if (idx >= 768) return;
    const float* W = blockIdx.y ? W2 : W1;
    uint4* out = blockIdx.y ? out2 : out1;
    int lane = idx & 31;
    int ks = (idx >> 5) % 6;
    int t  = idx / 192;
    int n = t * 8 + (lane >> 2);
    float v[4];
    #pragma unroll
    for (int reg = 0; reg < 2; reg++) {
        #pragma unroll
        for (int jj = 0; jj < 2; jj++) {
            int kidx = ks * 16 + (lane & 3) * 2 + reg * 8 + jj;
            int kk = kidx >> 5, i = kidx & 31;
            float w = 0.f;
            if (n < 30 && i < 30) w = W[(n * 30 + i) * 3 + kk];
            v[reg * 2 + jj] = w;
        }
    }
    uint32_t h0, l0, h1, l1;
    split2(make_float2(v[0], v[1]), h0, l0);
    split2(make_float2(v[2], v[3]), h1, l1);
    out[idx] = make_uint4(h0, h1, l0, l1);
}

// ---------------- fused conv (round-8 proven) ----------------
__device__ __forceinline__ float ldx(const float* __restrict__ xb, int r, int kidx)
{
    int i = kidx & 31, kk = kidx >> 5;
    int ts = r + kk - 1;
    return (i < NS && ts >= 0 && ts < NT) ? xb[i * NT + ts] : 0.f;
}
__device__ __forceinline__ void conv_l1_group(
    const float* __restrict__ xb, const uint4* __restrict__ Wf, const float* __restrict__ bc1,
    uint2 (*h1s)[16], int t0, int g, int tlo, int thi, int lane)
{
    const int gq = lane >> 2, kq = (lane & 3) * 2;
    const int r0 = t0 - 8 + g * 16 + gq, r1 = r0 + 8;
    float acc[4][4];
    #pragma unroll
    for (int t = 0; t < 4; t++) { acc[t][0] = 0.f; acc[t][1] = 0.f; acc[t][2] = 0.f; acc[t][3] = 0.f; }
    for (int ks = 0; ks < 6; ks++) {
        int kb = ks * 16 + kq;
        float v00 = ldx(xb, r0, kb),     v01 = ldx(xb, r0, kb + 1);
        float v10 = ldx(xb, r1, kb),     v11 = ldx(xb, r1, kb + 1);
        float v02 = ldx(xb, r0, kb + 8), v03 = ldx(xb, r0, kb + 9);
        float v12 = ldx(xb, r1, kb + 8), v13 = ldx(xb, r1, kb + 9);
        uint32_t ah0, al0, ah1, al1, ah2, al2, ah3, al3;
        split2(make_float2(v00, v01), ah0, al0);
        split2(make_float2(v10, v11), ah1, al1);
        split2(make_float2(v02, v03), ah2, al2);
        split2(make_float2(v12, v13), ah3, al3);
        const uint4* bp = Wf + ks * 32 + lane;
        #pragma unroll
        for (int t = 0; t < 4; t++) {
            if (t < tlo || t >= thi) continue;
            uint4 w = bp[t * 192];
            mma16816(acc[t], ah0, ah1, ah2, ah3, w.x, w.y);
            mma16816(acc[t], ah0, ah1, ah2, ah3, w.z, w.w);
            mma16816(acc[t], al0, al1, al2, al3, w.x, w.y);
        }
    }
    const int sr0 = g * 16 + gq, sr1 = sr0 + 8;
    #pragma unroll
    for (int t = 0; t < 4; t++) {
        if (t < tlo || t >= thi) continue;
        int n0 = t * 8 + kq;
        float bb0 = (n0 < 30) ? bc1[n0] : 0.f;
        float bb1 = (n0 + 1 < 30) ? bc1[n0 + 1] : 0.f;
        float v0 = fmaxf(acc[t][0] + bb0, 0.f), v1 = fmaxf(acc[t][1] + bb1, 0.f);
        float v2 = fmaxf(acc[t][2] + bb0, 0.f), v3 = fmaxf(acc[t][3] + bb1, 0.f);
        uint32_t h, l;
        split2(make_float2(v0, v1), h, l);
        h1s[sr0][t * 4 + (kq >> 1)] = make_uint2(h, l);
        split2(make_float2(v2, v3), h, l);
        h1s[sr1][t * 4 + (kq >> 1)] = make_uint2(h, l);
    }
}

__global__ __launch_bounds__(128) void convf_kernel(
    const float* __restrict__ x, const uint4* __restrict__ Wf1, const float* __restrict__ bc1,
    const uint4* __restrict__ Wf2, const float* __restrict__ bc2, float* __restrict__ out)
{
    __shared__ uint2 h1s[80][16];
    const int b = blockIdx.y;
    const int t0 = blockIdx.x * 64;
    const int lane = threadIdx.x & 31, warp = threadIdx.x >> 5;
    const float* xb = x + (size_t)b * NS * NT;

    conv_l1_group(xb, Wf1, bc1, h1s, t0, warp, 0, 4, lane);
    if (warp < 2) conv_l1_group(xb, Wf1, bc1, h1s, t0, 4, warp * 2, warp * 2 + 2, lane);
    __syncthreads();

    const int gq = lane >> 2, kq = (lane & 3) * 2;
    const int r0 = t0 + warp * 16 + gq, r1 = r0 + 8;
    float acc[4][4];
    #pragma unroll
    for (int t = 0; t < 4; t++) { acc[t][0] = 0.f; acc[t][1] = 0.f; acc[t][2] = 0.f; acc[t][3] = 0.f; }
    for (int ks = 0; ks < 6; ks++) {
        int kb = ks * 16 + kq;
        int kk = kb >> 5;
        int i  = kb & 31;
        int ts0 = r0 + kk - 1, ts1 = r1 + kk - 1;
        int s0 = ts0 - (t0 - 8), s1 = ts1 - (t0 - 8);
        uint2 z = make_uint2(0u, 0u);
        uint2 p00 = (ts0 >= 0 && ts0 < NT) ? h1s[s0][i >> 1]       : z;
        uint2 p01 = (ts0 >= 0 && ts0 < NT) ? h1s[s0][(i + 8) >> 1] : z;
        uint2 p10 = (ts1 >= 0 && ts1 < NT) ? h1s[s1][i >> 1]       : z;
        uint2 p11 = (ts1 >= 0 && ts1 < NT) ? h1s[s1][(i + 8) >> 1] : z;
        const uint4* bp = Wf2 + ks * 32 + lane;
        #pragma unroll
        for (int t = 0; t < 4; t++) {
            uint4 w = bp[t * 192];
            mma16816(acc[t], p00.x, p10.x, p01.x, p11.x, w.x, w.y);
            mma16816(acc[t], p00.x, p10.x, p01.x, p11.x, w.z, w.w);
            mma16816(acc[t], p00.y, p10.y, p01.y, p11.y, w.x, w.y);
        }
    }
    #pragma unroll
    for (int t = 0; t < 4; t++) {
        int n0 = t * 8 + kq;
        if (n0 < 30) {
            float bb = bc2[n0];
            out[((size_t)b * NS + n0) * NT + r0] = fmaxf(acc[t][0] + bb, 0.f);
            out[((size_t)b * NS + n0) * NT + r1] = fmaxf(acc[t][2] + bb, 0.f);
        }
        if (n0 + 1 < 30) {
            float bb = bc2[n0 + 1];
            out[((size_t)b * NS + n0 + 1) * NT + r0] = fmaxf(acc[t][1] + bb, 0.f);
            out[((size_t)b * NS + n0 + 1) * NT + r1] = fmaxf(acc[t][3] + bb, 0.f);
        }
    }
}

// ---------------- HMMA split-bf16 GEMM body (generic) ----------------
template<int NTl>
__device__ __forceinline__ void mgemm_body(
    const float* __restrict__ A, const uint4* __restrict__ B4,
    const float* __restrict__ bias, float* __restrict__ C,
    int N, int K, int nks, int ldc, int coloff, int relu)
{
    const int lane = threadIdx.x & 31;
    const int warp = threadIdx.x >> 5;
    const int gq = lane >> 2;
    const int q  = lane & 3;
    const int r0 = blockIdx.x * 64 + warp * 16 + gq;
    const int r1 = r0 + 8;
    const int kq = q * 2;

    float acc[NTl][4];
    #pragma unroll
    for (int t = 0; t < NTl; t++) {
        acc[t][0] = 0.f; acc[t][1] = 0.f; acc[t][2] = 0.f; acc[t][3] = 0.f;
    }

    const float* a0p = A + (size_t)r0 * K;
    const float* a1p = A + (size_t)r1 * K;

    for (int ks = 0; ks < nks; ks++) {
        const int kb = ks * 16 + kq;
        float2 x00 = (kb     < K) ? *reinterpret_cast<const float2*>(a0p + kb)     : make_float2(0.f, 0.f);
        float2 x01 = (kb + 8 < K) ? *reinterpret_cast<const float2*>(a0p + kb + 8) : make_float2(0.f, 0.f);
        float2 x10 = (kb     < K) ? *reinterpret_cast<const float2*>(a1p + kb)     : make_float2(0.f, 0.f);
        float2 x11 = (kb + 8 < K) ? *reinterpret_cast<const float2*>(a1p + kb + 8) : make_float2(0.f, 0.f);
        uint32_t ah0, al0, ah1, al1, ah2, al2, ah3, al3;
        split2(x00, ah0, al0);
        split2(x10, ah1, al1);
        split2(x01, ah2, al2);
        split2(x11, ah3, al3);
        const uint4* bp = B4 + ks * 32 + lane;
        const int stride = nks * 32;
        #pragma unroll
        for (int t = 0; t < NTl; t++) {
            uint4 w = bp[(size_t)t * stride];
            mma16816(acc[t], ah0, ah1, ah2, ah3, w.x, w.y);
            mma16816(acc[t], ah0, ah1, ah2, ah3, w.z, w.w);
            mma16816(acc[t], al0, al1, al2, al3, w.x, w.y);
        }
    }

    #pragma unroll
    for (int t = 0; t < NTl; t++) {
        int n0 = t * 8 + kq;
        if (n0 < N) {
            float b0v = bias ? bias[n0] : 0.f;
            float b1v = bias ? bias[n0 + 1] : 0.f;
            float v0 = acc[t][0] + b0v, v1 = acc[t][1] + b1v;
            float v2 = acc[t][2] + b0v, v3 = acc[t][3] + b1v;
            if (relu) {
                v0 = fmaxf(v0, 0.f); v1 = fmaxf(v1, 0.f);
                v2 = fmaxf(v2, 0.f); v3 = fmaxf(v3, 0.f);
            }
            *reinterpret_cast<float2*>(&C[(size_t)r0 * ldc + coloff + n0]) = make_float2(v0, v1);
            *reinterpret_cast<float2*>(&C[(size_t)r1 * ldc + coloff + n0]) = make_float2(v2, v3);
        }
    }
}

// ---------------- dedicated F2 GEMM: K=1024 compile-time, prefetch double-buffer ----------------
template<int NTl>
__device__ __forceinline__ void f2_body(
    const float* __restrict__ A, const uint4* __restrict__ B4,
    const float* __restrict__ bias, float* __restrict__ C, int coloff)
{
    constexpr int K = 1024, nks = 64;
    const int lane = threadIdx.x & 31;
    const int warp = threadIdx.x >> 5;
    const int gq = lane >> 2;
    const int kq = (lane & 3) * 2;
    const int r0 = blockIdx.x * 64 + warp * 16 + gq;
    const int r1 = r0 + 8;

    float acc[NTl][4];
    #pragma unroll
    for (int t = 0; t < NTl; t++) {
        acc[t][0] = 0.f; acc[t][1] = 0.f; acc[t][2] = 0.f; acc[t][3] = 0.f;
    }

    const float* a0p = A + (size_t)r0 * K + kq;
    const float* a1p = A + (size_t)r1 * K + kq;

    float2 c0 = *reinterpret_cast<const float2*>(a0p);
    float2 c1 = *reinterpret_cast<const float2*>(a0p + 8);
    float2 c2 = *reinterpret_cast<const float2*>(a1p);
    float2 c3 = *reinterpret_cast<const float2*>(a1p + 8);

    for (int ks = 0; ks < nks; ks++) {
        float2 n0, n1, n2, n3;
        if (ks < nks - 1) {
            const int kb = (ks + 1) * 16;
            n0 = *reinterpret_cast<const float2*>(a0p + kb);
            n1 = *reinterpret_cast<const float2*>(a0p + kb + 8);
            n2 = *reinterpret_cast<const float2*>(a1p + kb);
            n3 = *reinterpret_cast<const float2*>(a1p + kb + 8);
        }
        uint32_t ah0, al0, ah1, al1, ah2, al2, ah3, al3;
        split2(c0, ah0, al0);
        split2(c2, ah1, al1);
        split2(c1, ah2, al2);
        split2(c3, ah3, al3);
        const uint4* bp = B4 + ks * 32 + lane;
        #pragma unroll
        for (int t = 0; t < NTl; t++) {
            uint4 w = bp[t * (nks * 32)];
            mma16816(acc[t], ah0, ah1, ah2, ah3, w.x, w.y);
            mma16816(acc[t], ah0, ah1, ah2, ah3, w.z, w.w);
            mma16816(acc[t], al0, al1, al2, al3, w.x, w.y);
        }
        c0 = n0; c1 = n1; c2 = n2; c3 = n3;
    }

    #pragma unroll
    for (int t = 0; t < NTl; t++) {
        int n0 = t * 8 + kq;
        float b0v = bias[n0], b1v = bias[n0 + 1];
        float v0 = fmaxf(acc[t][0] + b0v, 0.f), v1 = fmaxf(acc[t][1] + b1v, 0.f);
        float v2 = fmaxf(acc[t][2] + b0v, 0.f), v3 = fmaxf(acc[t][3] + b1v, 0.f);
        *reinterpret_cast<float2*>(&C[(size_t)r0 * 200 + coloff + n0]) = make_float2(v0, v1);
        *reinterpret_cast<float2*>(&C[(size_t)r1 * 200 + coloff + n0]) = make_float2(v2, v3);
    }
}

__global__ __launch_bounds__(128, 4) void f2gemm_kernel(
    const float* __restrict__ A, const uint4* __restrict__ B4,
    const float* __restrict__ bias, float* __restrict__ C)
{
    if (blockIdx.y == 0)
        f2_body<13>(A, B4, bias, C, 0);
    else
        f2_body<12>(A, B4 + 13 * 64 * 32, bias + 104, C, 104);
}

// N-split GEMM (200 cols -> 104 + 96), grid (480, 2)
__global__ __launch_bounds__(128, 4) void mgemmS_kernel(
    const float* __restrict__ A, const uint4* __restrict__ B4,
    const float* __restrict__ bias, float* __restrict__ C,
    int K, int nks, int ldc, int relu)
{
    if (blockIdx.y == 0)
        mgemm_body<13>(A, B4, bias, C, 104, K, nks, ldc, 0, relu);
    else
        mgemm_body<12>(A, B4 + 13 * nks * 32, bias ? bias + 104 : nullptr, C, 96, K, nks, ldc, 104, relu);
}

// MEGA1: x1=relu(P1@Wm1), h1s=relu(Q@Wg1), Gv[:,0:150]=relu(Q@Wl), Gv[:,150:300]=relu(P1@Wgl)
__global__ __launch_bounds__(128, 4) void mega1_kernel(
    const float* __restrict__ P1, const float* __restrict__ Q,
    const uint4* __restrict__ Bm1, const uint4* __restrict__ Bg1,
    const uint4* __restrict__ Bl, const uint4* __restrict__ Bgl,
    float* __restrict__ x1, float* __restrict__ h1s, float* __restrict__ Gv)
{
    switch (blockIdx.y) {
    case 0: mgemm_body<13>(P1, Bm1,        nullptr, x1,  104, 200, 13, 200, 0,   1); break;
    case 1: mgemm_body<12>(P1, Bm1 + 5408, nullptr, x1,  96,  200, 13, 200, 104, 1); break;
    case 2: mgemm_body<13>(Q,  Bg1,        nullptr, h1s, 104, 200, 13, 200, 0,   1); break;
    case 3: mgemm_body<12>(Q,  Bg1 + 5408, nullptr, h1s, 96,  200, 13, 200, 104, 1); break;
    case 4: mgemm_body<10>(Q,  Bl,         nullptr, Gv,  80,  200, 13, 300, 0,   1); break;
    case 5: mgemm_body<9> (Q,  Bl + 4160,  nullptr, Gv,  70,  200, 13, 300, 80,  1); break;
    case 6: mgemm_body<10>(P1, Bgl,        nullptr, Gv,  80,  200, 13, 300, 150, 1); break;
    default: mgemm_body<9>(P1, Bgl + 4160, nullptr, Gv,  70,  200, 13, 300, 230, 1); break;
    }
}

// MEGA3: x2=relu(tA@Wm2), xsn=tC@Wg2
__global__ __launch_bounds__(128, 4) void mega3_kernel(
    const float* __restrict__ tA, const float* __restrict__ tC,
    const uint4* __restrict__ Bm2, const uint4* __restrict__ Bg2,
    float* __restrict__ x2, float* __restrict__ xsn)
{
    switch (blockIdx.y) {
    case 0: mgemm_body<13>(tA, Bm2,        nullptr, x2,  104, 200, 13, 200, 0,   1); break;
    case 1: mgemm_body<12>(tA, Bm2 + 5408, nullptr, x2,  96,  200, 13, 200, 104, 1); break;
    case 2: mgemm_body<13>(tC, Bg2,        nullptr, xsn, 104, 200, 13, 200, 0,   0); break;
    default: mgemm_body<12>(tC, Bg2 + 5408, nullptr, xsn, 96, 200, 13, 200, 104, 0); break;
    }
}

// merged 3x (N=100, K=200), split 56+44, grid (480, 6)
__global__ __launch_bounds__(128, 4) void mgemm3_kernel(
    const float* __restrict__ A0, const float* __restrict__ A1, const float* __restrict__ A2,
    const uint4* __restrict__ B4, float* __restrict__ C)
{
    const int j = blockIdx.y >> 1, h = blockIdx.y & 1;
    const float* A = (j == 0) ? A0 : (j == 1) ? A1 : A2;
    const uint4* B = B4 + j * 5408;
    if (h == 0) mgemm_body<7>(A, B, nullptr, C, 56, 200, 13, 300, j * 100, 0);
    else        mgemm_body<6>(A, B + 7 * 13 * 32, nullptr, C, 44, 200, 13, 300, j * 100 + 56, 0);
}

// ---------------- batched small matmul body ----------------
__device__ __forceinline__ void bmm30_body(
    const float* __restrict__ Am, const float* __restrict__ X, float* __restrict__ Out,
    int batched, int b, int tid)
{
    __shared__ float As[NS * NS];
    __shared__ float Xs[NS * NFD];
    const float* A = batched ? (Am + (size_t)b * NS * NS) : Am;
    for (int i = tid; i < NS * NS; i += 256) As[i] = A[i];
    for (int i = tid; i < NS * NFD; i += 256) Xs[i] = X[(size_t)b * NS * NFD + i];
    __syncthreads();
    if (tid < 250) {
        int si = tid / 25, fi = tid - (tid / 25) * 25;
        int s0 = si * 3, f0 = fi * 8;
        float acc[3][8];
        #pragma unroll
        for (int r = 0; r < 3; r++)
            #pragma unroll
            for (int q = 0; q < 8; q++) acc[r][q] = 0.f;
        for (int j = 0; j < NS; j++) {
            float a0 = As[(s0 + 0) * NS + j];
            float a1 = As[(s0 + 1) * NS + j];
            float a2 = As[(s0 + 2) * NS + j];
            float4 xA = *reinterpret_cast<const float4*>(&Xs[j * NFD + f0]);
            float4 xB = *reinterpret_cast<const float4*>(&Xs[j * NFD + f0 + 4]);
            float xv[8] = {xA.x, xA.y, xA.z, xA.w, xB.x, xB.y, xB.z, xB.w};
            #pragma unroll
            for (int q = 0; q < 8; q++) {
                acc[0][q] += a0 * xv[q];
                acc[1][q] += a1 * xv[q];
                acc[2][q] += a2 * xv[q];
            }
        }
        #pragma unroll
        for (int r = 0; r < 3; r++)
            #pragma unroll
            for (int q = 0; q < 8; q++)
                Out[(size_t)b * NS * NFD + (s0 + r) * NFD + f0 + q] = acc[r][q];
    }
}

__global__ __launch_bounds__(256) void bmm30_kernel(
    const float* __restrict__ Am, const float* __restrict__ X, float* __restrict__ Out, int batched)
{
    bmm30_body(Am, X, Out, batched, blockIdx.x, threadIdx.x);
}

// merged tA = A_F@x1 (y=0) and tC = adj@h1s (y=1)
__global__ __launch_bounds__(256) void bmmM2_kernel(
    const float* __restrict__ AF, const float* __restrict__ adj,
    const float* __restrict__ x1, const float* __restrict__ h1s,
    float* __restrict__ tA, float* __restrict__ tC)
{
    if (blockIdx.y == 0) bmm30_body(AF, x1, tA, 1, blockIdx.x, threadIdx.x);
    else                 bmm30_body(adj, h1s, tC, 0, blockIdx.x, threadIdx.x);
}

// ---------------- fused A_F + P1 + Q ----------------
__global__ __launch_bounds__(256) void afpq_kernel(
    const float* __restrict__ Tm, const float* __restrict__ F2, const float* __restrict__ adj,
    float* __restrict__ AF, float* __restrict__ P1, float* __restrict__ Q)
{
    extern __shared__ float sm[];
    float* Ts  = sm;
    float* Fs  = sm + 6000;
    float* As  = sm + 12000;
    float* AFs = sm + 12900;
    const int b = blockIdx.x;
    const int tid = threadIdx.x;
    const size_t base = (size_t)b * 6000;
    for (int i = tid; i < 6000; i += 256) {
        Ts[i] = Tm[base + i];
        Fs[i] = F2[base + i];
    }
    for (int i = tid; i < 900; i += 256) As[i] = adj[i];
    __syncthreads();

    float acc[3][3];
    int ii = 0, jj = 0;
    if (tid < 100) {
        ii = (tid / 10) * 3; jj = (tid % 10) * 3;
        #pragma unroll
        for (int r = 0; r < 3; r++)
            #pragma unroll
            for (int c = 0; c < 3; c++) acc[r][c] = 0.f;
        for (int g = 0; g < NFD; g++) {
            float t0 = Ts[(ii + 0) * NFD + g], t1 = Ts[(ii + 1) * NFD + g], t2 = Ts[(ii + 2) * NFD + g];
            float f0 = Fs[(jj + 0) * NFD + g], f1 = Fs[(jj + 1) * NFD + g], f2 = Fs[(jj + 2) * NFD + g];
            acc[0][0] += t0 * f0; acc[0][1] += t0 * f1; acc[0][2] += t0 * f2;
            acc[1][0] += t1 * f0; acc[1][1] += t1 * f1; acc[1][2] += t1 * f2;
            acc[2][0] += t2 * f0; acc[2][1] += t2 * f1; acc[2][2] += t2 * f2;
        }
    }
    __syncthreads();
    float (*Ms)[31] = reinterpret_cast<float(*)[31]>(Ts);
    if (tid < 100) {
        #pragma unroll
        for (int r = 0; r < 3; r++)
            #pragma unroll
            for (int c = 0; c < 3; c++) Ms[ii + r][jj + c] = fmaxf(acc[r][c], 0.f);
    }
    __syncthreads();
    if (tid < NS) {
        float mx = -1e30f;
        for (int j = 0; j < NS; j++) mx = fmaxf(mx, Ms[tid][j]);
        float s = 0.f;
        for (int j = 0; j < NS; j++) s += expf(Ms[tid][j] - mx);
        float inv = 1.f / s;
        for (int j = 0; j < NS; j++) {
            float v = expf(Ms[tid][j] - mx) * inv;
            AFs[tid * NS + j] = v;
            AF[(size_t)b * NS * NS + tid * NS + j] = v;
        }
    }
    __syncthreads();

    if (tid < 250) {
        int si = tid / 25, fi = tid - (tid / 25) * 25;
        int s0 = si * 3, f0 = fi * 8;
        float accP[3][8], accQ[3][8];
        #pragma unroll
        for (int r = 0; r < 3; r++)
            #pragma unroll
            for (int q = 0; q < 8; q++) { accP[r][q] = 0.f; accQ[r][q] = 0.f; }
        for (int j = 0; j < NS; j++) {
            float p0 = AFs[(s0 + 0) * NS + j];
            float p1 = AFs[(s0 + 1) * NS + j];
            float p2 = AFs[(s0 + 2) * NS + j];
            float a0 = As[(s0 + 0) * NS + j];
            float a1 = As[(s0 + 1) * NS + j];
            float a2 = As[(s0 + 2) * NS + j];
            float4 xA = *reinterpret_cast<const float4*>(&Fs[j * NFD + f0]);
            float4 xB = *reinterpret_cast<const float4*>(&Fs[j * NFD + f0 + 4]);
            float xv[8] = {xA.x, xA.y, xA.z, xA.w, xB.x, xB.y, xB.z, xB.w};
            #pragma unroll
            for (int q = 0; q < 8; q++) {
                accP[0][q] += p0 * xv[q];
                accP[1][q] += p1 * xv[q];
                accP[2][q] += p2 * xv[q];
                accQ[0][q] += a0 * xv[q];
                accQ[1][q] += a1 * xv[q];
                accQ[2][q] += a2 * xv[q];
            }
        }
        #pragma unroll
        for (int r = 0; r < 3; r++)
            #pragma unroll
            for (int q = 0; q < 8; q++) {
                P1[base + (s0 + r) * NFD + f0 + q] = accP[r][q];
                Q [base + (s0 + r) * NFD + f0 + q] = accQ[r][q];
            }
    }
}

// ---------------- fused gate + 3x bmm30(adj, g_k*H_k), xsn from gmem ----------------
__global__ __launch_bounds__(256) void gbmm_kernel(
    const float* __restrict__ adj, const float* __restrict__ x1, const float* __restrict__ x2,
    const float* __restrict__ x3, const float* __restrict__ xsn, const float* __restrict__ wg,
    float* __restrict__ o1, float* __restrict__ o2, float* __restrict__ o3)
{
    extern __shared__ float sm[];
    float* As = sm;
    float* X0 = sm + 900;
    float* X1 = sm + 6900;
    float* X2 = sm + 12900;
    const int b = blockIdx.x, tid = threadIdx.x;
    const size_t base = (size_t)b * 6000;
    for (int i = tid; i < 900; i += 256) As[i] = adj[i];
    for (int i = tid; i < 6000; i += 256) {
        X0[i] = x1[base + i];
        X1[i] = x2[base + i];
        X2[i] = x3[base + i];
    }
    __syncthreads();

    {
        const int warp = tid >> 5, lane = tid & 31;
        for (int rr = 0; rr < 4; rr++) {
            int r = warp * 4 + rr;
            if (r >= NS) break;
            float H0[7], H1[7], H2[7];
            float s0 = 0.f, s1 = 0.f, s2 = 0.f;
            #pragma unroll
            for (int q = 0; q < 7; q++) {
                int f = q * 32 + lane;
                float h0 = 0.f, h1 = 0.f, h2 = 0.f;
                if (f < NFD) {
                    float sv = xsn[base + r * NFD + f];
                    h0 = (X0[r * NFD + f] + sv) * 0.5f;
                    h1 = (X1[r * NFD + f] + sv) * 0.5f;
                    h2 = (X2[r * NFD + f] + sv) * 0.5f;
                    s0 += h0 * wg[f * 3 + 0];
                    s1 += h1 * wg[f * 3 + 1];
                    s2 += h2 * wg[f * 3 + 2];
                }
                H0[q] = h0; H1[q] = h1; H2[q] = h2;
            }
            #pragma unroll
            for (int o = 16; o; o >>= 1) {
                s0 += __shfl_xor_sync(0xffffffffu, s0, o);
                s1 += __shfl_xor_sync(0xffffffffu, s1, o);
                s2 += __shfl_xor_sync(0xffffffffu, s2, o);
            }
            float mx = fmaxf(s0, fmaxf(s1, s2));
            float e0 = expf(s0 - mx), e1 = expf(s1 - mx), e2 = expf(s2 - mx);
            float inv = 1.f / (e0 + e1 + e2);
            e0 *= inv; e1 *= inv; e2 *= inv;
            #pragma unroll
            for (int q = 0; q < 7; q++) {
                int f = q * 32 + lane;
                if (f < NFD) {
                    X0[r * NFD + f] = e0 * H0[q];
                    X1[r * NFD + f] = e1 * H1[q];
                    X2[r * NFD + f] = e2 * H2[q];
                }
            }
        }
    }
    __syncthreads();

    if (tid < 250) {
        int si = tid / 25, fi = tid - (tid / 25) * 25;
        int s0 = si * 3, f0 = fi * 8;
        float* Xk[3] = {X0, X1, X2};
        float* Ok[3] = {o1, o2, o3};
        #pragma unroll
        for (int k = 0; k < 3; k++) {
            const float* X = Xk[k];
            float acc[3][8];
            #pragma unroll
            for (int r = 0; r < 3; r++)
                #pragma unroll
                for (int q = 0; q < 8; q++) acc[r][q] = 0.f;
            for (int j = 0; j < NS; j++) {
                float a0 = As[(s0 + 0) * NS + j];
                float a1 = As[(s0 + 1) * NS + j];
                float a2 = As[(s0 + 2) * NS + j];
                float4 xA = *reinterpret_cast<const float4*>(&X[j * NFD + f0]);
                float4 xB = *reinterpret_cast<const float4*>(&X[j * NFD + f0 + 4]);
                float xv[8] = {xA.x, xA.y, xA.z, xA.w, xB.x, xB.y, xB.z, xB.w};
                #pragma unroll
                for (int q = 0; q < 8; q++) {
                    acc[0][q] += a0 * xv[q];
                    acc[1][q] += a1 * xv[q];
                    acc[2][q] += a2 * xv[q];
                }
            }
            #pragma unroll
            for (int r = 0; r < 3; r++)
                #pragma unroll
                for (int q = 0; q < 8; q++)
                    Ok[k][base + (s0 + r) * NFD + f0 + q] = acc[r][q];
        }
    }
}

// ---------------- SE blocks ----------------
__global__ __launch_bounds__(128) void se1_kernel(
    const float* __restrict__ Gv, const float* __restrict__ Ws1,
    const float* __restrict__ Ws2, float* __restrict__ wch)
{
    const int warp = threadIdx.x >> 5, lane = threadIdx.x & 31;
    const int b = blockIdx.x * 4 + warp;
    __shared__ float mvs[4][NS];
    __shared__ float avs[4][15];
    float* mv = mvs[warp];
    float* av = avs[warp];
    for (int s = 0; s < NS; s++) {
        float p = 0.f;
        for (int j = lane; j < 300; j += 32) p += Gv[(size_t)b * 9000 + s * 300 + j];
        #pragma unroll
        for (int o = 16; o; o >>= 1) p += __shfl_xor_sync(0xffffffffu, p, o);
        if (lane == 0) mv[s] = p * (1.f / 300.f);
    }
    __syncwarp();
    if (lane < 15) {
        float a = 0.f;
        for (int s = 0; s < NS; s++) a += mv[s] * Ws1[s * 15 + lane];
        av[lane] = fmaxf(a, 0.f);
    }
    __syncwarp();
    if (lane < NS) {
        float a = 0.f;
        for (int h = 0; h < 15; h++) a += av[h] * Ws2[h * NS + lane];
        wch[b * NS + lane] = 1.f / (1.f + expf(-a));
    }
}

__global__ __launch_bounds__(320) void se2_kernel(const float* __restrict__ Gh,
                                                  const float* __restrict__ Wf1,
                                                  const float* __restrict__ Wf2,
                                                  float* __restrict__ wft)
{
    __shared__ float m[4][300];
    __shared__ float t1[4][152];
    const int b0 = blockIdx.x * 4, tid = threadIdx.x;
    if (tid < 300) {
        #pragma unroll
        for (int bb = 0; bb < 4; bb++) {
            float a = 0.f;
            for (int s = 0; s < NS; s++) a += Gh[(size_t)(b0 + bb) * 9000 + s * 300 + tid];
            m[bb][tid] = a * (1.f / 30.f);
        }
    }
    __syncthreads();
    if (tid < 150) {
        float a[4] = {0.f, 0.f, 0.f, 0.f};
        for (int j = 0; j < 300; j++) {
            float w = Wf1[j * 150 + tid];
            #pragma unroll
            for (int bb = 0; bb < 4; bb++) a[bb] += m[bb][j] * w;
        }
        #pragma unroll
        for (int bb = 0; bb < 4; bb++) t1[bb][tid] = fmaxf(a[bb], 0.f);
    }
    __syncthreads();
    if (tid < 300) {
        float a[4] = {0.f, 0.f, 0.f, 0.f};
        for (int h = 0; h < 150; h++) {
            float w = Wf2[h * 300 + tid];
            #pragma unroll
            for (int bb = 0; bb < 4; bb++) a[bb] += t1[bb][h] * w;
        }
        #pragma unroll
        for (int bb = 0; bb < 4; bb++)
            wft[(size_t)(b0 + bb) * 300 + tid] = 1.f / (1.f + expf(-a[bb]));
    }
}

// ---------------- classifier + log_softmax ----------------
__global__ __launch_bounds__(256) void cls_kernel(
    const float* __restrict__ Gh, const float* __restrict__ Gv,
    const float* __restrict__ wch, const float* __restrict__ wft,
    const float* __restrict__ Wcls, const float* __restrict__ bcls, float* __restrict__ out)
{
    const int b0 = blockIdx.x * 4, tid = threadIdx.x;
    const int lane = tid & 31, warp = tid >> 5;
    float acc[4][NCL];
    #pragma unroll
    for (int bb = 0; bb < 4; bb++)
        #pragma unroll
        for (int k = 0; k < NCL; k++) acc[bb][k] = 0.f;

    for (int idx = tid; idx < 18000; idx += 256) {
        int s = idx / 600;
        int c = idx - s * 600;
        float w[NCL];
        #pragma unroll
        for (int k = 0; k < NCL; k++) w[k] = Wcls[(size_t)idx * NCL + k];
        #pragma unroll
        for (int bb = 0; bb < 4; bb++) {
            int b = b0 + bb;
            float val;
            if (c < 300) val = Gh[(size_t)b * 9000 + s * 300 + c] * wch[b * NS + s];
            else {
                int cc = c - 300;
                val = Gv[(size_t)b * 9000 + s * 300 + cc] * wft[(size_t)b * 300 + cc];
            }
            #pragma unroll
            for (int k = 0; k < NCL; k++) acc[bb][k] += val * w[k];
        }
    }
    #pragma unroll
    for (int bb = 0; bb < 4; bb++)
        #pragma unroll
        for (int k = 0; k < NCL; k++)
            #pragma unroll
            for (int o = 16; o; o >>= 1)
                acc[bb][k] += __shfl_xor_sync(0xffffffffu, acc[bb][k], o);
    __shared__ float red[8][4][NCL];
    __shared__ float zs[4][NCL];
    if (lane == 0) {
        #pragma unroll
        for (int bb = 0; bb < 4; bb++)
            #pragma unroll
            for (int k = 0; k < NCL; k++) red[warp][bb][k] = acc[bb][k];
    }
    __syncthreads();
    if (tid < 28) {
        int bb = tid / 7, k = tid - bb * 7;
        float z = bcls[k];
        #pragma unroll
        for (int w2 = 0; w2 < 8; w2++) z += red[w2][bb][k];
        zs[bb][k] = z;
    }
    __syncthreads();
    if (tid < 4) {
        float mx = -1e30f;
        #pragma unroll
        for (int k = 0; k < NCL; k++) mx = fmaxf(mx, zs[tid][k]);
        float s = 0.f;
        #pragma unroll
        for (int k = 0; k < NCL; k++) s += expf(zs[tid][k] - mx);
        float ls = logf(s);
        #pragma unroll
        for (int k = 0; k < NCL; k++) out[(b0 + tid) * NCL + k] = zs[tid][k] - mx - ls;
    }
}

// ---------------- launch ----------------
extern "C" void kernel_launch(void* const* d_in, const int* in_sizes, int n_in,
                              void* d_out, int out_size)
{
    const float* x    = (const float*)d_in[0];
    const float* adj  = (const float*)d_in[1];
    const float* Wc1  = (const float*)d_in[2];
    const float* bc1  = (const float*)d_in[3];
    const float* Wc2  = (const float*)d_in[4];
    const float* bc2  = (const float*)d_in[5];
    const float* Wt   = (const float*)d_in[6];
    const float* bt   = (const float*)d_in[7];
    const float* Wa   = (const float*)d_in[8];
    const float* Wm1  = (const float*)d_in[9];
    const float* Wm2  = (const float*)d_in[10];
    const float* Wm3  = (const float*)d_in[11];
    const float* Wg1  = (const float*)d_in[12];
    const float* Wg2  = (const float*)d_in[13];
    const float* wg   = (const float*)d_in[14];
    const float* Wp1  = (const float*)d_in[15];
    const float* Wp2  = (const float*)d_in[16];
    const float* Wp3  = (const float*)d_in[17];
    const float* Wl   = (const float*)d_in[18];
    const float* Wgl  = (const float*)d_in[19];
    const float* Ws1  = (const float*)d_in[20];
    const float* Ws2  = (const float*)d_in[21];
    const float* Wf1  = (const float*)d_in[22];
    const float* Wf2  = (const float*)d_in[23];
    const float* Wcls = (const float*)d_in[24];
    const float* bcls = (const float*)d_in[25];
    float* out = (float*)d_out;

    float *p_h2, *p_F2, *p_tmp, *p_tmp2, *p_P1, *p_x1, *p_x2, *p_x3, *p_Q, *p_h1s, *p_xsn;
    float *p_gH1, *p_gH2, *p_gH3, *p_AF, *p_Gh, *p_Gv, *p_wch, *p_wft;
    uint4 *p_b4, *p_cw1, *p_cw2;
    cudaGetSymbolAddress((void**)&p_h2,   g_h2);
    cudaGetSymbolAddress((void**)&p_F2,   g_F2);
    cudaGetSymbolAddress((void**)&p_tmp,  g_tmp);
    cudaGetSymbolAddress((void**)&p_tmp2, g_tmp2);
    cudaGetSymbolAddress((void**)&p_P1,   g_P1);
    cudaGetSymbolAddress((void**)&p_x1,   g_x1);
    cudaGetSymbolAddress((void**)&p_x2,   g_x2);
    cudaGetSymbolAddress((void**)&p_x3,   g_x3);
    cudaGetSymbolAddress((void**)&p_Q,    g_Q);
    cudaGetSymbolAddress((void**)&p_h1s,  g_h1s);
    cudaGetSymbolAddress((void**)&p_xsn,  g_xsn);
    cudaGetSymbolAddress((void**)&p_gH1,  g_gH1);
    cudaGetSymbolAddress((void**)&p_gH2,  g_gH2);
    cudaGetSymbolAddress((void**)&p_gH3,  g_gH3);
    cudaGetSymbolAddress((void**)&p_AF,   g_AF);
    cudaGetSymbolAddress((void**)&p_Gh,   g_Gh);
    cudaGetSymbolAddress((void**)&p_Gv,   g_Gv);
    cudaGetSymbolAddress((void**)&p_wch,  g_wch);
    cudaGetSymbolAddress((void**)&p_wft,  g_wft);
    cudaGetSymbolAddress((void**)&p_b4,   g_bf4);
    cudaGetSymbolAddress((void**)&p_cw1,  g_cw1);
    cudaGetSymbolAddress((void**)&p_cw2,  g_cw2);

    // fragment pool offsets (uint4 units)
    const int oWt  = 0;
    const int oWa  = 51200;
    const int oWm1 = 61600, oWm2 = 72000, oWm3 = 82400;
    const int oWg1 = 92800, oWg2 = 103200;
    const int oWp1 = 113600, oWp2 = 119008, oWp3 = 124416;
    const int oWl  = 129824, oWgl = 137728;

    PJobs J;
    const float* Ws[12] = {Wt, Wa, Wm1, Wm2, Wm3, Wg1, Wg2, Wp1, Wp2, Wp3, Wl, Wgl};
    const int   Ks[12] = {1024, 200, 200, 200, 200, 200, 200, 200, 200, 200, 200, 200};
    const int   Nn[12] = {200, 200, 200, 200, 200, 200, 200, 100, 100, 100, 150, 150};
    const int   Tt[12] = {25, 25, 25, 25, 25, 25, 25, 13, 13, 13, 19, 19};
    const int   Kk[12] = {64, 13, 13, 13, 13, 13, 13, 13, 13, 13, 13, 13};
    const int   Of[12] = {oWt, oWa, oWm1, oWm2, oWm3, oWg1, oWg2, oWp1, oWp2, oWp3, oWl, oWgl};
    for (int i = 0; i < 12; i++) {
        J.W[i] = Ws[i]; J.K[i] = Ks[i]; J.N[i] = Nn[i];
        J.nT[i] = Tt[i]; J.nks[i] = Kk[i]; J.off[i] = Of[i];
    }

    const int GBMM_SMEM = 18900 * 4;   // 75.6 KB -> 2 CTAs/SM
    const int AFPQ_SMEM = 13800 * 4;   // 55.2 KB
    cudaFuncSetAttribute(gbmm_kernel, cudaFuncAttributeMaxDynamicSharedMemorySize, GBMM_SMEM);
    cudaFuncSetAttribute(afpq_kernel, cudaFuncAttributeMaxDynamicSharedMemorySize, AFPQ_SMEM);

    prepall_kernel<<<dim3(200, 12), 256>>>(J, p_b4);
    prepcw_kernel<<<dim3(3, 2), 256>>>(Wc1, Wc2, p_cw1, p_cw2);

    const int GM = MROWS / 64;   // 480 CTAs
    dim3 gS(GM, 2);

    // CNN feature extractor
    convf_kernel<<<dim3(16, BATCH), 128>>>(x, p_cw1, bc1, p_cw2, bc2, p_h2);
    // F2 projection: dedicated prefetch kernel, K=1024 compile-time
    f2gemm_kernel<<<gS, 128>>>(p_h2, p_b4+oWt, bt, p_F2);

    // learned adjacency scores
    mgemmS_kernel<<<gS, 128>>>(p_F2, p_b4+oWa, nullptr, p_tmp, 200, 13, 200, 0);

    // fused: A_F softmax + P1 = A_F@F2 + Q = adj@F2
    afpq_kernel<<<BATCH, 256, AFPQ_SMEM>>>(p_tmp, p_F2, adj, p_AF, p_P1, p_Q);

    // MEGA1: x1, h1s, and both LGFM halves of G_v
    mega1_kernel<<<dim3(GM, 8), 128>>>(p_P1, p_Q, p_b4+oWm1, p_b4+oWg1, p_b4+oWl, p_b4+oWgl,
                                       p_x1, p_h1s, p_Gv);

    // se1 only needs G_v
    se1_kernel<<<BATCH / 4, 128>>>(p_Gv, Ws1, Ws2, p_wch);

    // MEGA2: tA = A_F@x1, tC = adj@h1s
    bmmM2_kernel<<<dim3(BATCH, 2), 256>>>(p_AF, adj, p_x1, p_h1s, p_tmp, p_tmp2);

    // MEGA3: x2 = relu(tA@Wm2), xsn = tC@Wg2
    mega3_kernel<<<dim3(GM, 4), 128>>>(p_tmp, p_tmp2, p_b4+oWm2, p_b4+oWg2, p_x2, p_xsn);

    // x3 chain
    bmm30_kernel<<<BATCH, 256>>>(p_AF, p_x2, p_tmp, 1);
    mgemmS_kernel<<<gS, 128>>>(p_tmp, p_b4+oWm3, nullptr, p_x3, 200, 13, 200, 1);

    // fused gate + adj-aggregation
    gbmm_kernel<<<BATCH, 256, GBMM_SMEM>>>(adj, p_x1, p_x2, p_x3, p_xsn, wg, p_gH1, p_gH2, p_gH3);

    // G_h: 3 projections (merged, N-split)
    mgemm3_kernel<<<dim3(GM, 6), 128>>>(p_gH1, p_gH2, p_gH3, p_b4+oWp1, p_Gh);

    // se2 + classifier
    se2_kernel<<<BATCH / 4, 320>>>(p_Gh, Wf1, Wf2, p_wft);
    cls_kernel<<<BATCH / 4, 256>>>(p_Gh, p_Gv, p_wch, p_wft, Wcls, bcls, out);
}